// round 1
// baseline (speedup 1.0000x reference)
#include <cuda_runtime.h>

// ---------------- problem constants ----------------
#define TOK    131072              // B*H*W tokens (raster order)
#define HSZ    25165824            // 8*192*128*128 (one output tensor)
#define NCHAN  192

// ---------------- static device scratch ----------------
__device__ float g_proj[(size_t)TOK * 192];   // in_proj out; later reused as normalized amap
__device__ float g_xn  [(size_t)TOK * 192];   // layernorm out
__device__ float g_qkv [(size_t)TOK * 576];
__device__ float g_attn[(size_t)TOK * 192];
__device__ float g_amap[(size_t)TOK * 192];
__device__ float g_gates[(size_t)TOK * 768];
__device__ float g_hraw[(size_t)TOK * 192];   // BCHW layout
__device__ float g_p1s[8 * 192 * 64];         // GN1 partial sums  [(b*192+c)*64 + chunk]
__device__ float g_p1q[8 * 192 * 64];
__device__ float g_mu1[64], g_inv1[64];
__device__ float g_p2s[64 * 16], g_p2q[64 * 16];
__device__ float g_mu2[64], g_inv2[64];

// ---------------- f32x2 helpers (Blackwell packed fp32) ----------------
__device__ __forceinline__ unsigned long long fdup(float v) {
    unsigned long long r;
    asm("mov.b64 %0, {%1, %1};" : "=l"(r) : "f"(v));
    return r;
}
__device__ __forceinline__ void ffma2(unsigned long long& d,
                                      unsigned long long a,
                                      unsigned long long b) {
    asm("fma.rn.f32x2 %0, %1, %2, %0;" : "+l"(d) : "l"(a), "l"(b));
}
union U64F2 { unsigned long long u; float2 f; };

// =====================================================================
// SGEMM (row-major A [M,K], W [N,K] row-major, C = A*W^T + bias [M,N])
// TM=128, TN=64, TK=16, 128 threads, per-thread 8x8 via f32x2 pairs.
// grid = (N/64, M/128)   (N-tiles fastest -> A tiles stay hot in L2)
// =====================================================================
__global__ __launch_bounds__(128)
void k_gemm_rm(const float* __restrict__ A, const float* __restrict__ W,
               const float* __restrict__ bias, float* __restrict__ C,
               int K, int N)
{
    __shared__ unsigned long long As2[16][129];          // duplicated pairs
    __shared__ __align__(16) float Ws[16][64];

    const int m0 = blockIdx.y * 128;
    const int n0 = blockIdx.x * 64;
    const int tid = threadIdx.x;
    const int tm = tid & 15, tn = tid >> 4;

    unsigned long long acc[8][4];
#pragma unroll
    for (int i = 0; i < 8; i++)
#pragma unroll
        for (int q = 0; q < 4; q++) acc[i][q] = 0ull;

    const int nch = K >> 4;
    for (int kt = 0; kt < nch; kt++) {
        // --- load A tile 128x16 (duplicated into f32x2 pairs) ---
#pragma unroll
        for (int j = 0; j < 4; j++) {
            int f = tid + 128 * j;
            int row = f >> 2, v = f & 3;
            float4 a4 = *reinterpret_cast<const float4*>(
                &A[(size_t)(m0 + row) * K + kt * 16 + v * 4]);
            As2[v * 4 + 0][row] = fdup(a4.x);
            As2[v * 4 + 1][row] = fdup(a4.y);
            As2[v * 4 + 2][row] = fdup(a4.z);
            As2[v * 4 + 3][row] = fdup(a4.w);
        }
        // --- load W tile 64x16 (transposed to [k][n]) ---
#pragma unroll
        for (int j = 0; j < 2; j++) {
            int f = tid + 128 * j;
            int row = f >> 2, v = f & 3;
            float4 w4 = *reinterpret_cast<const float4*>(
                &W[(size_t)(n0 + row) * K + kt * 16 + v * 4]);
            Ws[v * 4 + 0][row] = w4.x;
            Ws[v * 4 + 1][row] = w4.y;
            Ws[v * 4 + 2][row] = w4.z;
            Ws[v * 4 + 3][row] = w4.w;
        }
        __syncthreads();
#pragma unroll
        for (int k = 0; k < 16; k++) {
            unsigned long long afr[8];
#pragma unroll
            for (int jj = 0; jj < 8; jj++) afr[jj] = As2[k][tm + 16 * jj];
            ulonglong2 bA = *reinterpret_cast<const ulonglong2*>(&Ws[k][tn * 4]);
            ulonglong2 bB = *reinterpret_cast<const ulonglong2*>(&Ws[k][32 + tn * 4]);
            unsigned long long bfr[4] = { bA.x, bA.y, bB.x, bB.y };
#pragma unroll
            for (int jj = 0; jj < 8; jj++) {
#pragma unroll
                for (int q = 0; q < 4; q++) ffma2(acc[jj][q], afr[jj], bfr[q]);
            }
        }
        __syncthreads();
    }

    const int nA = n0 + tn * 4;
    const int nB = n0 + 32 + tn * 4;
    float4 biasA = *reinterpret_cast<const float4*>(&bias[nA]);
    float4 biasB = *reinterpret_cast<const float4*>(&bias[nB]);
#pragma unroll
    for (int jj = 0; jj < 8; jj++) {
        size_t ro = (size_t)(m0 + tm + 16 * jj) * N;
        U64F2 u0, u1, u2, u3;
        u0.u = acc[jj][0]; u1.u = acc[jj][1];
        u2.u = acc[jj][2]; u3.u = acc[jj][3];
        float4 o0 = make_float4(u0.f.x + biasA.x, u0.f.y + biasA.y,
                                u1.f.x + biasA.z, u1.f.y + biasA.w);
        float4 o1 = make_float4(u2.f.x + biasB.x, u2.f.y + biasB.y,
                                u3.f.x + biasB.z, u3.f.y + biasB.w);
        *reinterpret_cast<float4*>(&C[ro + nA]) = o0;
        *reinterpret_cast<float4*>(&C[ro + nB]) = o1;
    }
}

// =====================================================================
// in_proj GEMM: A gathered K-major from x (k<64) / h (k>=64), K=256, N=192
// =====================================================================
__global__ __launch_bounds__(128)
void k_gemm_inproj(const float* __restrict__ X, const float* __restrict__ Hh,
                   const float* __restrict__ W, const float* __restrict__ bias,
                   float* __restrict__ C)
{
    const int K = 256, N = 192;
    __shared__ unsigned long long As2[16][129];
    __shared__ __align__(16) float Ws[16][64];

    const int m0 = blockIdx.y * 128;
    const int n0 = blockIdx.x * 64;
    const int tid = threadIdx.x;
    const int tm = tid & 15, tn = tid >> 4;

    const int m = m0 + tid;          // tile stays inside one batch (16384 % 128 == 0)
    const int b = m >> 14, p = m & 16383;

    unsigned long long acc[8][4];
#pragma unroll
    for (int i = 0; i < 8; i++)
#pragma unroll
        for (int q = 0; q < 4; q++) acc[i][q] = 0ull;

    for (int kt = 0; kt < 16; kt++) {
#pragma unroll
        for (int kk = 0; kk < 16; kk++) {
            int k = kt * 16 + kk;
            float v;
            if (k < 64) v = X[(((size_t)(b * 64 + k)) << 14) + p];
            else        v = Hh[(((size_t)(b * 192 + (k - 64))) << 14) + p];
            As2[kk][tid] = fdup(v);
        }
#pragma unroll
        for (int j = 0; j < 2; j++) {
            int f = tid + 128 * j;
            int row = f >> 2, v = f & 3;
            float4 w4 = *reinterpret_cast<const float4*>(
                &W[(size_t)(n0 + row) * K + kt * 16 + v * 4]);
            Ws[v * 4 + 0][row] = w4.x;
            Ws[v * 4 + 1][row] = w4.y;
            Ws[v * 4 + 2][row] = w4.z;
            Ws[v * 4 + 3][row] = w4.w;
        }
        __syncthreads();
#pragma unroll
        for (int k = 0; k < 16; k++) {
            unsigned long long afr[8];
#pragma unroll
            for (int jj = 0; jj < 8; jj++) afr[jj] = As2[k][tm + 16 * jj];
            ulonglong2 bA = *reinterpret_cast<const ulonglong2*>(&Ws[k][tn * 4]);
            ulonglong2 bB = *reinterpret_cast<const ulonglong2*>(&Ws[k][32 + tn * 4]);
            unsigned long long bfr[4] = { bA.x, bA.y, bB.x, bB.y };
#pragma unroll
            for (int jj = 0; jj < 8; jj++) {
#pragma unroll
                for (int q = 0; q < 4; q++) ffma2(acc[jj][q], afr[jj], bfr[q]);
            }
        }
        __syncthreads();
    }

    const int nA = n0 + tn * 4;
    const int nB = n0 + 32 + tn * 4;
    float4 biasA = *reinterpret_cast<const float4*>(&bias[nA]);
    float4 biasB = *reinterpret_cast<const float4*>(&bias[nB]);
#pragma unroll
    for (int jj = 0; jj < 8; jj++) {
        size_t ro = (size_t)(m0 + tm + 16 * jj) * N;
        U64F2 u0, u1, u2, u3;
        u0.u = acc[jj][0]; u1.u = acc[jj][1];
        u2.u = acc[jj][2]; u3.u = acc[jj][3];
        float4 o0 = make_float4(u0.f.x + biasA.x, u0.f.y + biasA.y,
                                u1.f.x + biasA.z, u1.f.y + biasA.w);
        float4 o1 = make_float4(u2.f.x + biasB.x, u2.f.y + biasB.y,
                                u3.f.x + biasB.z, u3.f.y + biasB.w);
        *reinterpret_cast<float4*>(&C[ro + nA]) = o0;
        *reinterpret_cast<float4*>(&C[ro + nB]) = o1;
    }
}

// =====================================================================
// LayerNorm over 192 channels, one warp per token
// =====================================================================
__global__ __launch_bounds__(256)
void k_ln(const float* __restrict__ lng, const float* __restrict__ lnb)
{
    int warp = (blockIdx.x * blockDim.x + threadIdx.x) >> 5;
    int lane = threadIdx.x & 31;
    const float* row = &g_proj[(size_t)warp * 192];
    float v[6];
    float s = 0.f;
#pragma unroll
    for (int j = 0; j < 6; j++) { v[j] = row[lane + 32 * j]; s += v[j]; }
#pragma unroll
    for (int o = 16; o; o >>= 1) s += __shfl_xor_sync(0xffffffffu, s, o);
    float mean = s * (1.0f / 192.0f);
    float q = 0.f;
#pragma unroll
    for (int j = 0; j < 6; j++) { float d = v[j] - mean; q += d * d; }
#pragma unroll
    for (int o = 16; o; o >>= 1) q += __shfl_xor_sync(0xffffffffu, q, o);
    float inv = rsqrtf(q * (1.0f / 192.0f) + 1e-5f);
    float* dst = &g_xn[(size_t)warp * 192];
#pragma unroll
    for (int j = 0; j < 6; j++) {
        int c = lane + 32 * j;
        dst[c] = (v[j] - mean) * inv * lng[c] + lnb[c];
    }
}

// =====================================================================
// Window attention: one block per 4x4 window (8192 blocks)
// =====================================================================
__global__ __launch_bounds__(256)
void k_attn()
{
    __shared__ float sq[16 * 576];
    __shared__ float ss[4 * 16 * 16];
    __shared__ int smm[16];

    int w = blockIdx.x;
    int tid = threadIdx.x;
    if (tid < 16) {
        int b = w >> 10, wi = w & 1023, wy = wi >> 5, wx = wi & 31;
        int ty = tid >> 2, tx = tid & 3;
        smm[tid] = (b << 14) + ((wy * 4 + ty) << 7) + (wx * 4 + tx);
    }
    __syncthreads();

    for (int i = tid; i < 16 * 576; i += 256) {
        int t = i / 576, c = i - t * 576;
        sq[i] = g_qkv[(size_t)smm[t] * 576 + c];
    }
    __syncthreads();

    {   // scores: 4 heads x 16x16
        int h = tid >> 6, r = (tid >> 2) & 15, c0 = (tid & 3) * 4;
        const float* qrow = &sq[r * 576 + h * 48];
#pragma unroll
        for (int cc = 0; cc < 4; cc++) {
            const float* krow = &sq[(c0 + cc) * 576 + 192 + h * 48];
            float d = 0.f;
#pragma unroll
            for (int k = 0; k < 48; k++) d += qrow[k] * krow[k];
            ss[(h * 16 + r) * 16 + c0 + cc] = d * 0.14433756729740643f; // 48^-0.5
        }
    }
    __syncthreads();

    if (tid < 64) {  // softmax per row
        float* row = &ss[tid * 16];
        float mx = row[0];
#pragma unroll
        for (int j = 1; j < 16; j++) mx = fmaxf(mx, row[j]);
        float sm = 0.f;
#pragma unroll
        for (int j = 0; j < 16; j++) { float e = __expf(row[j] - mx); row[j] = e; sm += e; }
        float r = 1.f / sm;
#pragma unroll
        for (int j = 0; j < 16; j++) row[j] *= r;
    }
    __syncthreads();

    for (int i = tid; i < 16 * 192; i += 256) {
        int r = i / 192, c = i - r * 192;
        int h = c / 48, d = c - h * 48;
        const float* srow = &ss[(h * 16 + r) * 16];
        const float* vcol = &sq[384 + h * 48 + d];
        float o = 0.f;
#pragma unroll
        for (int j = 0; j < 16; j++) o += srow[j] * vcol[j * 576];
        g_attn[(size_t)smm[r] * 192 + c] = o;
    }
}

// =====================================================================
// GroupNorm #1 (over token-major amap): deterministic partial sums
// =====================================================================
__global__ __launch_bounds__(192)
void k_gn1_stats()
{
    int b = blockIdx.x >> 6;
    int chunk = blockIdx.x & 63;
    int c = threadIdx.x;
    size_t base = ((size_t)(b * 16384 + chunk * 256)) * 192 + c;
    float s = 0.f, q = 0.f;
    for (int r = 0; r < 256; r++) {
        float v = g_amap[base + (size_t)r * 192];
        s += v; q += v * v;
    }
    g_p1s[(b * 192 + c) * 64 + chunk] = s;
    g_p1q[(b * 192 + c) * 64 + chunk] = q;
}

__global__ void k_gn1_final()
{
    int t = threadIdx.x;
    if (t >= 64) return;
    int b = t >> 3, g = t & 7;
    float S = 0.f, Q = 0.f;
    for (int i = 0; i < 24; i++) {
        int cc = b * 192 + g * 24 + i;
        for (int ch = 0; ch < 64; ch++) { S += g_p1s[cc * 64 + ch]; Q += g_p1q[cc * 64 + ch]; }
    }
    const float inv_n = 1.0f / 393216.0f;
    float mu = S * inv_n;
    float var = Q * inv_n - mu * mu;
    g_mu1[t] = mu;
    g_inv1[t] = rsqrtf(var + 1e-5f);
}

__global__ __launch_bounds__(256)
void k_norm1(const float* __restrict__ gg, const float* __restrict__ gb)
{
    size_t idx4 = (size_t)blockIdx.x * 256 + threadIdx.x;
    size_t base = idx4 * 4;
    int c = (int)(base % 192);
    int b = (int)(base / 3145728);   // 192*16384
    int grp = c / 24;
    float mu = g_mu1[b * 8 + grp], inv = g_inv1[b * 8 + grp];
    float4 v = *reinterpret_cast<const float4*>(&g_amap[base]);
    float4 o;
    o.x = (v.x - mu) * inv * gg[c + 0] + gb[c + 0];
    o.y = (v.y - mu) * inv * gg[c + 1] + gb[c + 1];
    o.z = (v.z - mu) * inv * gg[c + 2] + gb[c + 2];
    o.w = (v.w - mu) * inv * gg[c + 3] + gb[c + 3];
    *reinterpret_cast<float4*>(&g_proj[base]) = o;   // reuse g_proj as anorm
}

// =====================================================================
// LSTM pointwise: reads gates tile through smem (transpose), writes
// cnext (to d_out second half, BCHW) and raw hnext (BCHW scratch)
// =====================================================================
__global__ __launch_bounds__(256)
void k_lstm(const float* __restrict__ Cin, float* __restrict__ out)
{
    __shared__ float gs[16 * 768];
    int tok0 = blockIdx.x * 16;
    int b = tok0 >> 14;
    int p0 = tok0 & 16383;
    int tid = threadIdx.x;
    for (int i = tid; i < 16 * 768; i += 256) gs[i] = g_gates[(size_t)tok0 * 768 + i];
    __syncthreads();
#pragma unroll
    for (int it = 0; it < 12; it++) {
        int idx = tid + 256 * it;        // 0..3071
        int pl = idx / 192, n = idx - pl * 192;
        float gi = gs[pl * 768 + n];
        float gf = gs[pl * 768 + n + 192];
        float go = gs[pl * 768 + n + 384];
        float gG = gs[pl * 768 + n + 576];
        float i_ = 1.f / (1.f + __expf(-gi));
        float f_ = 1.f / (1.f + __expf(-gf));
        float o_ = 1.f / (1.f + __expf(-go));
        float g_ = tanhf(gG);
        size_t addr = ((size_t)(b * 192 + n) << 14) + p0 + pl;
        float cp = Cin[addr];
        float cn = f_ * cp + i_ * g_;
        out[(size_t)HSZ + addr] = cn;
        g_hraw[addr] = o_ * tanhf(cn);
    }
}

// =====================================================================
// GroupNorm #2 over BCHW hraw (contiguous per (b,g))
// =====================================================================
__global__ __launch_bounds__(256)
void k_gn2_stats()
{
    __shared__ float rs[256], rq[256];
    int grp = blockIdx.x >> 4;     // 64 groups
    int part = blockIdx.x & 15;
    int b = grp >> 3, g = grp & 7;
    size_t base = ((size_t)(b * 192 + g * 24) << 14) + (size_t)part * 24576;
    int tid = threadIdx.x;
    float s = 0.f, q = 0.f;
    for (int j = 0; j < 96; j++) {
        float v = g_hraw[base + tid + 256 * j];
        s += v; q += v * v;
    }
    rs[tid] = s; rq[tid] = q;
    __syncthreads();
    for (int o = 128; o; o >>= 1) {
        if (tid < o) { rs[tid] += rs[tid + o]; rq[tid] += rq[tid + o]; }
        __syncthreads();
    }
    if (tid == 0) { g_p2s[grp * 16 + part] = rs[0]; g_p2q[grp * 16 + part] = rq[0]; }
}

__global__ void k_gn2_final()
{
    int t = threadIdx.x;
    if (t >= 64) return;
    float S = 0.f, Q = 0.f;
    for (int i = 0; i < 16; i++) { S += g_p2s[t * 16 + i]; Q += g_p2q[t * 16 + i]; }
    const float inv_n = 1.0f / 393216.0f;
    float mu = S * inv_n;
    float var = Q * inv_n - mu * mu;
    g_mu2[t] = mu;
    g_inv2[t] = rsqrtf(var + 1e-5f);
}

__global__ __launch_bounds__(256)
void k_finalize(const float* __restrict__ gg, const float* __restrict__ gb,
                float* __restrict__ out)
{
    size_t idx4 = (size_t)blockIdx.x * 256 + threadIdx.x;
    size_t base = idx4 * 4;
    int bc = (int)(base >> 14);      // b*192 + c
    int b = bc / 192;
    int c = bc - b * 192;
    int grp = c / 24;
    float mu = g_mu2[b * 8 + grp], inv = g_inv2[b * 8 + grp];
    float sc = gg[c] * inv;
    float bi = gb[c];
    float4 v = *reinterpret_cast<const float4*>(&g_hraw[base]);
    float4 o;
    o.x = (v.x - mu) * sc + bi;
    o.y = (v.y - mu) * sc + bi;
    o.z = (v.z - mu) * sc + bi;
    o.w = (v.w - mu) * sc + bi;
    *reinterpret_cast<float4*>(&out[base]) = o;
}

// =====================================================================
// host launcher
// =====================================================================
extern "C" void kernel_launch(void* const* d_in, const int* in_sizes, int n_in,
                              void* d_out, int out_size)
{
    const float* x       = (const float*)d_in[0];
    const float* h       = (const float*)d_in[1];
    const float* c       = (const float*)d_in[2];
    const float* w_in    = (const float*)d_in[3];
    const float* b_in    = (const float*)d_in[4];
    const float* ln_g    = (const float*)d_in[5];
    const float* ln_b    = (const float*)d_in[6];
    const float* w_qkv   = (const float*)d_in[7];
    const float* b_qkv   = (const float*)d_in[8];
    const float* w_proj  = (const float*)d_in[9];
    const float* b_proj  = (const float*)d_in[10];
    const float* gn_g    = (const float*)d_in[11];
    const float* gn_b    = (const float*)d_in[12];
    const float* w_gates = (const float*)d_in[13];
    const float* b_gates = (const float*)d_in[14];
    float* out = (float*)d_out;

    void *p_proj, *p_xn, *p_qkv, *p_attn, *p_amap, *p_gates;
    cudaGetSymbolAddress(&p_proj,  g_proj);
    cudaGetSymbolAddress(&p_xn,    g_xn);
    cudaGetSymbolAddress(&p_qkv,   g_qkv);
    cudaGetSymbolAddress(&p_attn,  g_attn);
    cudaGetSymbolAddress(&p_amap,  g_amap);
    cudaGetSymbolAddress(&p_gates, g_gates);

    // 1) in_proj (concat(x,h) @ w_in^T + b_in) -> g_proj
    k_gemm_inproj<<<dim3(3, 1024), 128>>>(x, h, w_in, b_in, (float*)p_proj);
    // 2) LayerNorm -> g_xn
    k_ln<<<16384, 256>>>(ln_g, ln_b);
    // 3) qkv GEMM -> g_qkv
    k_gemm_rm<<<dim3(9, 1024), 128>>>((const float*)p_xn, w_qkv, b_qkv,
                                      (float*)p_qkv, 192, 576);
    // 4) window attention -> g_attn
    k_attn<<<8192, 256>>>();
    // 5) out_proj GEMM -> g_amap
    k_gemm_rm<<<dim3(3, 1024), 128>>>((const float*)p_attn, w_proj, b_proj,
                                      (float*)p_amap, 192, 192);
    // 6) GroupNorm(amap)
    k_gn1_stats<<<512, 192>>>();
    k_gn1_final<<<1, 64>>>();
    k_norm1<<<24576, 256>>>(gn_g, gn_b);
    // 7) gates GEMM -> g_gates
    k_gemm_rm<<<dim3(12, 1024), 128>>>((const float*)p_proj, w_gates, b_gates,
                                       (float*)p_gates, 192, 768);
    // 8) LSTM pointwise -> cnext (d_out) + hraw
    k_lstm<<<8192, 256>>>(c, out);
    // 9) GroupNorm(hnext) -> d_out first half
    k_gn2_stats<<<1024, 256>>>();
    k_gn2_final<<<1, 64>>>();
    k_finalize<<<24576, 256>>>(gn_g, gn_b, out);
}

// round 3
// speedup vs baseline: 1.7398x; 1.7398x over previous
#include <cuda_runtime.h>
#include <cstdint>

// ---------------- problem constants ----------------
#define TOK    131072              // B*H*W tokens (raster order)
#define HSZ    25165824            // 8*192*128*128 (one output tensor)

// ---------------- static device scratch ----------------
__device__ float g_comb[(size_t)TOK * 256];   // packed concat(x,h), token-major
__device__ float g_proj[(size_t)TOK * 192];   // in_proj out; later reused as normalized amap
__device__ float g_xn  [(size_t)TOK * 192];   // layernorm out
__device__ float g_qkv [(size_t)TOK * 576];
__device__ float g_attn[(size_t)TOK * 192];
__device__ float g_amap[(size_t)TOK * 192];
__device__ float g_gates[(size_t)TOK * 768];
__device__ float g_hraw[(size_t)TOK * 192];   // BCHW layout
__device__ float g_p1s[8 * 192 * 64];
__device__ float g_p1q[8 * 192 * 64];
__device__ float g_mu1[64], g_inv1[64];
__device__ float g_p2s[64 * 16], g_p2q[64 * 16];
__device__ float g_mu2[64], g_inv2[64];

// ---------------- PTX helpers ----------------
#define CP_ASYNC16(sm, gp) \
    asm volatile("cp.async.cg.shared.global [%0], [%1], 16;" :: "r"((uint32_t)(sm)), "l"(gp))
#define CP_COMMIT() asm volatile("cp.async.commit_group;" ::: "memory")
#define CP_WAIT(n)  asm volatile("cp.async.wait_group %0;" :: "n"(n) : "memory")

__device__ __forceinline__ uint32_t smem_to_u32(const void* p) {
    uint32_t a;
    asm("{ .reg .u64 t; cvta.to.shared.u64 t, %1; cvt.u32.u64 %0, t; }" : "=r"(a) : "l"(p));
    return a;
}
__device__ __forceinline__ uint32_t f2tf32(float f) {
    uint32_t r;
    asm("cvt.rna.tf32.f32 %0, %1;" : "=r"(r) : "f"(f));
    return r;
}
__device__ __forceinline__ void mma_tf32(float& c0, float& c1, float& c2, float& c3,
                                         uint32_t a0, uint32_t a1, uint32_t a2, uint32_t a3,
                                         uint32_t b0, uint32_t b1) {
    asm volatile("mma.sync.aligned.m16n8k8.row.col.f32.tf32.tf32.f32 "
                 "{%0,%1,%2,%3}, {%4,%5,%6,%7}, {%8,%9}, {%0,%1,%2,%3};"
                 : "+f"(c0), "+f"(c1), "+f"(c2), "+f"(c3)
                 : "r"(a0), "r"(a1), "r"(a2), "r"(a3), "r"(b0), "r"(b1));
}

// =====================================================================
// Tensor-core tf32 GEMM: C[M, Ntot] = A[M, K] * W[Ntot, K]^T + bias
// CTA tile 128x64, warp tile 32x32 (8 warps: 4m x 2n), kc=16,
// double-buffered cp.async. grid = (Ntot/64, M/128), 256 threads.
// =====================================================================
template<int K>
__global__ __launch_bounds__(256)
void k_tc(const float* __restrict__ A, const float* __restrict__ W,
          const float* __restrict__ bias, float* __restrict__ C, int Ntot)
{
    constexpr int NCH = K / 16;
    constexpr int AST = 20;                 // padded row stride (floats)
    __shared__ float As[2][128 * AST];
    __shared__ float Bs[2][64 * AST];

    const int tid  = threadIdx.x;
    const int lane = tid & 31;
    const int warp = tid >> 5;
    const int wm = warp & 3, wn = warp >> 2;
    const int m0 = blockIdx.y * 128;
    const int n0 = blockIdx.x * 64;

    const uint32_t sA0 = smem_to_u32(&As[0][0]);
    const uint32_t sA1 = smem_to_u32(&As[1][0]);
    const uint32_t sB0 = smem_to_u32(&Bs[0][0]);
    const uint32_t sB1 = smem_to_u32(&Bs[1][0]);

    float acc[2][4][4];
#pragma unroll
    for (int i = 0; i < 2; i++)
#pragma unroll
        for (int j = 0; j < 4; j++)
#pragma unroll
            for (int q = 0; q < 4; q++) acc[i][j][q] = 0.f;

    auto prefetch = [&](int kt) {
        int buf = kt & 1;
        uint32_t sa = buf ? sA1 : sA0;
        uint32_t sbb = buf ? sB1 : sB0;
        const float* ag = A + (size_t)m0 * K + kt * 16;
        const float* bg = W + (size_t)n0 * K + kt * 16;
        // A: 128 rows x 4 16B-chunks = 512 chunks, 2 per thread
#pragma unroll
        for (int j = 0; j < 2; j++) {
            int cidx = tid + 256 * j;
            int row = cidx >> 2, off = cidx & 3;
            CP_ASYNC16(sa + (uint32_t)(row * AST + off * 4) * 4,
                       ag + (size_t)row * K + off * 4);
        }
        // B: 64 rows x 4 chunks = 256 chunks, 1 per thread
        {
            int row = tid >> 2, off = tid & 3;
            CP_ASYNC16(sbb + (uint32_t)(row * AST + off * 4) * 4,
                       bg + (size_t)row * K + off * 4);
        }
        CP_COMMIT();
    };

    prefetch(0);

    for (int kt = 0; kt < NCH; kt++) {
        if (kt + 1 < NCH) { prefetch(kt + 1); CP_WAIT(1); }
        else              { CP_WAIT(0); }
        __syncthreads();
        const float* as = As[kt & 1];
        const float* bs = Bs[kt & 1];
#pragma unroll
        for (int ks = 0; ks < 2; ks++) {
            const int kk = ks * 8;
            uint32_t af[2][4];
#pragma unroll
            for (int mf = 0; mf < 2; mf++) {
                int r = wm * 32 + mf * 16 + (lane >> 2);
                int cc = kk + (lane & 3);
                af[mf][0] = f2tf32(as[r * AST + cc]);
                af[mf][1] = f2tf32(as[(r + 8) * AST + cc]);
                af[mf][2] = f2tf32(as[r * AST + cc + 4]);
                af[mf][3] = f2tf32(as[(r + 8) * AST + cc + 4]);
            }
            uint32_t bf[4][2];
#pragma unroll
            for (int nf = 0; nf < 4; nf++) {
                int r = wn * 32 + nf * 8 + (lane >> 2);
                int cc = kk + (lane & 3);
                bf[nf][0] = f2tf32(bs[r * AST + cc]);
                bf[nf][1] = f2tf32(bs[r * AST + cc + 4]);
            }
#pragma unroll
            for (int mf = 0; mf < 2; mf++)
#pragma unroll
                for (int nf = 0; nf < 4; nf++)
                    mma_tf32(acc[mf][nf][0], acc[mf][nf][1], acc[mf][nf][2], acc[mf][nf][3],
                             af[mf][0], af[mf][1], af[mf][2], af[mf][3],
                             bf[nf][0], bf[nf][1]);
        }
        __syncthreads();
    }

    // epilogue
#pragma unroll
    for (int mf = 0; mf < 2; mf++) {
        int row = m0 + wm * 32 + mf * 16 + (lane >> 2);
#pragma unroll
        for (int nf = 0; nf < 4; nf++) {
            int col = n0 + wn * 32 + nf * 8 + 2 * (lane & 3);
            float bx = bias[col], by = bias[col + 1];
            float2 o0 = make_float2(acc[mf][nf][0] + bx, acc[mf][nf][1] + by);
            float2 o1 = make_float2(acc[mf][nf][2] + bx, acc[mf][nf][3] + by);
            *reinterpret_cast<float2*>(&C[(size_t)row * Ntot + col]) = o0;
            *reinterpret_cast<float2*>(&C[(size_t)(row + 8) * Ntot + col]) = o1;
        }
    }
}

// =====================================================================
// pack concat(x,h) BCHW -> token-major [M, 256]
// =====================================================================
__global__ __launch_bounds__(256)
void k_pack(const float* __restrict__ X, const float* __restrict__ Hh)
{
    __shared__ float t[64][65];
    int mt = blockIdx.x;
    int ct = blockIdx.y;
    int b = (mt * 64) >> 14;
    int p0 = (mt * 64) & 16383;
    for (int i = threadIdx.x; i < 4096; i += 256) {
        int ch = i >> 6, tok = i & 63;
        int c = ct * 64 + ch;
        float v;
        if (c < 64) v = X [(((size_t)(b * 64  + c))        << 14) + p0 + tok];
        else        v = Hh[(((size_t)(b * 192 + (c - 64))) << 14) + p0 + tok];
        t[tok][ch] = v;
    }
    __syncthreads();
    for (int i = threadIdx.x; i < 4096; i += 256) {
        int tok = i >> 6, ch = i & 63;
        g_comb[(size_t)(mt * 64 + tok) * 256 + ct * 64 + ch] = t[tok][ch];
    }
}

// =====================================================================
// LayerNorm over 192 channels, one warp per token
// =====================================================================
__global__ __launch_bounds__(256)
void k_ln(const float* __restrict__ lng, const float* __restrict__ lnb)
{
    int warp = (blockIdx.x * blockDim.x + threadIdx.x) >> 5;
    int lane = threadIdx.x & 31;
    const float* row = &g_proj[(size_t)warp * 192];
    float v[6];
    float s = 0.f;
#pragma unroll
    for (int j = 0; j < 6; j++) { v[j] = row[lane + 32 * j]; s += v[j]; }
#pragma unroll
    for (int o = 16; o; o >>= 1) s += __shfl_xor_sync(0xffffffffu, s, o);
    float mean = s * (1.0f / 192.0f);
    float q = 0.f;
#pragma unroll
    for (int j = 0; j < 6; j++) { float d = v[j] - mean; q += d * d; }
#pragma unroll
    for (int o = 16; o; o >>= 1) q += __shfl_xor_sync(0xffffffffu, q, o);
    float inv = rsqrtf(q * (1.0f / 192.0f) + 1e-5f);
    float* dst = &g_xn[(size_t)warp * 192];
#pragma unroll
    for (int j = 0; j < 6; j++) {
        int c = lane + 32 * j;
        dst[c] = (v[j] - mean) * inv * lng[c] + lnb[c];
    }
}

// =====================================================================
// Window attention (padded smem stride 580 -> no 32-bank aliasing)
// =====================================================================
#define QS 580
__global__ __launch_bounds__(256)
void k_attn()
{
    __shared__ float sq[16 * QS];
    __shared__ float ss[4 * 16 * 16];
    __shared__ int smm[16];

    int w = blockIdx.x;
    int tid = threadIdx.x;
    if (tid < 16) {
        int b = w >> 10, wi = w & 1023, wy = wi >> 5, wx = wi & 31;
        int ty = tid >> 2, tx = tid & 3;
        smm[tid] = (b << 14) + ((wy * 4 + ty) << 7) + (wx * 4 + tx);
    }
    __syncthreads();

    for (int i = tid; i < 16 * 576; i += 256) {
        int t = i / 576, c = i - t * 576;
        sq[t * QS + c] = g_qkv[(size_t)smm[t] * 576 + c];
    }
    __syncthreads();

    {   // scores: 4 heads x 16x16
        int h = tid >> 6, r = (tid >> 2) & 15, c0 = (tid & 3) * 4;
        const float* qrow = &sq[r * QS + h * 48];
#pragma unroll
        for (int cc = 0; cc < 4; cc++) {
            const float* krow = &sq[(c0 + cc) * QS + 192 + h * 48];
            float d = 0.f;
#pragma unroll
            for (int k = 0; k < 48; k++) d += qrow[k] * krow[k];
            ss[(h * 16 + r) * 16 + c0 + cc] = d * 0.14433756729740643f;
        }
    }
    __syncthreads();

    if (tid < 64) {  // softmax per row
        float* row = &ss[tid * 16];
        float mx = row[0];
#pragma unroll
        for (int j = 1; j < 16; j++) mx = fmaxf(mx, row[j]);
        float sm = 0.f;
#pragma unroll
        for (int j = 0; j < 16; j++) { float e = __expf(row[j] - mx); row[j] = e; sm += e; }
        float r = 1.f / sm;
#pragma unroll
        for (int j = 0; j < 16; j++) row[j] *= r;
    }
    __syncthreads();

    for (int i = tid; i < 16 * 192; i += 256) {
        int r = i / 192, c = i - r * 192;
        int h = c / 48, d = c - h * 48;
        const float* srow = &ss[(h * 16 + r) * 16];
        const float* vcol = &sq[384 + h * 48 + d];
        float o = 0.f;
#pragma unroll
        for (int j = 0; j < 16; j++) o += srow[j] * vcol[j * QS];
        g_attn[(size_t)smm[r] * 192 + c] = o;
    }
}

// =====================================================================
// GroupNorm #1 (token-major amap)
// =====================================================================
__global__ __launch_bounds__(192)
void k_gn1_stats()
{
    int b = blockIdx.x >> 6;
    int chunk = blockIdx.x & 63;
    int c = threadIdx.x;
    size_t base = ((size_t)(b * 16384 + chunk * 256)) * 192 + c;
    float s = 0.f, q = 0.f;
    for (int r = 0; r < 256; r++) {
        float v = g_amap[base + (size_t)r * 192];
        s += v; q += v * v;
    }
    g_p1s[(b * 192 + c) * 64 + chunk] = s;
    g_p1q[(b * 192 + c) * 64 + chunk] = q;
}

__global__ void k_gn1_final()
{
    int t = threadIdx.x;
    if (t >= 64) return;
    int b = t >> 3, g = t & 7;
    float S = 0.f, Q = 0.f;
    for (int i = 0; i < 24; i++) {
        int cc = b * 192 + g * 24 + i;
        for (int ch = 0; ch < 64; ch++) { S += g_p1s[cc * 64 + ch]; Q += g_p1q[cc * 64 + ch]; }
    }
    const float inv_n = 1.0f / 393216.0f;
    float mu = S * inv_n;
    float var = Q * inv_n - mu * mu;
    g_mu1[t] = mu;
    g_inv1[t] = rsqrtf(var + 1e-5f);
}

__global__ __launch_bounds__(256)
void k_norm1(const float* __restrict__ gg, const float* __restrict__ gb)
{
    size_t idx4 = (size_t)blockIdx.x * 256 + threadIdx.x;
    size_t base = idx4 * 4;
    int c = (int)(base % 192);
    int b = (int)(base / 3145728);
    int grp = c / 24;
    float mu = g_mu1[b * 8 + grp], inv = g_inv1[b * 8 + grp];
    float4 v = *reinterpret_cast<const float4*>(&g_amap[base]);
    float4 o;
    o.x = (v.x - mu) * inv * gg[c + 0] + gb[c + 0];
    o.y = (v.y - mu) * inv * gg[c + 1] + gb[c + 1];
    o.z = (v.z - mu) * inv * gg[c + 2] + gb[c + 2];
    o.w = (v.w - mu) * inv * gg[c + 3] + gb[c + 3];
    *reinterpret_cast<float4*>(&g_proj[base]) = o;
}

// =====================================================================
// LSTM pointwise
// =====================================================================
__global__ __launch_bounds__(256)
void k_lstm(const float* __restrict__ Cin, float* __restrict__ out)
{
    __shared__ float gs[16 * 768];
    int tok0 = blockIdx.x * 16;
    int b = tok0 >> 14;
    int p0 = tok0 & 16383;
    int tid = threadIdx.x;
    for (int i = tid; i < 16 * 768; i += 256) gs[i] = g_gates[(size_t)tok0 * 768 + i];
    __syncthreads();
#pragma unroll
    for (int it = 0; it < 12; it++) {
        int idx = tid + 256 * it;
        int pl = idx / 192, n = idx - pl * 192;
        float gi = gs[pl * 768 + n];
        float gf = gs[pl * 768 + n + 192];
        float go = gs[pl * 768 + n + 384];
        float gG = gs[pl * 768 + n + 576];
        float i_ = 1.f / (1.f + __expf(-gi));
        float f_ = 1.f / (1.f + __expf(-gf));
        float o_ = 1.f / (1.f + __expf(-go));
        float g_ = tanhf(gG);
        size_t addr = ((size_t)(b * 192 + n) << 14) + p0 + pl;
        float cp = Cin[addr];
        float cn = f_ * cp + i_ * g_;
        out[(size_t)HSZ + addr] = cn;
        g_hraw[addr] = o_ * tanhf(cn);
    }
}

// =====================================================================
// GroupNorm #2 over BCHW hraw
// =====================================================================
__global__ __launch_bounds__(256)
void k_gn2_stats()
{
    __shared__ float rs[256], rq[256];
    int grp = blockIdx.x >> 4;
    int part = blockIdx.x & 15;
    int b = grp >> 3, g = grp & 7;
    size_t base = ((size_t)(b * 192 + g * 24) << 14) + (size_t)part * 24576;
    int tid = threadIdx.x;
    float s = 0.f, q = 0.f;
    for (int j = 0; j < 96; j++) {
        float v = g_hraw[base + tid + 256 * j];
        s += v; q += v * v;
    }
    rs[tid] = s; rq[tid] = q;
    __syncthreads();
    for (int o = 128; o; o >>= 1) {
        if (tid < o) { rs[tid] += rs[tid + o]; rq[tid] += rq[tid + o]; }
        __syncthreads();
    }
    if (tid == 0) { g_p2s[grp * 16 + part] = rs[0]; g_p2q[grp * 16 + part] = rq[0]; }
}

__global__ void k_gn2_final()
{
    int t = threadIdx.x;
    if (t >= 64) return;
    float S = 0.f, Q = 0.f;
    for (int i = 0; i < 16; i++) { S += g_p2s[t * 16 + i]; Q += g_p2q[t * 16 + i]; }
    const float inv_n = 1.0f / 393216.0f;
    float mu = S * inv_n;
    float var = Q * inv_n - mu * mu;
    g_mu2[t] = mu;
    g_inv2[t] = rsqrtf(var + 1e-5f);
}

__global__ __launch_bounds__(256)
void k_finalize(const float* __restrict__ gg, const float* __restrict__ gb,
                float* __restrict__ out)
{
    size_t idx4 = (size_t)blockIdx.x * 256 + threadIdx.x;
    size_t base = idx4 * 4;
    int bc = (int)(base >> 14);
    int b = bc / 192;
    int c = bc - b * 192;
    int grp = c / 24;
    float mu = g_mu2[b * 8 + grp], inv = g_inv2[b * 8 + grp];
    float sc = gg[c] * inv;
    float bi = gb[c];
    float4 v = *reinterpret_cast<const float4*>(&g_hraw[base]);
    float4 o;
    o.x = (v.x - mu) * sc + bi;
    o.y = (v.y - mu) * sc + bi;
    o.z = (v.z - mu) * sc + bi;
    o.w = (v.w - mu) * sc + bi;
    *reinterpret_cast<float4*>(&out[base]) = o;
}

// =====================================================================
// host launcher
// =====================================================================
extern "C" void kernel_launch(void* const* d_in, const int* in_sizes, int n_in,
                              void* d_out, int out_size)
{
    const float* x       = (const float*)d_in[0];
    const float* h       = (const float*)d_in[1];
    const float* c       = (const float*)d_in[2];
    const float* w_in    = (const float*)d_in[3];
    const float* b_in    = (const float*)d_in[4];
    const float* ln_g    = (const float*)d_in[5];
    const float* ln_b    = (const float*)d_in[6];
    const float* w_qkv   = (const float*)d_in[7];
    const float* b_qkv   = (const float*)d_in[8];
    const float* w_proj  = (const float*)d_in[9];
    const float* b_proj  = (const float*)d_in[10];
    const float* gn_g    = (const float*)d_in[11];
    const float* gn_b    = (const float*)d_in[12];
    const float* w_gates = (const float*)d_in[13];
    const float* b_gates = (const float*)d_in[14];
    float* out = (float*)d_out;

    void *p_comb, *p_proj, *p_xn, *p_qkv, *p_attn, *p_amap, *p_gates;
    cudaGetSymbolAddress(&p_comb,  g_comb);
    cudaGetSymbolAddress(&p_proj,  g_proj);
    cudaGetSymbolAddress(&p_xn,    g_xn);
    cudaGetSymbolAddress(&p_qkv,   g_qkv);
    cudaGetSymbolAddress(&p_attn,  g_attn);
    cudaGetSymbolAddress(&p_amap,  g_amap);
    cudaGetSymbolAddress(&p_gates, g_gates);

    // 1) pack concat(x,h) -> g_comb [M,256]
    k_pack<<<dim3(2048, 4), 256>>>(x, h);
    // 2) in_proj GEMM (K=256, N=192) -> g_proj
    k_tc<256><<<dim3(3, 1024), 256>>>((const float*)p_comb, w_in, b_in,
                                      (float*)p_proj, 192);
    // 3) LayerNorm -> g_xn
    k_ln<<<16384, 256>>>(ln_g, ln_b);
    // 4) qkv GEMM (K=192, N=576) -> g_qkv
    k_tc<192><<<dim3(9, 1024), 256>>>((const float*)p_xn, w_qkv, b_qkv,
                                      (float*)p_qkv, 576);
    // 5) window attention -> g_attn
    k_attn<<<8192, 256>>>();
    // 6) out_proj GEMM (K=192, N=192) -> g_amap
    k_tc<192><<<dim3(3, 1024), 256>>>((const float*)p_attn, w_proj, b_proj,
                                      (float*)p_amap, 192);
    // 7) GroupNorm(amap) -> g_proj (reused as anorm)
    k_gn1_stats<<<512, 192>>>();
    k_gn1_final<<<1, 64>>>();
    k_norm1<<<24576, 256>>>(gn_g, gn_b);
    // 8) gates GEMM (K=192, N=768) -> g_gates
    k_tc<192><<<dim3(12, 1024), 256>>>((const float*)p_proj, w_gates, b_gates,
                                       (float*)p_gates, 768);
    // 9) LSTM pointwise -> cnext (d_out second half) + hraw
    k_lstm<<<8192, 256>>>(c, out);
    // 10) GroupNorm(hnext) -> d_out first half
    k_gn2_stats<<<1024, 256>>>();
    k_gn2_final<<<1, 64>>>();
    k_finalize<<<24576, 256>>>(gn_g, gn_b, out);
}

// round 4
// speedup vs baseline: 1.7423x; 1.0014x over previous
#include <cuda_runtime.h>
#include <cstdint>

// ---------------- problem constants ----------------
#define TOK    131072              // B*H*W tokens (raster order)
#define HSZ    25165824            // 8*192*128*128 (one output tensor)

// ---------------- static device scratch ----------------
__device__ float g_comb[(size_t)TOK * 256];   // packed concat(x,h), token-major
__device__ float g_proj[(size_t)TOK * 192];   // in_proj out; later reused as normalized amap
__device__ float g_xn  [(size_t)TOK * 192];   // layernorm out
__device__ float g_qkv [(size_t)TOK * 576];
__device__ float g_attn[(size_t)TOK * 192];
__device__ float g_amap[(size_t)TOK * 192];
__device__ float g_gates[(size_t)TOK * 768];
__device__ float g_hraw[(size_t)TOK * 192];   // BCHW layout
__device__ float g_p1s[8 * 192 * 64];
__device__ float g_p1q[8 * 192 * 64];
__device__ float g_mu1[64], g_inv1[64];
__device__ float g_p2s[64 * 16], g_p2q[64 * 16];
__device__ float g_mu2[64], g_inv2[64];

// ---------------- PTX helpers ----------------
#define CP_ASYNC16(sm, gp) \
    asm volatile("cp.async.cg.shared.global [%0], [%1], 16;" :: "r"((uint32_t)(sm)), "l"(gp))
#define CP_COMMIT() asm volatile("cp.async.commit_group;" ::: "memory")
#define CP_WAIT(n)  asm volatile("cp.async.wait_group %0;" :: "n"(n) : "memory")

__device__ __forceinline__ uint32_t smem_to_u32(const void* p) {
    uint32_t a;
    asm("{ .reg .u64 t; cvta.to.shared.u64 t, %1; cvt.u32.u64 %0, t; }" : "=r"(a) : "l"(p));
    return a;
}
__device__ __forceinline__ uint32_t f2tf32(float f) {
    uint32_t r;
    asm("cvt.rna.tf32.f32 %0, %1;" : "=r"(r) : "f"(f));
    return r;
}
__device__ __forceinline__ void mma_tf32(float& c0, float& c1, float& c2, float& c3,
                                         uint32_t a0, uint32_t a1, uint32_t a2, uint32_t a3,
                                         uint32_t b0, uint32_t b1) {
    asm volatile("mma.sync.aligned.m16n8k8.row.col.f32.tf32.tf32.f32 "
                 "{%0,%1,%2,%3}, {%4,%5,%6,%7}, {%8,%9}, {%0,%1,%2,%3};"
                 : "+f"(c0), "+f"(c1), "+f"(c2), "+f"(c3)
                 : "r"(a0), "r"(a1), "r"(a2), "r"(a3), "r"(b0), "r"(b1));
}

// =====================================================================
// Tensor-core tf32 GEMM: C[M, Ntot] = A[M, K] * W[Ntot, K]^T + bias
// CTA tile 128x64, warp tile 32x32 (8 warps: 4m x 2n), kc=16,
// double-buffered cp.async. grid = (Ntot/64, M/128), 256 threads.
// =====================================================================
template<int K>
__global__ __launch_bounds__(256)
void k_tc(const float* __restrict__ A, const float* __restrict__ W,
          const float* __restrict__ bias, float* __restrict__ C, int Ntot)
{
    constexpr int NCH = K / 16;
    constexpr int AST = 20;                 // padded row stride (floats)
    __shared__ float As[2][128 * AST];
    __shared__ float Bs[2][64 * AST];

    const int tid  = threadIdx.x;
    const int lane = tid & 31;
    const int warp = tid >> 5;
    const int wm = warp & 3, wn = warp >> 2;
    const int m0 = blockIdx.y * 128;
    const int n0 = blockIdx.x * 64;

    const uint32_t sA0 = smem_to_u32(&As[0][0]);
    const uint32_t sA1 = smem_to_u32(&As[1][0]);
    const uint32_t sB0 = smem_to_u32(&Bs[0][0]);
    const uint32_t sB1 = smem_to_u32(&Bs[1][0]);

    float acc[2][4][4];
#pragma unroll
    for (int i = 0; i < 2; i++)
#pragma unroll
        for (int j = 0; j < 4; j++)
#pragma unroll
            for (int q = 0; q < 4; q++) acc[i][j][q] = 0.f;

    auto prefetch = [&](int kt) {
        int buf = kt & 1;
        uint32_t sa = buf ? sA1 : sA0;
        uint32_t sbb = buf ? sB1 : sB0;
        const float* ag = A + (size_t)m0 * K + kt * 16;
        const float* bg = W + (size_t)n0 * K + kt * 16;
        // A: 128 rows x 4 16B-chunks = 512 chunks, 2 per thread
#pragma unroll
        for (int j = 0; j < 2; j++) {
            int cidx = tid + 256 * j;
            int row = cidx >> 2, off = cidx & 3;
            CP_ASYNC16(sa + (uint32_t)(row * AST + off * 4) * 4,
                       ag + (size_t)row * K + off * 4);
        }
        // B: 64 rows x 4 chunks = 256 chunks, 1 per thread
        {
            int row = tid >> 2, off = tid & 3;
            CP_ASYNC16(sbb + (uint32_t)(row * AST + off * 4) * 4,
                       bg + (size_t)row * K + off * 4);
        }
        CP_COMMIT();
    };

    prefetch(0);

    for (int kt = 0; kt < NCH; kt++) {
        if (kt + 1 < NCH) { prefetch(kt + 1); CP_WAIT(1); }
        else              { CP_WAIT(0); }
        __syncthreads();
        const float* as = As[kt & 1];
        const float* bs = Bs[kt & 1];
#pragma unroll
        for (int ks = 0; ks < 2; ks++) {
            const int kk = ks * 8;
            uint32_t af[2][4];
#pragma unroll
            for (int mf = 0; mf < 2; mf++) {
                int r = wm * 32 + mf * 16 + (lane >> 2);
                int cc = kk + (lane & 3);
                af[mf][0] = f2tf32(as[r * AST + cc]);
                af[mf][1] = f2tf32(as[(r + 8) * AST + cc]);
                af[mf][2] = f2tf32(as[r * AST + cc + 4]);
                af[mf][3] = f2tf32(as[(r + 8) * AST + cc + 4]);
            }
            uint32_t bf[4][2];
#pragma unroll
            for (int nf = 0; nf < 4; nf++) {
                int r = wn * 32 + nf * 8 + (lane >> 2);
                int cc = kk + (lane & 3);
                bf[nf][0] = f2tf32(bs[r * AST + cc]);
                bf[nf][1] = f2tf32(bs[r * AST + cc + 4]);
            }
#pragma unroll
            for (int mf = 0; mf < 2; mf++)
#pragma unroll
                for (int nf = 0; nf < 4; nf++)
                    mma_tf32(acc[mf][nf][0], acc[mf][nf][1], acc[mf][nf][2], acc[mf][nf][3],
                             af[mf][0], af[mf][1], af[mf][2], af[mf][3],
                             bf[nf][0], bf[nf][1]);
        }
        __syncthreads();
    }

    // epilogue
#pragma unroll
    for (int mf = 0; mf < 2; mf++) {
        int row = m0 + wm * 32 + mf * 16 + (lane >> 2);
#pragma unroll
        for (int nf = 0; nf < 4; nf++) {
            int col = n0 + wn * 32 + nf * 8 + 2 * (lane & 3);
            float bx = bias[col], by = bias[col + 1];
            float2 o0 = make_float2(acc[mf][nf][0] + bx, acc[mf][nf][1] + by);
            float2 o1 = make_float2(acc[mf][nf][2] + bx, acc[mf][nf][3] + by);
            *reinterpret_cast<float2*>(&C[(size_t)row * Ntot + col]) = o0;
            *reinterpret_cast<float2*>(&C[(size_t)(row + 8) * Ntot + col]) = o1;
        }
    }
}

// =====================================================================
// pack concat(x,h) BCHW -> token-major [M, 256]
// =====================================================================
__global__ __launch_bounds__(256)
void k_pack(const float* __restrict__ X, const float* __restrict__ Hh)
{
    __shared__ float t[64][65];
    int mt = blockIdx.x;
    int ct = blockIdx.y;
    int b = (mt * 64) >> 14;
    int p0 = (mt * 64) & 16383;
    for (int i = threadIdx.x; i < 4096; i += 256) {
        int ch = i >> 6, tok = i & 63;
        int c = ct * 64 + ch;
        float v;
        if (c < 64) v = X [(((size_t)(b * 64  + c))        << 14) + p0 + tok];
        else        v = Hh[(((size_t)(b * 192 + (c - 64))) << 14) + p0 + tok];
        t[tok][ch] = v;
    }
    __syncthreads();
    for (int i = threadIdx.x; i < 4096; i += 256) {
        int tok = i >> 6, ch = i & 63;
        g_comb[(size_t)(mt * 64 + tok) * 256 + ct * 64 + ch] = t[tok][ch];
    }
}

// =====================================================================
// LayerNorm over 192 channels, one warp per token
// =====================================================================
__global__ __launch_bounds__(256)
void k_ln(const float* __restrict__ lng, const float* __restrict__ lnb)
{
    int warp = (blockIdx.x * blockDim.x + threadIdx.x) >> 5;
    int lane = threadIdx.x & 31;
    const float* row = &g_proj[(size_t)warp * 192];
    float v[6];
    float s = 0.f;
#pragma unroll
    for (int j = 0; j < 6; j++) { v[j] = row[lane + 32 * j]; s += v[j]; }
#pragma unroll
    for (int o = 16; o; o >>= 1) s += __shfl_xor_sync(0xffffffffu, s, o);
    float mean = s * (1.0f / 192.0f);
    float q = 0.f;
#pragma unroll
    for (int j = 0; j < 6; j++) { float d = v[j] - mean; q += d * d; }
#pragma unroll
    for (int o = 16; o; o >>= 1) q += __shfl_xor_sync(0xffffffffu, q, o);
    float inv = rsqrtf(q * (1.0f / 192.0f) + 1e-5f);
    float* dst = &g_xn[(size_t)warp * 192];
#pragma unroll
    for (int j = 0; j < 6; j++) {
        int c = lane + 32 * j;
        dst[c] = (v[j] - mean) * inv * lng[c] + lnb[c];
    }
}

// =====================================================================
// Window attention (padded smem stride 580 -> no 32-bank aliasing)
// =====================================================================
#define QS 580
__global__ __launch_bounds__(256)
void k_attn()
{
    __shared__ float sq[16 * QS];
    __shared__ float ss[4 * 16 * 16];
    __shared__ int smm[16];

    int w = blockIdx.x;
    int tid = threadIdx.x;
    if (tid < 16) {
        int b = w >> 10, wi = w & 1023, wy = wi >> 5, wx = wi & 31;
        int ty = tid >> 2, tx = tid & 3;
        smm[tid] = (b << 14) + ((wy * 4 + ty) << 7) + (wx * 4 + tx);
    }
    __syncthreads();

    for (int i = tid; i < 16 * 576; i += 256) {
        int t = i / 576, c = i - t * 576;
        sq[t * QS + c] = g_qkv[(size_t)smm[t] * 576 + c];
    }
    __syncthreads();

    {   // scores: 4 heads x 16x16
        int h = tid >> 6, r = (tid >> 2) & 15, c0 = (tid & 3) * 4;
        const float* qrow = &sq[r * QS + h * 48];
#pragma unroll
        for (int cc = 0; cc < 4; cc++) {
            const float* krow = &sq[(c0 + cc) * QS + 192 + h * 48];
            float d = 0.f;
#pragma unroll
            for (int k = 0; k < 48; k++) d += qrow[k] * krow[k];
            ss[(h * 16 + r) * 16 + c0 + cc] = d * 0.14433756729740643f;
        }
    }
    __syncthreads();

    if (tid < 64) {  // softmax per row
        float* row = &ss[tid * 16];
        float mx = row[0];
#pragma unroll
        for (int j = 1; j < 16; j++) mx = fmaxf(mx, row[j]);
        float sm = 0.f;
#pragma unroll
        for (int j = 0; j < 16; j++) { float e = __expf(row[j] - mx); row[j] = e; sm += e; }
        float r = 1.f / sm;
#pragma unroll
        for (int j = 0; j < 16; j++) row[j] *= r;
    }
    __syncthreads();

    for (int i = tid; i < 16 * 192; i += 256) {
        int r = i / 192, c = i - r * 192;
        int h = c / 48, d = c - h * 48;
        const float* srow = &ss[(h * 16 + r) * 16];
        const float* vcol = &sq[384 + h * 48 + d];
        float o = 0.f;
#pragma unroll
        for (int j = 0; j < 16; j++) o += srow[j] * vcol[j * QS];
        g_attn[(size_t)smm[r] * 192 + c] = o;
    }
}

// =====================================================================
// GroupNorm #1 (token-major amap)
// =====================================================================
__global__ __launch_bounds__(192)
void k_gn1_stats()
{
    int b = blockIdx.x >> 6;
    int chunk = blockIdx.x & 63;
    int c = threadIdx.x;
    size_t base = ((size_t)(b * 16384 + chunk * 256)) * 192 + c;
    float s = 0.f, q = 0.f;
    for (int r = 0; r < 256; r++) {
        float v = g_amap[base + (size_t)r * 192];
        s += v; q += v * v;
    }
    g_p1s[(b * 192 + c) * 64 + chunk] = s;
    g_p1q[(b * 192 + c) * 64 + chunk] = q;
}

__global__ void k_gn1_final()
{
    int t = threadIdx.x;
    if (t >= 64) return;
    int b = t >> 3, g = t & 7;
    float S = 0.f, Q = 0.f;
    for (int i = 0; i < 24; i++) {
        int cc = b * 192 + g * 24 + i;
        for (int ch = 0; ch < 64; ch++) { S += g_p1s[cc * 64 + ch]; Q += g_p1q[cc * 64 + ch]; }
    }
    const float inv_n = 1.0f / 393216.0f;
    float mu = S * inv_n;
    float var = Q * inv_n - mu * mu;
    g_mu1[t] = mu;
    g_inv1[t] = rsqrtf(var + 1e-5f);
}

__global__ __launch_bounds__(256)
void k_norm1(const float* __restrict__ gg, const float* __restrict__ gb)
{
    size_t idx4 = (size_t)blockIdx.x * 256 + threadIdx.x;
    size_t base = idx4 * 4;
    int c = (int)(base % 192);
    int b = (int)(base / 3145728);
    int grp = c / 24;
    float mu = g_mu1[b * 8 + grp], inv = g_inv1[b * 8 + grp];
    float4 v = *reinterpret_cast<const float4*>(&g_amap[base]);
    float4 o;
    o.x = (v.x - mu) * inv * gg[c + 0] + gb[c + 0];
    o.y = (v.y - mu) * inv * gg[c + 1] + gb[c + 1];
    o.z = (v.z - mu) * inv * gg[c + 2] + gb[c + 2];
    o.w = (v.w - mu) * inv * gg[c + 3] + gb[c + 3];
    *reinterpret_cast<float4*>(&g_proj[base]) = o;
}

// =====================================================================
// LSTM pointwise
// =====================================================================
__global__ __launch_bounds__(256)
void k_lstm(const float* __restrict__ Cin, float* __restrict__ out)
{
    __shared__ float gs[16 * 768];
    int tok0 = blockIdx.x * 16;
    int b = tok0 >> 14;
    int p0 = tok0 & 16383;
    int tid = threadIdx.x;
    for (int i = tid; i < 16 * 768; i += 256) gs[i] = g_gates[(size_t)tok0 * 768 + i];
    __syncthreads();
#pragma unroll
    for (int it = 0; it < 12; it++) {
        int idx = tid + 256 * it;
        int pl = idx / 192, n = idx - pl * 192;
        float gi = gs[pl * 768 + n];
        float gf = gs[pl * 768 + n + 192];
        float go = gs[pl * 768 + n + 384];
        float gG = gs[pl * 768 + n + 576];
        float i_ = 1.f / (1.f + __expf(-gi));
        float f_ = 1.f / (1.f + __expf(-gf));
        float o_ = 1.f / (1.f + __expf(-go));
        float g_ = tanhf(gG);
        size_t addr = ((size_t)(b * 192 + n) << 14) + p0 + pl;
        float cp = Cin[addr];
        float cn = f_ * cp + i_ * g_;
        out[(size_t)HSZ + addr] = cn;
        g_hraw[addr] = o_ * tanhf(cn);
    }
}

// =====================================================================
// GroupNorm #2 over BCHW hraw
// =====================================================================
__global__ __launch_bounds__(256)
void k_gn2_stats()
{
    __shared__ float rs[256], rq[256];
    int grp = blockIdx.x >> 4;
    int part = blockIdx.x & 15;
    int b = grp >> 3, g = grp & 7;
    size_t base = ((size_t)(b * 192 + g * 24) << 14) + (size_t)part * 24576;
    int tid = threadIdx.x;
    float s = 0.f, q = 0.f;
    for (int j = 0; j < 96; j++) {
        float v = g_hraw[base + tid + 256 * j];
        s += v; q += v * v;
    }
    rs[tid] = s; rq[tid] = q;
    __syncthreads();
    for (int o = 128; o; o >>= 1) {
        if (tid < o) { rs[tid] += rs[tid + o]; rq[tid] += rq[tid + o]; }
        __syncthreads();
    }
    if (tid == 0) { g_p2s[grp * 16 + part] = rs[0]; g_p2q[grp * 16 + part] = rq[0]; }
}

__global__ void k_gn2_final()
{
    int t = threadIdx.x;
    if (t >= 64) return;
    float S = 0.f, Q = 0.f;
    for (int i = 0; i < 16; i++) { S += g_p2s[t * 16 + i]; Q += g_p2q[t * 16 + i]; }
    const float inv_n = 1.0f / 393216.0f;
    float mu = S * inv_n;
    float var = Q * inv_n - mu * mu;
    g_mu2[t] = mu;
    g_inv2[t] = rsqrtf(var + 1e-5f);
}

__global__ __launch_bounds__(256)
void k_finalize(const float* __restrict__ gg, const float* __restrict__ gb,
                float* __restrict__ out)
{
    size_t idx4 = (size_t)blockIdx.x * 256 + threadIdx.x;
    size_t base = idx4 * 4;
    int bc = (int)(base >> 14);
    int b = bc / 192;
    int c = bc - b * 192;
    int grp = c / 24;
    float mu = g_mu2[b * 8 + grp], inv = g_inv2[b * 8 + grp];
    float sc = gg[c] * inv;
    float bi = gb[c];
    float4 v = *reinterpret_cast<const float4*>(&g_hraw[base]);
    float4 o;
    o.x = (v.x - mu) * sc + bi;
    o.y = (v.y - mu) * sc + bi;
    o.z = (v.z - mu) * sc + bi;
    o.w = (v.w - mu) * sc + bi;
    *reinterpret_cast<float4*>(&out[base]) = o;
}

// =====================================================================
// host launcher
// =====================================================================
extern "C" void kernel_launch(void* const* d_in, const int* in_sizes, int n_in,
                              void* d_out, int out_size)
{
    const float* x       = (const float*)d_in[0];
    const float* h       = (const float*)d_in[1];
    const float* c       = (const float*)d_in[2];
    const float* w_in    = (const float*)d_in[3];
    const float* b_in    = (const float*)d_in[4];
    const float* ln_g    = (const float*)d_in[5];
    const float* ln_b    = (const float*)d_in[6];
    const float* w_qkv   = (const float*)d_in[7];
    const float* b_qkv   = (const float*)d_in[8];
    const float* w_proj  = (const float*)d_in[9];
    const float* b_proj  = (const float*)d_in[10];
    const float* gn_g    = (const float*)d_in[11];
    const float* gn_b    = (const float*)d_in[12];
    const float* w_gates = (const float*)d_in[13];
    const float* b_gates = (const float*)d_in[14];
    float* out = (float*)d_out;

    void *p_comb, *p_proj, *p_xn, *p_qkv, *p_attn, *p_amap, *p_gates;
    cudaGetSymbolAddress(&p_comb,  g_comb);
    cudaGetSymbolAddress(&p_proj,  g_proj);
    cudaGetSymbolAddress(&p_xn,    g_xn);
    cudaGetSymbolAddress(&p_qkv,   g_qkv);
    cudaGetSymbolAddress(&p_attn,  g_attn);
    cudaGetSymbolAddress(&p_amap,  g_amap);
    cudaGetSymbolAddress(&p_gates, g_gates);

    // 1) pack concat(x,h) -> g_comb [M,256]
    k_pack<<<dim3(2048, 4), 256>>>(x, h);
    // 2) in_proj GEMM (K=256, N=192) -> g_proj
    k_tc<256><<<dim3(3, 1024), 256>>>((const float*)p_comb, w_in, b_in,
                                      (float*)p_proj, 192);
    // 3) LayerNorm -> g_xn
    k_ln<<<16384, 256>>>(ln_g, ln_b);
    // 4) qkv GEMM (K=192, N=576) -> g_qkv
    k_tc<192><<<dim3(9, 1024), 256>>>((const float*)p_xn, w_qkv, b_qkv,
                                      (float*)p_qkv, 576);
    // 5) window attention -> g_attn
    k_attn<<<8192, 256>>>();
    // 6) out_proj GEMM (K=192, N=192) -> g_amap
    k_tc<192><<<dim3(3, 1024), 256>>>((const float*)p_attn, w_proj, b_proj,
                                      (float*)p_amap, 192);
    // 7) GroupNorm(amap) -> g_proj (reused as anorm)
    k_gn1_stats<<<512, 192>>>();
    k_gn1_final<<<1, 64>>>();
    k_norm1<<<24576, 256>>>(gn_g, gn_b);
    // 8) gates GEMM (K=192, N=768) -> g_gates
    k_tc<192><<<dim3(12, 1024), 256>>>((const float*)p_proj, w_gates, b_gates,
                                       (float*)p_gates, 768);
    // 9) LSTM pointwise -> cnext (d_out second half) + hraw
    k_lstm<<<8192, 256>>>(c, out);
    // 10) GroupNorm(hnext) -> d_out first half
    k_gn2_stats<<<1024, 256>>>();
    k_gn2_final<<<1, 64>>>();
    k_finalize<<<24576, 256>>>(gn_g, gn_b, out);
}

// round 5
// speedup vs baseline: 1.9219x; 1.1031x over previous
#include <cuda_runtime.h>
#include <cstdint>

// ---------------- problem constants ----------------
#define TOK    131072              // B*H*W tokens (raster order)
#define HSZ    25165824            // 8*192*128*128 (one output tensor)

// ---------------- static device scratch ----------------
__device__ float g_proj[(size_t)TOK * 192];   // in_proj out; later reused as normalized amap
__device__ float g_xn  [(size_t)TOK * 192];   // layernorm out
__device__ float g_qkv [(size_t)TOK * 576];
__device__ float g_attn[(size_t)TOK * 192];
__device__ float g_amap[(size_t)TOK * 192];
__device__ float g_gates[(size_t)TOK * 768];
__device__ float g_hraw[(size_t)TOK * 192];   // BCHW layout
__device__ float g_p1s[8 * 192 * 64];
__device__ float g_p1q[8 * 192 * 64];
__device__ float g_mu1[64], g_inv1[64];
__device__ float g_p2s[64 * 16], g_p2q[64 * 16];
__device__ float g_mu2[64], g_inv2[64];

// ---------------- PTX helpers ----------------
#define CP_ASYNC16(sm, gp) \
    asm volatile("cp.async.cg.shared.global [%0], [%1], 16;" :: "r"((uint32_t)(sm)), "l"(gp))
#define CP_COMMIT() asm volatile("cp.async.commit_group;" ::: "memory")
#define CP_WAIT(n)  asm volatile("cp.async.wait_group %0;" :: "n"(n) : "memory")

__device__ __forceinline__ uint32_t smem_to_u32(const void* p) {
    uint32_t a;
    asm("{ .reg .u64 t; cvta.to.shared.u64 t, %1; cvt.u32.u64 %0, t; }" : "=r"(a) : "l"(p));
    return a;
}
__device__ __forceinline__ void mma_tf32(float& c0, float& c1, float& c2, float& c3,
                                         uint32_t a0, uint32_t a1, uint32_t a2, uint32_t a3,
                                         uint32_t b0, uint32_t b1) {
    asm volatile("mma.sync.aligned.m16n8k8.row.col.f32.tf32.tf32.f32 "
                 "{%0,%1,%2,%3}, {%4,%5,%6,%7}, {%8,%9}, {%0,%1,%2,%3};"
                 : "+f"(c0), "+f"(c1), "+f"(c2), "+f"(c3)
                 : "r"(a0), "r"(a1), "r"(a2), "r"(a3), "r"(b0), "r"(b1));
}

// =====================================================================
// Tensor-core tf32 GEMM: C[M, Ntot] = A[M, K] * W[Ntot, K]^T + bias
// CTA tile 256x64, warp tile 64x32 (8 warps: 4m x 2n), kc=32,
// double-buffered cp.async, dynamic smem. grid = (Ntot/64, M/256).
// Raw fp32 bits fed to tf32 MMA (HW truncates mantissa).
// =====================================================================
template<int K>
__global__ __launch_bounds__(256, 2)
void k_tc2(const float* __restrict__ A, const float* __restrict__ W,
           const float* __restrict__ bias, float* __restrict__ C, int Ntot)
{
    constexpr int NCH = K / 32;
    constexpr int AST = 36;                  // padded row stride (floats)
    extern __shared__ float smf[];
    float* Asb[2] = { smf, smf + 256 * AST };
    float* Bsb[2] = { smf + 2 * 256 * AST, smf + 2 * 256 * AST + 64 * AST };

    const int tid  = threadIdx.x;
    const int lane = tid & 31;
    const int warp = tid >> 5;
    const int wm = warp & 3, wn = warp >> 2;
    const int m0 = blockIdx.y * 256;
    const int n0 = blockIdx.x * 64;

    const uint32_t sA[2] = { smem_to_u32(Asb[0]), smem_to_u32(Asb[1]) };
    const uint32_t sB[2] = { smem_to_u32(Bsb[0]), smem_to_u32(Bsb[1]) };

    float acc[4][4][4];
#pragma unroll
    for (int i = 0; i < 4; i++)
#pragma unroll
        for (int j = 0; j < 4; j++)
#pragma unroll
            for (int q = 0; q < 4; q++) acc[i][j][q] = 0.f;

    auto prefetch = [&](int kt) {
        int buf = kt & 1;
        const float* ag = A + (size_t)m0 * K + kt * 32;
        const float* bg = W + (size_t)n0 * K + kt * 32;
#pragma unroll
        for (int j = 0; j < 8; j++) {
            int idx = tid + 256 * j;
            int row = idx >> 3, off = idx & 7;
            CP_ASYNC16(sA[buf] + (uint32_t)(row * AST + off * 4) * 4,
                       ag + (size_t)row * K + off * 4);
        }
#pragma unroll
        for (int j = 0; j < 2; j++) {
            int idx = tid + 256 * j;
            int row = idx >> 3, off = idx & 7;
            CP_ASYNC16(sB[buf] + (uint32_t)(row * AST + off * 4) * 4,
                       bg + (size_t)row * K + off * 4);
        }
        CP_COMMIT();
    };

    prefetch(0);

    for (int kt = 0; kt < NCH; kt++) {
        if (kt + 1 < NCH) { prefetch(kt + 1); CP_WAIT(1); }
        else              { CP_WAIT(0); }
        __syncthreads();
        const float* as = Asb[kt & 1];
        const float* bs = Bsb[kt & 1];
#pragma unroll
        for (int ks = 0; ks < 4; ks++) {
            const int kk = ks * 8;
            const int cc = kk + (lane & 3);
            uint32_t af[4][4];
#pragma unroll
            for (int mf = 0; mf < 4; mf++) {
                int r = wm * 64 + mf * 16 + (lane >> 2);
                af[mf][0] = __float_as_uint(as[r * AST + cc]);
                af[mf][1] = __float_as_uint(as[(r + 8) * AST + cc]);
                af[mf][2] = __float_as_uint(as[r * AST + cc + 4]);
                af[mf][3] = __float_as_uint(as[(r + 8) * AST + cc + 4]);
            }
            uint32_t bf[4][2];
#pragma unroll
            for (int nf = 0; nf < 4; nf++) {
                int rb = wn * 32 + nf * 8 + (lane >> 2);
                bf[nf][0] = __float_as_uint(bs[rb * AST + cc]);
                bf[nf][1] = __float_as_uint(bs[rb * AST + cc + 4]);
            }
#pragma unroll
            for (int mf = 0; mf < 4; mf++)
#pragma unroll
                for (int nf = 0; nf < 4; nf++)
                    mma_tf32(acc[mf][nf][0], acc[mf][nf][1], acc[mf][nf][2], acc[mf][nf][3],
                             af[mf][0], af[mf][1], af[mf][2], af[mf][3],
                             bf[nf][0], bf[nf][1]);
        }
        __syncthreads();
    }

#pragma unroll
    for (int mf = 0; mf < 4; mf++) {
        int row = m0 + wm * 64 + mf * 16 + (lane >> 2);
#pragma unroll
        for (int nf = 0; nf < 4; nf++) {
            int col = n0 + wn * 32 + nf * 8 + 2 * (lane & 3);
            float bx = bias[col], by = bias[col + 1];
            float2 o0 = make_float2(acc[mf][nf][0] + bx, acc[mf][nf][1] + by);
            float2 o1 = make_float2(acc[mf][nf][2] + bx, acc[mf][nf][3] + by);
            *reinterpret_cast<float2*>(&C[(size_t)row * Ntot + col]) = o0;
            *reinterpret_cast<float2*>(&C[(size_t)(row + 8) * Ntot + col]) = o1;
        }
    }
}

// =====================================================================
// in_proj GEMM with fused BCHW gather: A[m][k] = (k<64 ? x : h)
// A stored k-major (transposed) in smem; K=256, Ntot=192.
// =====================================================================
__global__ __launch_bounds__(256, 2)
void k_tc_in(const float* __restrict__ X, const float* __restrict__ Hh,
             const float* __restrict__ W, const float* __restrict__ bias,
             float* __restrict__ C)
{
    constexpr int K = 256, NCH = 8;
    constexpr int MST = 264;                 // A (transposed) row stride
    constexpr int AST = 36;                  // B row stride
    extern __shared__ float smf[];
    float* Asb[2] = { smf, smf + 32 * MST };
    float* Bsb[2] = { smf + 2 * 32 * MST, smf + 2 * 32 * MST + 64 * AST };

    const int tid  = threadIdx.x;
    const int lane = tid & 31;
    const int warp = tid >> 5;
    const int wm = warp & 3, wn = warp >> 2;
    const int m0 = blockIdx.y * 256;
    const int n0 = blockIdx.x * 64;
    const int b  = m0 >> 14;
    const int p0 = m0 & 16383;

    const uint32_t sA[2] = { smem_to_u32(Asb[0]), smem_to_u32(Asb[1]) };
    const uint32_t sB[2] = { smem_to_u32(Bsb[0]), smem_to_u32(Bsb[1]) };

    float acc[4][4][4];
#pragma unroll
    for (int i = 0; i < 4; i++)
#pragma unroll
        for (int j = 0; j < 4; j++)
#pragma unroll
            for (int q = 0; q < 4; q++) acc[i][j][q] = 0.f;

    auto prefetch = [&](int kt) {
        int buf = kt & 1;
#pragma unroll
        for (int j = 0; j < 8; j++) {
            int idx = tid + 256 * j;
            int k = idx >> 6, ms = idx & 63;
            int kg = kt * 32 + k;
            const float* src = (kg < 64)
                ? X  + (((size_t)(b * 64  + kg))        << 14) + p0 + ms * 4
                : Hh + (((size_t)(b * 192 + (kg - 64))) << 14) + p0 + ms * 4;
            CP_ASYNC16(sA[buf] + (uint32_t)(k * MST + ms * 4) * 4, src);
        }
        const float* bg = W + (size_t)n0 * K + kt * 32;
#pragma unroll
        for (int j = 0; j < 2; j++) {
            int idx = tid + 256 * j;
            int row = idx >> 3, off = idx & 7;
            CP_ASYNC16(sB[buf] + (uint32_t)(row * AST + off * 4) * 4,
                       bg + (size_t)row * K + off * 4);
        }
        CP_COMMIT();
    };

    prefetch(0);

    for (int kt = 0; kt < NCH; kt++) {
        if (kt + 1 < NCH) { prefetch(kt + 1); CP_WAIT(1); }
        else              { CP_WAIT(0); }
        __syncthreads();
        const float* as = Asb[kt & 1];
        const float* bs = Bsb[kt & 1];
#pragma unroll
        for (int ks = 0; ks < 4; ks++) {
            const int kk = ks * 8;
            const int cc = kk + (lane & 3);
            uint32_t af[4][4];
#pragma unroll
            for (int mf = 0; mf < 4; mf++) {
                int r = wm * 64 + mf * 16 + (lane >> 2);
                af[mf][0] = __float_as_uint(as[cc * MST + r]);
                af[mf][1] = __float_as_uint(as[cc * MST + r + 8]);
                af[mf][2] = __float_as_uint(as[(cc + 4) * MST + r]);
                af[mf][3] = __float_as_uint(as[(cc + 4) * MST + r + 8]);
            }
            uint32_t bf[4][2];
#pragma unroll
            for (int nf = 0; nf < 4; nf++) {
                int rb = wn * 32 + nf * 8 + (lane >> 2);
                bf[nf][0] = __float_as_uint(bs[rb * AST + cc]);
                bf[nf][1] = __float_as_uint(bs[rb * AST + cc + 4]);
            }
#pragma unroll
            for (int mf = 0; mf < 4; mf++)
#pragma unroll
                for (int nf = 0; nf < 4; nf++)
                    mma_tf32(acc[mf][nf][0], acc[mf][nf][1], acc[mf][nf][2], acc[mf][nf][3],
                             af[mf][0], af[mf][1], af[mf][2], af[mf][3],
                             bf[nf][0], bf[nf][1]);
        }
        __syncthreads();
    }

#pragma unroll
    for (int mf = 0; mf < 4; mf++) {
        int row = m0 + wm * 64 + mf * 16 + (lane >> 2);
#pragma unroll
        for (int nf = 0; nf < 4; nf++) {
            int col = n0 + wn * 32 + nf * 8 + 2 * (lane & 3);
            float bx = bias[col], by = bias[col + 1];
            float2 o0 = make_float2(acc[mf][nf][0] + bx, acc[mf][nf][1] + by);
            float2 o1 = make_float2(acc[mf][nf][2] + bx, acc[mf][nf][3] + by);
            *reinterpret_cast<float2*>(&C[(size_t)row * 192 + col]) = o0;
            *reinterpret_cast<float2*>(&C[(size_t)(row + 8) * 192 + col]) = o1;
        }
    }
}

// =====================================================================
// LayerNorm over 192 channels, one warp per token
// =====================================================================
__global__ __launch_bounds__(256)
void k_ln(const float* __restrict__ lng, const float* __restrict__ lnb)
{
    int warp = (blockIdx.x * blockDim.x + threadIdx.x) >> 5;
    int lane = threadIdx.x & 31;
    const float* row = &g_proj[(size_t)warp * 192];
    float v[6];
    float s = 0.f;
#pragma unroll
    for (int j = 0; j < 6; j++) { v[j] = row[lane + 32 * j]; s += v[j]; }
#pragma unroll
    for (int o = 16; o; o >>= 1) s += __shfl_xor_sync(0xffffffffu, s, o);
    float mean = s * (1.0f / 192.0f);
    float q = 0.f;
#pragma unroll
    for (int j = 0; j < 6; j++) { float d = v[j] - mean; q += d * d; }
#pragma unroll
    for (int o = 16; o; o >>= 1) q += __shfl_xor_sync(0xffffffffu, q, o);
    float inv = rsqrtf(q * (1.0f / 192.0f) + 1e-5f);
    float* dst = &g_xn[(size_t)warp * 192];
#pragma unroll
    for (int j = 0; j < 6; j++) {
        int c = lane + 32 * j;
        dst[c] = (v[j] - mean) * inv * lng[c] + lnb[c];
    }
}

// =====================================================================
// Window attention — float4 vectorized, padded smem stride 580
// =====================================================================
#define QS 580
__global__ __launch_bounds__(256)
void k_attn()
{
    __shared__ float sq[16 * QS];
    __shared__ float ss[4 * 16 * 16];
    __shared__ int smm[16];

    int w = blockIdx.x;
    int tid = threadIdx.x;
    if (tid < 16) {
        int b = w >> 10, wi = w & 1023, wy = wi >> 5, wx = wi & 31;
        int ty = tid >> 2, tx = tid & 3;
        smm[tid] = (b << 14) + ((wy * 4 + ty) << 7) + (wx * 4 + tx);
    }
    __syncthreads();

    // load 16 x 576 floats as float4 (9 per thread)
#pragma unroll
    for (int j = 0; j < 9; j++) {
        int i = tid + 256 * j;
        int t = i / 144, c4 = i - t * 144;
        float4 v = *reinterpret_cast<const float4*>(&g_qkv[(size_t)smm[t] * 576 + c4 * 4]);
        *reinterpret_cast<float4*>(&sq[t * QS + c4 * 4]) = v;
    }
    __syncthreads();

    {   // scores: 4 heads x 16x16
        int h = tid >> 6, r = (tid >> 2) & 15, c0 = (tid & 3) * 4;
        const float4* qrow = reinterpret_cast<const float4*>(&sq[r * QS + h * 48]);
#pragma unroll
        for (int cc = 0; cc < 4; cc++) {
            const float4* krow = reinterpret_cast<const float4*>(&sq[(c0 + cc) * QS + 192 + h * 48]);
            float d = 0.f;
#pragma unroll
            for (int k = 0; k < 12; k++) {
                float4 qv = qrow[k], kv = krow[k];
                d += qv.x * kv.x + qv.y * kv.y + qv.z * kv.z + qv.w * kv.w;
            }
            ss[(h * 16 + r) * 16 + c0 + cc] = d * 0.14433756729740643f;
        }
    }
    __syncthreads();

    if (tid < 64) {  // softmax per row
        float* row = &ss[tid * 16];
        float mx = row[0];
#pragma unroll
        for (int j = 1; j < 16; j++) mx = fmaxf(mx, row[j]);
        float sm = 0.f;
#pragma unroll
        for (int j = 0; j < 16; j++) { float e = __expf(row[j] - mx); row[j] = e; sm += e; }
        float r = 1.f / sm;
#pragma unroll
        for (int j = 0; j < 16; j++) row[j] *= r;
    }
    __syncthreads();

    // output: 16 x 192 floats as float4 (3 per thread)
#pragma unroll
    for (int j = 0; j < 3; j++) {
        int i = tid + 256 * j;
        int r = i / 48, c4 = i - r * 48;
        int h = c4 / 12;
        const float* srow = &ss[(h * 16 + r) * 16];
        const float* vbase = &sq[384 + c4 * 4];     // h*48 + d0 == c4*4
        float4 o = make_float4(0.f, 0.f, 0.f, 0.f);
#pragma unroll
        for (int jj = 0; jj < 16; jj++) {
            float4 vv = *reinterpret_cast<const float4*>(&vbase[jj * QS]);
            float sv = srow[jj];
            o.x += sv * vv.x; o.y += sv * vv.y; o.z += sv * vv.z; o.w += sv * vv.w;
        }
        *reinterpret_cast<float4*>(&g_attn[(size_t)smm[r] * 192 + c4 * 4]) = o;
    }
}

// =====================================================================
// GroupNorm #1 (token-major amap)
// =====================================================================
__global__ __launch_bounds__(192)
void k_gn1_stats()
{
    int b = blockIdx.x >> 6;
    int chunk = blockIdx.x & 63;
    int c = threadIdx.x;
    size_t base = ((size_t)(b * 16384 + chunk * 256)) * 192 + c;
    float s = 0.f, q = 0.f;
    for (int r = 0; r < 256; r++) {
        float v = g_amap[base + (size_t)r * 192];
        s += v; q += v * v;
    }
    g_p1s[(b * 192 + c) * 64 + chunk] = s;
    g_p1q[(b * 192 + c) * 64 + chunk] = q;
}

__global__ void k_gn1_final()
{
    int t = threadIdx.x;
    if (t >= 64) return;
    int b = t >> 3, g = t & 7;
    float S = 0.f, Q = 0.f;
    for (int i = 0; i < 24; i++) {
        int cc = b * 192 + g * 24 + i;
        for (int ch = 0; ch < 64; ch++) { S += g_p1s[cc * 64 + ch]; Q += g_p1q[cc * 64 + ch]; }
    }
    const float inv_n = 1.0f / 393216.0f;
    float mu = S * inv_n;
    float var = Q * inv_n - mu * mu;
    g_mu1[t] = mu;
    g_inv1[t] = rsqrtf(var + 1e-5f);
}

__global__ __launch_bounds__(256)
void k_norm1(const float* __restrict__ gg, const float* __restrict__ gb)
{
    size_t idx4 = (size_t)blockIdx.x * 256 + threadIdx.x;
    size_t base = idx4 * 4;
    int c = (int)(base % 192);
    int b = (int)(base / 3145728);
    int grp = c / 24;
    float mu = g_mu1[b * 8 + grp], inv = g_inv1[b * 8 + grp];
    float4 v = *reinterpret_cast<const float4*>(&g_amap[base]);
    float4 o;
    o.x = (v.x - mu) * inv * gg[c + 0] + gb[c + 0];
    o.y = (v.y - mu) * inv * gg[c + 1] + gb[c + 1];
    o.z = (v.z - mu) * inv * gg[c + 2] + gb[c + 2];
    o.w = (v.w - mu) * inv * gg[c + 3] + gb[c + 3];
    *reinterpret_cast<float4*>(&g_proj[base]) = o;
}

// =====================================================================
// LSTM pointwise
// =====================================================================
__global__ __launch_bounds__(256)
void k_lstm(const float* __restrict__ Cin, float* __restrict__ out)
{
    __shared__ float gs[16 * 768];
    int tok0 = blockIdx.x * 16;
    int b = tok0 >> 14;
    int p0 = tok0 & 16383;
    int tid = threadIdx.x;
    for (int i = tid; i < 16 * 768 / 4; i += 256) {
        *reinterpret_cast<float4*>(&gs[i * 4]) =
            *reinterpret_cast<const float4*>(&g_gates[(size_t)tok0 * 768 + i * 4]);
    }
    __syncthreads();
#pragma unroll
    for (int it = 0; it < 12; it++) {
        int idx = tid + 256 * it;
        int pl = idx / 192, n = idx - pl * 192;
        float gi = gs[pl * 768 + n];
        float gf = gs[pl * 768 + n + 192];
        float go = gs[pl * 768 + n + 384];
        float gG = gs[pl * 768 + n + 576];
        float i_ = 1.f / (1.f + __expf(-gi));
        float f_ = 1.f / (1.f + __expf(-gf));
        float o_ = 1.f / (1.f + __expf(-go));
        float g_ = tanhf(gG);
        size_t addr = ((size_t)(b * 192 + n) << 14) + p0 + pl;
        float cp = Cin[addr];
        float cn = f_ * cp + i_ * g_;
        out[(size_t)HSZ + addr] = cn;
        g_hraw[addr] = o_ * tanhf(cn);
    }
}

// =====================================================================
// GroupNorm #2 over BCHW hraw
// =====================================================================
__global__ __launch_bounds__(256)
void k_gn2_stats()
{
    __shared__ float rs[256], rq[256];
    int grp = blockIdx.x >> 4;
    int part = blockIdx.x & 15;
    int b = grp >> 3, g = grp & 7;
    size_t base = ((size_t)(b * 192 + g * 24) << 14) + (size_t)part * 24576;
    int tid = threadIdx.x;
    float s = 0.f, q = 0.f;
    for (int j = 0; j < 24; j++) {
        float4 v = *reinterpret_cast<const float4*>(&g_hraw[base + (size_t)(tid + 256 * j) * 4]);
        s += v.x + v.y + v.z + v.w;
        q += v.x * v.x + v.y * v.y + v.z * v.z + v.w * v.w;
    }
    rs[tid] = s; rq[tid] = q;
    __syncthreads();
    for (int o = 128; o; o >>= 1) {
        if (tid < o) { rs[tid] += rs[tid + o]; rq[tid] += rq[tid + o]; }
        __syncthreads();
    }
    if (tid == 0) { g_p2s[grp * 16 + part] = rs[0]; g_p2q[grp * 16 + part] = rq[0]; }
}

__global__ void k_gn2_final()
{
    int t = threadIdx.x;
    if (t >= 64) return;
    float S = 0.f, Q = 0.f;
    for (int i = 0; i < 16; i++) { S += g_p2s[t * 16 + i]; Q += g_p2q[t * 16 + i]; }
    const float inv_n = 1.0f / 393216.0f;
    float mu = S * inv_n;
    float var = Q * inv_n - mu * mu;
    g_mu2[t] = mu;
    g_inv2[t] = rsqrtf(var + 1e-5f);
}

__global__ __launch_bounds__(256)
void k_finalize(const float* __restrict__ gg, const float* __restrict__ gb,
                float* __restrict__ out)
{
    size_t idx4 = (size_t)blockIdx.x * 256 + threadIdx.x;
    size_t base = idx4 * 4;
    int bc = (int)(base >> 14);
    int b = bc / 192;
    int c = bc - b * 192;
    int grp = c / 24;
    float mu = g_mu2[b * 8 + grp], inv = g_inv2[b * 8 + grp];
    float sc = gg[c] * inv;
    float bi = gb[c];
    float4 v = *reinterpret_cast<const float4*>(&g_hraw[base]);
    float4 o;
    o.x = (v.x - mu) * sc + bi;
    o.y = (v.y - mu) * sc + bi;
    o.z = (v.z - mu) * sc + bi;
    o.w = (v.w - mu) * sc + bi;
    *reinterpret_cast<float4*>(&out[base]) = o;
}

// =====================================================================
// host launcher
// =====================================================================
extern "C" void kernel_launch(void* const* d_in, const int* in_sizes, int n_in,
                              void* d_out, int out_size)
{
    const float* x       = (const float*)d_in[0];
    const float* h       = (const float*)d_in[1];
    const float* c       = (const float*)d_in[2];
    const float* w_in    = (const float*)d_in[3];
    const float* b_in    = (const float*)d_in[4];
    const float* ln_g    = (const float*)d_in[5];
    const float* ln_b    = (const float*)d_in[6];
    const float* w_qkv   = (const float*)d_in[7];
    const float* b_qkv   = (const float*)d_in[8];
    const float* w_proj  = (const float*)d_in[9];
    const float* b_proj  = (const float*)d_in[10];
    const float* gn_g    = (const float*)d_in[11];
    const float* gn_b    = (const float*)d_in[12];
    const float* w_gates = (const float*)d_in[13];
    const float* b_gates = (const float*)d_in[14];
    float* out = (float*)d_out;

    void *p_proj, *p_xn, *p_qkv, *p_attn, *p_amap, *p_gates;
    cudaGetSymbolAddress(&p_proj,  g_proj);
    cudaGetSymbolAddress(&p_xn,    g_xn);
    cudaGetSymbolAddress(&p_qkv,   g_qkv);
    cudaGetSymbolAddress(&p_attn,  g_attn);
    cudaGetSymbolAddress(&p_amap,  g_amap);
    cudaGetSymbolAddress(&p_gates, g_gates);

    const int SM_TC  = (2 * 256 + 2 * 64) * 36 * 4;            // 92160
    const int SM_IN  = (2 * 32 * 264 + 2 * 64 * 36) * 4;       // 86016
    cudaFuncSetAttribute(k_tc2<192>, cudaFuncAttributeMaxDynamicSharedMemorySize, SM_TC);
    cudaFuncSetAttribute(k_tc_in,    cudaFuncAttributeMaxDynamicSharedMemorySize, SM_IN);

    // 1) in_proj GEMM with fused BCHW gather (K=256, N=192) -> g_proj
    k_tc_in<<<dim3(3, 512), 256, SM_IN>>>(x, h, w_in, b_in, (float*)p_proj);
    // 2) LayerNorm -> g_xn
    k_ln<<<16384, 256>>>(ln_g, ln_b);
    // 3) qkv GEMM (K=192, N=576) -> g_qkv
    k_tc2<192><<<dim3(9, 512), 256, SM_TC>>>((const float*)p_xn, w_qkv, b_qkv,
                                             (float*)p_qkv, 576);
    // 4) window attention -> g_attn
    k_attn<<<8192, 256>>>();
    // 5) out_proj GEMM (K=192, N=192) -> g_amap
    k_tc2<192><<<dim3(3, 512), 256, SM_TC>>>((const float*)p_attn, w_proj, b_proj,
                                             (float*)p_amap, 192);
    // 6) GroupNorm(amap) -> g_proj (reused as anorm)
    k_gn1_stats<<<512, 192>>>();
    k_gn1_final<<<1, 64>>>();
    k_norm1<<<24576, 256>>>(gn_g, gn_b);
    // 7) gates GEMM (K=192, N=768) -> g_gates
    k_tc2<192><<<dim3(12, 512), 256, SM_TC>>>((const float*)p_proj, w_gates, b_gates,
                                              (float*)p_gates, 768);
    // 8) LSTM pointwise -> cnext (d_out second half) + hraw
    k_lstm<<<8192, 256>>>(c, out);
    // 9) GroupNorm(hnext) -> d_out first half
    k_gn2_stats<<<1024, 256>>>();
    k_gn2_final<<<1, 64>>>();
    k_finalize<<<24576, 256>>>(gn_g, gn_b, out);
}

// round 6
// speedup vs baseline: 1.9673x; 1.0237x over previous
#include <cuda_runtime.h>
#include <cstdint>

// ---------------- problem constants ----------------
#define TOK    131072              // B*H*W tokens (raster order)
#define HSZ    25165824            // 8*192*128*128 (one output tensor)

// ---------------- static device scratch ----------------
__device__ float g_proj[(size_t)TOK * 192];   // in_proj out (raw, pre-LN)
__device__ float g_qkv [(size_t)TOK * 576];
__device__ float g_attn[(size_t)TOK * 192];
__device__ float g_amap[(size_t)TOK * 192];   // out_proj out (raw, pre-GN)
__device__ float g_gates[(size_t)TOK * 768];
__device__ float g_hraw[(size_t)TOK * 192];   // BCHW layout
__device__ float g_lnmu[TOK], g_lniv[TOK];
__device__ float g_p1s[8 * 192 * 64];
__device__ float g_p1q[8 * 192 * 64];
__device__ float g_mu1[64], g_inv1[64];
__device__ float g_p2s[64 * 16], g_p2q[64 * 16];
__device__ float g_mu2[64], g_inv2[64];

// ---------------- PTX helpers ----------------
#define CP_ASYNC16(sm, gp) \
    asm volatile("cp.async.cg.shared.global [%0], [%1], 16;" :: "r"((uint32_t)(sm)), "l"(gp))
#define CP_COMMIT() asm volatile("cp.async.commit_group;" ::: "memory")
#define CP_WAIT(n)  asm volatile("cp.async.wait_group %0;" :: "n"(n) : "memory")

__device__ __forceinline__ uint32_t smem_to_u32(const void* p) {
    uint32_t a;
    asm("{ .reg .u64 t; cvta.to.shared.u64 t, %1; cvt.u32.u64 %0, t; }" : "=r"(a) : "l"(p));
    return a;
}
__device__ __forceinline__ void mma_tf32(float& c0, float& c1, float& c2, float& c3,
                                         uint32_t a0, uint32_t a1, uint32_t a2, uint32_t a3,
                                         uint32_t b0, uint32_t b1) {
    asm volatile("mma.sync.aligned.m16n8k8.row.col.f32.tf32.tf32.f32 "
                 "{%0,%1,%2,%3}, {%4,%5,%6,%7}, {%8,%9}, {%0,%1,%2,%3};"
                 : "+f"(c0), "+f"(c1), "+f"(c2), "+f"(c3)
                 : "r"(a0), "r"(a1), "r"(a2), "r"(a3), "r"(b0), "r"(b1));
}

// =====================================================================
// Plain tf32 GEMM: C = A[M,K] * W[N,K]^T + bias. CTA 256x64, 8 warps.
// =====================================================================
template<int K>
__global__ __launch_bounds__(256, 2)
void k_tc2(const float* __restrict__ A, const float* __restrict__ W,
           const float* __restrict__ bias, float* __restrict__ C, int Ntot)
{
    constexpr int NCH = K / 32;
    constexpr int AST = 36;
    extern __shared__ float smf[];
    float* Asb[2] = { smf, smf + 256 * AST };
    float* Bsb[2] = { smf + 2 * 256 * AST, smf + 2 * 256 * AST + 64 * AST };

    const int tid  = threadIdx.x;
    const int lane = tid & 31;
    const int warp = tid >> 5;
    const int wm = warp & 3, wn = warp >> 2;
    const int m0 = blockIdx.y * 256;
    const int n0 = blockIdx.x * 64;

    const uint32_t sA[2] = { smem_to_u32(Asb[0]), smem_to_u32(Asb[1]) };
    const uint32_t sB[2] = { smem_to_u32(Bsb[0]), smem_to_u32(Bsb[1]) };

    float acc[4][4][4];
#pragma unroll
    for (int i = 0; i < 4; i++)
#pragma unroll
        for (int j = 0; j < 4; j++)
#pragma unroll
            for (int q = 0; q < 4; q++) acc[i][j][q] = 0.f;

    auto prefetch = [&](int kt) {
        int buf = kt & 1;
        const float* ag = A + (size_t)m0 * K + kt * 32;
        const float* bg = W + (size_t)n0 * K + kt * 32;
#pragma unroll
        for (int j = 0; j < 8; j++) {
            int idx = tid + 256 * j;
            int row = idx >> 3, off = idx & 7;
            CP_ASYNC16(sA[buf] + (uint32_t)(row * AST + off * 4) * 4,
                       ag + (size_t)row * K + off * 4);
        }
#pragma unroll
        for (int j = 0; j < 2; j++) {
            int idx = tid + 256 * j;
            int row = idx >> 3, off = idx & 7;
            CP_ASYNC16(sB[buf] + (uint32_t)(row * AST + off * 4) * 4,
                       bg + (size_t)row * K + off * 4);
        }
        CP_COMMIT();
    };

    prefetch(0);

    for (int kt = 0; kt < NCH; kt++) {
        if (kt + 1 < NCH) { prefetch(kt + 1); CP_WAIT(1); }
        else              { CP_WAIT(0); }
        __syncthreads();
        const float* as = Asb[kt & 1];
        const float* bs = Bsb[kt & 1];
#pragma unroll
        for (int ks = 0; ks < 4; ks++) {
            const int kk = ks * 8;
            const int cc = kk + (lane & 3);
            uint32_t af[4][4];
#pragma unroll
            for (int mf = 0; mf < 4; mf++) {
                int r = wm * 64 + mf * 16 + (lane >> 2);
                af[mf][0] = __float_as_uint(as[r * AST + cc]);
                af[mf][1] = __float_as_uint(as[(r + 8) * AST + cc]);
                af[mf][2] = __float_as_uint(as[r * AST + cc + 4]);
                af[mf][3] = __float_as_uint(as[(r + 8) * AST + cc + 4]);
            }
            uint32_t bf[4][2];
#pragma unroll
            for (int nf = 0; nf < 4; nf++) {
                int rb = wn * 32 + nf * 8 + (lane >> 2);
                bf[nf][0] = __float_as_uint(bs[rb * AST + cc]);
                bf[nf][1] = __float_as_uint(bs[rb * AST + cc + 4]);
            }
#pragma unroll
            for (int mf = 0; mf < 4; mf++)
#pragma unroll
                for (int nf = 0; nf < 4; nf++)
                    mma_tf32(acc[mf][nf][0], acc[mf][nf][1], acc[mf][nf][2], acc[mf][nf][3],
                             af[mf][0], af[mf][1], af[mf][2], af[mf][3],
                             bf[nf][0], bf[nf][1]);
        }
        __syncthreads();
    }

#pragma unroll
    for (int mf = 0; mf < 4; mf++) {
        int row = m0 + wm * 64 + mf * 16 + (lane >> 2);
#pragma unroll
        for (int nf = 0; nf < 4; nf++) {
            int col = n0 + wn * 32 + nf * 8 + 2 * (lane & 3);
            float bx = bias[col], by = bias[col + 1];
            float2 o0 = make_float2(acc[mf][nf][0] + bx, acc[mf][nf][1] + by);
            float2 o1 = make_float2(acc[mf][nf][2] + bx, acc[mf][nf][3] + by);
            *reinterpret_cast<float2*>(&C[(size_t)row * Ntot + col]) = o0;
            *reinterpret_cast<float2*>(&C[(size_t)(row + 8) * Ntot + col]) = o1;
        }
    }
}

// =====================================================================
// Normalizing tf32 GEMM: same as k_tc2, but A is transformed in smem
// before the MMA: a = (v - mu)*iv*cg[k] + cb[k].
// MODE 0 (LayerNorm): mu/iv per row (token), arrays indexed by m.
// MODE 1 (GroupNorm): mu/iv per (batch, k/24), arrays of 64.
// =====================================================================
template<int K, int MODE>
__global__ __launch_bounds__(256, 2)
void k_tcn(const float* __restrict__ A, const float* __restrict__ W,
           const float* __restrict__ bias, float* __restrict__ C, int Ntot,
           const float* __restrict__ mu_arr, const float* __restrict__ iv_arr,
           const float* __restrict__ cg, const float* __restrict__ cb)
{
    constexpr int NCH = K / 32;
    constexpr int AST = 36;
    extern __shared__ float smf[];
    float* Asb[2] = { smf, smf + 256 * AST };
    float* Bsb[2] = { smf + 2 * 256 * AST, smf + 2 * 256 * AST + 64 * AST };

    const int tid  = threadIdx.x;
    const int lane = tid & 31;
    const int warp = tid >> 5;
    const int wm = warp & 3, wn = warp >> 2;
    const int m0 = blockIdx.y * 256;
    const int n0 = blockIdx.x * 64;
    const int arow = tid >> 3;               // + 32*j
    const int aoff = tid & 7;

    const uint32_t sA[2] = { smem_to_u32(Asb[0]), smem_to_u32(Asb[1]) };
    const uint32_t sB[2] = { smem_to_u32(Bsb[0]), smem_to_u32(Bsb[1]) };

    float rmu[8], riv[8];
    if (MODE == 0) {
#pragma unroll
        for (int j = 0; j < 8; j++) {
            rmu[j] = mu_arr[m0 + arow + 32 * j];
            riv[j] = iv_arr[m0 + arow + 32 * j];
        }
    }
    const int b8 = (m0 >> 14) << 3;          // batch*8 (CTA within one batch)

    float acc[4][4][4];
#pragma unroll
    for (int i = 0; i < 4; i++)
#pragma unroll
        for (int j = 0; j < 4; j++)
#pragma unroll
            for (int q = 0; q < 4; q++) acc[i][j][q] = 0.f;

    auto prefetch = [&](int kt) {
        int buf = kt & 1;
        const float* ag = A + (size_t)m0 * K + kt * 32;
        const float* bg = W + (size_t)n0 * K + kt * 32;
#pragma unroll
        for (int j = 0; j < 8; j++) {
            int row = arow + 32 * j;
            CP_ASYNC16(sA[buf] + (uint32_t)(row * AST + aoff * 4) * 4,
                       ag + (size_t)row * K + aoff * 4);
        }
#pragma unroll
        for (int j = 0; j < 2; j++) {
            int idx = tid + 256 * j;
            int row = idx >> 3, off = idx & 7;
            CP_ASYNC16(sB[buf] + (uint32_t)(row * AST + off * 4) * 4,
                       bg + (size_t)row * K + off * 4);
        }
        CP_COMMIT();
    };

    prefetch(0);

    for (int kt = 0; kt < NCH; kt++) {
        if (kt + 1 < NCH) { prefetch(kt + 1); CP_WAIT(1); }
        else              { CP_WAIT(0); }
        __syncthreads();                     // chunk kt arrived; prev compute done
        {   // in-place normalize A chunk kt (thread-owned quads)
            float* as = Asb[kt & 1];
            const int k = kt * 32 + aoff * 4;
            float4 g4 = *reinterpret_cast<const float4*>(&cg[k]);
            float4 b4 = *reinterpret_cast<const float4*>(&cb[k]);
            float mug = 0.f, ivg = 1.f;
            if (MODE == 1) {
                int grp = k / 24;
                mug = mu_arr[b8 + grp];
                ivg = iv_arr[b8 + grp];
            }
#pragma unroll
            for (int j = 0; j < 8; j++) {
                int row = arow + 32 * j;
                float mu = (MODE == 0) ? rmu[j] : mug;
                float iv = (MODE == 0) ? riv[j] : ivg;
                float4 v = *reinterpret_cast<float4*>(&as[row * AST + aoff * 4]);
                v.x = (v.x - mu) * iv * g4.x + b4.x;
                v.y = (v.y - mu) * iv * g4.y + b4.y;
                v.z = (v.z - mu) * iv * g4.z + b4.z;
                v.w = (v.w - mu) * iv * g4.w + b4.w;
                *reinterpret_cast<float4*>(&as[row * AST + aoff * 4]) = v;
            }
        }
        __syncthreads();                     // transformed tile visible
        const float* as = Asb[kt & 1];
        const float* bs = Bsb[kt & 1];
#pragma unroll
        for (int ks = 0; ks < 4; ks++) {
            const int kk = ks * 8;
            const int cc = kk + (lane & 3);
            uint32_t af[4][4];
#pragma unroll
            for (int mf = 0; mf < 4; mf++) {
                int r = wm * 64 + mf * 16 + (lane >> 2);
                af[mf][0] = __float_as_uint(as[r * AST + cc]);
                af[mf][1] = __float_as_uint(as[(r + 8) * AST + cc]);
                af[mf][2] = __float_as_uint(as[r * AST + cc + 4]);
                af[mf][3] = __float_as_uint(as[(r + 8) * AST + cc + 4]);
            }
            uint32_t bf[4][2];
#pragma unroll
            for (int nf = 0; nf < 4; nf++) {
                int rb = wn * 32 + nf * 8 + (lane >> 2);
                bf[nf][0] = __float_as_uint(bs[rb * AST + cc]);
                bf[nf][1] = __float_as_uint(bs[rb * AST + cc + 4]);
            }
#pragma unroll
            for (int mf = 0; mf < 4; mf++)
#pragma unroll
                for (int nf = 0; nf < 4; nf++)
                    mma_tf32(acc[mf][nf][0], acc[mf][nf][1], acc[mf][nf][2], acc[mf][nf][3],
                             af[mf][0], af[mf][1], af[mf][2], af[mf][3],
                             bf[nf][0], bf[nf][1]);
        }
        __syncthreads();                     // compute done before next prefetch
    }

#pragma unroll
    for (int mf = 0; mf < 4; mf++) {
        int row = m0 + wm * 64 + mf * 16 + (lane >> 2);
#pragma unroll
        for (int nf = 0; nf < 4; nf++) {
            int col = n0 + wn * 32 + nf * 8 + 2 * (lane & 3);
            float bx = bias[col], by = bias[col + 1];
            float2 o0 = make_float2(acc[mf][nf][0] + bx, acc[mf][nf][1] + by);
            float2 o1 = make_float2(acc[mf][nf][2] + bx, acc[mf][nf][3] + by);
            *reinterpret_cast<float2*>(&C[(size_t)row * Ntot + col]) = o0;
            *reinterpret_cast<float2*>(&C[(size_t)(row + 8) * Ntot + col]) = o1;
        }
    }
}

// =====================================================================
// in_proj GEMM with fused BCHW gather (unchanged from round 5)
// =====================================================================
__global__ __launch_bounds__(256, 2)
void k_tc_in(const float* __restrict__ X, const float* __restrict__ Hh,
             const float* __restrict__ W, const float* __restrict__ bias,
             float* __restrict__ C)
{
    constexpr int K = 256, NCH = 8;
    constexpr int MST = 264;
    constexpr int AST = 36;
    extern __shared__ float smf[];
    float* Asb[2] = { smf, smf + 32 * MST };
    float* Bsb[2] = { smf + 2 * 32 * MST, smf + 2 * 32 * MST + 64 * AST };

    const int tid  = threadIdx.x;
    const int lane = tid & 31;
    const int warp = tid >> 5;
    const int wm = warp & 3, wn = warp >> 2;
    const int m0 = blockIdx.y * 256;
    const int n0 = blockIdx.x * 64;
    const int b  = m0 >> 14;
    const int p0 = m0 & 16383;

    const uint32_t sA[2] = { smem_to_u32(Asb[0]), smem_to_u32(Asb[1]) };
    const uint32_t sB[2] = { smem_to_u32(Bsb[0]), smem_to_u32(Bsb[1]) };

    float acc[4][4][4];
#pragma unroll
    for (int i = 0; i < 4; i++)
#pragma unroll
        for (int j = 0; j < 4; j++)
#pragma unroll
            for (int q = 0; q < 4; q++) acc[i][j][q] = 0.f;

    auto prefetch = [&](int kt) {
        int buf = kt & 1;
#pragma unroll
        for (int j = 0; j < 8; j++) {
            int idx = tid + 256 * j;
            int k = idx >> 6, ms = idx & 63;
            int kg = kt * 32 + k;
            const float* src = (kg < 64)
                ? X  + (((size_t)(b * 64  + kg))        << 14) + p0 + ms * 4
                : Hh + (((size_t)(b * 192 + (kg - 64))) << 14) + p0 + ms * 4;
            CP_ASYNC16(sA[buf] + (uint32_t)(k * MST + ms * 4) * 4, src);
        }
        const float* bg = W + (size_t)n0 * K + kt * 32;
#pragma unroll
        for (int j = 0; j < 2; j++) {
            int idx = tid + 256 * j;
            int row = idx >> 3, off = idx & 7;
            CP_ASYNC16(sB[buf] + (uint32_t)(row * AST + off * 4) * 4,
                       bg + (size_t)row * K + off * 4);
        }
        CP_COMMIT();
    };

    prefetch(0);

    for (int kt = 0; kt < NCH; kt++) {
        if (kt + 1 < NCH) { prefetch(kt + 1); CP_WAIT(1); }
        else              { CP_WAIT(0); }
        __syncthreads();
        const float* as = Asb[kt & 1];
        const float* bs = Bsb[kt & 1];
#pragma unroll
        for (int ks = 0; ks < 4; ks++) {
            const int kk = ks * 8;
            const int cc = kk + (lane & 3);
            uint32_t af[4][4];
#pragma unroll
            for (int mf = 0; mf < 4; mf++) {
                int r = wm * 64 + mf * 16 + (lane >> 2);
                af[mf][0] = __float_as_uint(as[cc * MST + r]);
                af[mf][1] = __float_as_uint(as[cc * MST + r + 8]);
                af[mf][2] = __float_as_uint(as[(cc + 4) * MST + r]);
                af[mf][3] = __float_as_uint(as[(cc + 4) * MST + r + 8]);
            }
            uint32_t bf[4][2];
#pragma unroll
            for (int nf = 0; nf < 4; nf++) {
                int rb = wn * 32 + nf * 8 + (lane >> 2);
                bf[nf][0] = __float_as_uint(bs[rb * AST + cc]);
                bf[nf][1] = __float_as_uint(bs[rb * AST + cc + 4]);
            }
#pragma unroll
            for (int mf = 0; mf < 4; mf++)
#pragma unroll
                for (int nf = 0; nf < 4; nf++)
                    mma_tf32(acc[mf][nf][0], acc[mf][nf][1], acc[mf][nf][2], acc[mf][nf][3],
                             af[mf][0], af[mf][1], af[mf][2], af[mf][3],
                             bf[nf][0], bf[nf][1]);
        }
        __syncthreads();
    }

#pragma unroll
    for (int mf = 0; mf < 4; mf++) {
        int row = m0 + wm * 64 + mf * 16 + (lane >> 2);
#pragma unroll
        for (int nf = 0; nf < 4; nf++) {
            int col = n0 + wn * 32 + nf * 8 + 2 * (lane & 3);
            float bx = bias[col], by = bias[col + 1];
            float2 o0 = make_float2(acc[mf][nf][0] + bx, acc[mf][nf][1] + by);
            float2 o1 = make_float2(acc[mf][nf][2] + bx, acc[mf][nf][3] + by);
            *reinterpret_cast<float2*>(&C[(size_t)row * 192 + col]) = o0;
            *reinterpret_cast<float2*>(&C[(size_t)(row + 8) * 192 + col]) = o1;
        }
    }
}

// =====================================================================
// LayerNorm stats only: one warp per token -> mu, inv
// =====================================================================
__global__ __launch_bounds__(256)
void k_lnstats(float* __restrict__ omu, float* __restrict__ oiv)
{
    int warp = (blockIdx.x * blockDim.x + threadIdx.x) >> 5;
    int lane = threadIdx.x & 31;
    const float* row = &g_proj[(size_t)warp * 192];
    float v[6];
    float s = 0.f;
#pragma unroll
    for (int j = 0; j < 6; j++) { v[j] = row[lane + 32 * j]; s += v[j]; }
#pragma unroll
    for (int o = 16; o; o >>= 1) s += __shfl_xor_sync(0xffffffffu, s, o);
    float mean = s * (1.0f / 192.0f);
    float q = 0.f;
#pragma unroll
    for (int j = 0; j < 6; j++) { float d = v[j] - mean; q += d * d; }
#pragma unroll
    for (int o = 16; o; o >>= 1) q += __shfl_xor_sync(0xffffffffu, q, o);
    float inv = rsqrtf(q * (1.0f / 192.0f) + 1e-5f);
    if (lane == 0) { omu[warp] = mean; oiv[warp] = inv; }
}

// =====================================================================
// Window attention — float4 vectorized, forced 4 CTAs/SM
// =====================================================================
#define QS 580
__global__ __launch_bounds__(256, 4)
void k_attn()
{
    __shared__ float sq[16 * QS];
    __shared__ float ss[4 * 16 * 16];
    __shared__ int smm[16];

    int w = blockIdx.x;
    int tid = threadIdx.x;
    if (tid < 16) {
        int b = w >> 10, wi = w & 1023, wy = wi >> 5, wx = wi & 31;
        int ty = tid >> 2, tx = tid & 3;
        smm[tid] = (b << 14) + ((wy * 4 + ty) << 7) + (wx * 4 + tx);
    }
    __syncthreads();

#pragma unroll
    for (int j = 0; j < 9; j++) {
        int i = tid + 256 * j;
        int t = i / 144, c4 = i - t * 144;
        float4 v = *reinterpret_cast<const float4*>(&g_qkv[(size_t)smm[t] * 576 + c4 * 4]);
        *reinterpret_cast<float4*>(&sq[t * QS + c4 * 4]) = v;
    }
    __syncthreads();

    {   // scores: 4 heads x 16x16
        int h = tid >> 6, r = (tid >> 2) & 15, c0 = (tid & 3) * 4;
        const float4* qrow = reinterpret_cast<const float4*>(&sq[r * QS + h * 48]);
#pragma unroll
        for (int cc = 0; cc < 4; cc++) {
            const float4* krow = reinterpret_cast<const float4*>(&sq[(c0 + cc) * QS + 192 + h * 48]);
            float d = 0.f;
#pragma unroll
            for (int k = 0; k < 12; k++) {
                float4 qv = qrow[k], kv = krow[k];
                d += qv.x * kv.x + qv.y * kv.y + qv.z * kv.z + qv.w * kv.w;
            }
            ss[(h * 16 + r) * 16 + c0 + cc] = d * 0.14433756729740643f;
        }
    }
    __syncthreads();

    if (tid < 64) {
        float* row = &ss[tid * 16];
        float mx = row[0];
#pragma unroll
        for (int j = 1; j < 16; j++) mx = fmaxf(mx, row[j]);
        float sm = 0.f;
#pragma unroll
        for (int j = 0; j < 16; j++) { float e = __expf(row[j] - mx); row[j] = e; sm += e; }
        float r = 1.f / sm;
#pragma unroll
        for (int j = 0; j < 16; j++) row[j] *= r;
    }
    __syncthreads();

#pragma unroll
    for (int j = 0; j < 3; j++) {
        int i = tid + 256 * j;
        int r = i / 48, c4 = i - r * 48;
        int h = c4 / 12;
        const float* srow = &ss[(h * 16 + r) * 16];
        const float* vbase = &sq[384 + c4 * 4];
        float4 o = make_float4(0.f, 0.f, 0.f, 0.f);
#pragma unroll
        for (int jj = 0; jj < 16; jj++) {
            float4 vv = *reinterpret_cast<const float4*>(&vbase[jj * QS]);
            float sv = srow[jj];
            o.x += sv * vv.x; o.y += sv * vv.y; o.z += sv * vv.z; o.w += sv * vv.w;
        }
        *reinterpret_cast<float4*>(&g_attn[(size_t)smm[r] * 192 + c4 * 4]) = o;
    }
}

// =====================================================================
// GroupNorm #1 stats (token-major amap)
// =====================================================================
__global__ __launch_bounds__(192)
void k_gn1_stats()
{
    int b = blockIdx.x >> 6;
    int chunk = blockIdx.x & 63;
    int c = threadIdx.x;
    size_t base = ((size_t)(b * 16384 + chunk * 256)) * 192 + c;
    float s = 0.f, q = 0.f;
    for (int r = 0; r < 256; r++) {
        float v = g_amap[base + (size_t)r * 192];
        s += v; q += v * v;
    }
    g_p1s[(b * 192 + c) * 64 + chunk] = s;
    g_p1q[(b * 192 + c) * 64 + chunk] = q;
}

__global__ void k_gn1_final()
{
    int t = threadIdx.x;
    if (t >= 64) return;
    int b = t >> 3, g = t & 7;
    float S = 0.f, Q = 0.f;
    for (int i = 0; i < 24; i++) {
        int cc = b * 192 + g * 24 + i;
        for (int ch = 0; ch < 64; ch++) { S += g_p1s[cc * 64 + ch]; Q += g_p1q[cc * 64 + ch]; }
    }
    const float inv_n = 1.0f / 393216.0f;
    float mu = S * inv_n;
    float var = Q * inv_n - mu * mu;
    g_mu1[t] = mu;
    g_inv1[t] = rsqrtf(var + 1e-5f);
}

// =====================================================================
// LSTM pointwise
// =====================================================================
__global__ __launch_bounds__(256)
void k_lstm(const float* __restrict__ Cin, float* __restrict__ out)
{
    __shared__ float gs[16 * 768];
    int tok0 = blockIdx.x * 16;
    int b = tok0 >> 14;
    int p0 = tok0 & 16383;
    int tid = threadIdx.x;
    for (int i = tid; i < 16 * 768 / 4; i += 256) {
        *reinterpret_cast<float4*>(&gs[i * 4]) =
            *reinterpret_cast<const float4*>(&g_gates[(size_t)tok0 * 768 + i * 4]);
    }
    __syncthreads();
#pragma unroll
    for (int it = 0; it < 12; it++) {
        int idx = tid + 256 * it;
        int pl = idx / 192, n = idx - pl * 192;
        float gi = gs[pl * 768 + n];
        float gf = gs[pl * 768 + n + 192];
        float go = gs[pl * 768 + n + 384];
        float gG = gs[pl * 768 + n + 576];
        float i_ = 1.f / (1.f + __expf(-gi));
        float f_ = 1.f / (1.f + __expf(-gf));
        float o_ = 1.f / (1.f + __expf(-go));
        float g_ = tanhf(gG);
        size_t addr = ((size_t)(b * 192 + n) << 14) + p0 + pl;
        float cp = Cin[addr];
        float cn = f_ * cp + i_ * g_;
        out[(size_t)HSZ + addr] = cn;
        g_hraw[addr] = o_ * tanhf(cn);
    }
}

// =====================================================================
// GroupNorm #2 over BCHW hraw
// =====================================================================
__global__ __launch_bounds__(256)
void k_gn2_stats()
{
    __shared__ float rs[256], rq[256];
    int grp = blockIdx.x >> 4;
    int part = blockIdx.x & 15;
    int b = grp >> 3, g = grp & 7;
    size_t base = ((size_t)(b * 192 + g * 24) << 14) + (size_t)part * 24576;
    int tid = threadIdx.x;
    float s = 0.f, q = 0.f;
    for (int j = 0; j < 24; j++) {
        float4 v = *reinterpret_cast<const float4*>(&g_hraw[base + (size_t)(tid + 256 * j) * 4]);
        s += v.x + v.y + v.z + v.w;
        q += v.x * v.x + v.y * v.y + v.z * v.z + v.w * v.w;
    }
    rs[tid] = s; rq[tid] = q;
    __syncthreads();
    for (int o = 128; o; o >>= 1) {
        if (tid < o) { rs[tid] += rs[tid + o]; rq[tid] += rq[tid + o]; }
        __syncthreads();
    }
    if (tid == 0) { g_p2s[grp * 16 + part] = rs[0]; g_p2q[grp * 16 + part] = rq[0]; }
}

__global__ void k_gn2_final()
{
    int t = threadIdx.x;
    if (t >= 64) return;
    float S = 0.f, Q = 0.f;
    for (int i = 0; i < 16; i++) { S += g_p2s[t * 16 + i]; Q += g_p2q[t * 16 + i]; }
    const float inv_n = 1.0f / 393216.0f;
    float mu = S * inv_n;
    float var = Q * inv_n - mu * mu;
    g_mu2[t] = mu;
    g_inv2[t] = rsqrtf(var + 1e-5f);
}

__global__ __launch_bounds__(256)
void k_finalize(const float* __restrict__ gg, const float* __restrict__ gb,
                float* __restrict__ out)
{
    size_t idx4 = (size_t)blockIdx.x * 256 + threadIdx.x;
    size_t base = idx4 * 4;
    int bc = (int)(base >> 14);
    int b = bc / 192;
    int c = bc - b * 192;
    int grp = c / 24;
    float mu = g_mu2[b * 8 + grp], inv = g_inv2[b * 8 + grp];
    float sc = gg[c] * inv;
    float bi = gb[c];
    float4 v = *reinterpret_cast<const float4*>(&g_hraw[base]);
    float4 o;
    o.x = (v.x - mu) * sc + bi;
    o.y = (v.y - mu) * sc + bi;
    o.z = (v.z - mu) * sc + bi;
    o.w = (v.w - mu) * sc + bi;
    *reinterpret_cast<float4*>(&out[base]) = o;
}

// =====================================================================
// host launcher
// =====================================================================
extern "C" void kernel_launch(void* const* d_in, const int* in_sizes, int n_in,
                              void* d_out, int out_size)
{
    const float* x       = (const float*)d_in[0];
    const float* h       = (const float*)d_in[1];
    const float* c       = (const float*)d_in[2];
    const float* w_in    = (const float*)d_in[3];
    const float* b_in    = (const float*)d_in[4];
    const float* ln_g    = (const float*)d_in[5];
    const float* ln_b    = (const float*)d_in[6];
    const float* w_qkv   = (const float*)d_in[7];
    const float* b_qkv   = (const float*)d_in[8];
    const float* w_proj  = (const float*)d_in[9];
    const float* b_proj  = (const float*)d_in[10];
    const float* gn_g    = (const float*)d_in[11];
    const float* gn_b    = (const float*)d_in[12];
    const float* w_gates = (const float*)d_in[13];
    const float* b_gates = (const float*)d_in[14];
    float* out = (float*)d_out;

    void *p_proj, *p_qkv, *p_attn, *p_amap, *p_gates, *p_lnmu, *p_lniv, *p_mu1, *p_inv1;
    cudaGetSymbolAddress(&p_proj,  g_proj);
    cudaGetSymbolAddress(&p_qkv,   g_qkv);
    cudaGetSymbolAddress(&p_attn,  g_attn);
    cudaGetSymbolAddress(&p_amap,  g_amap);
    cudaGetSymbolAddress(&p_gates, g_gates);
    cudaGetSymbolAddress(&p_lnmu,  g_lnmu);
    cudaGetSymbolAddress(&p_lniv,  g_lniv);
    cudaGetSymbolAddress(&p_mu1,   g_mu1);
    cudaGetSymbolAddress(&p_inv1,  g_inv1);

    const int SM_TC  = (2 * 256 + 2 * 64) * 36 * 4;            // 92160
    const int SM_IN  = (2 * 32 * 264 + 2 * 64 * 36) * 4;       // 86016
    cudaFuncSetAttribute(k_tc2<192>,    cudaFuncAttributeMaxDynamicSharedMemorySize, SM_TC);
    cudaFuncSetAttribute(k_tcn<192, 0>, cudaFuncAttributeMaxDynamicSharedMemorySize, SM_TC);
    cudaFuncSetAttribute(k_tcn<192, 1>, cudaFuncAttributeMaxDynamicSharedMemorySize, SM_TC);
    cudaFuncSetAttribute(k_tc_in,       cudaFuncAttributeMaxDynamicSharedMemorySize, SM_IN);

    // 1) in_proj GEMM with fused BCHW gather -> g_proj (raw)
    k_tc_in<<<dim3(3, 512), 256, SM_IN>>>(x, h, w_in, b_in, (float*)p_proj);
    // 2) LayerNorm stats -> g_lnmu / g_lniv
    k_lnstats<<<16384, 256>>>((float*)p_lnmu, (float*)p_lniv);
    // 3) qkv GEMM with fused LayerNorm on A -> g_qkv
    k_tcn<192, 0><<<dim3(9, 512), 256, SM_TC>>>((const float*)p_proj, w_qkv, b_qkv,
                                                (float*)p_qkv, 576,
                                                (const float*)p_lnmu, (const float*)p_lniv,
                                                ln_g, ln_b);
    // 4) window attention -> g_attn
    k_attn<<<8192, 256>>>();
    // 5) out_proj GEMM -> g_amap (raw)
    k_tc2<192><<<dim3(3, 512), 256, SM_TC>>>((const float*)p_attn, w_proj, b_proj,
                                             (float*)p_amap, 192);
    // 6) GroupNorm stats over amap
    k_gn1_stats<<<512, 192>>>();
    k_gn1_final<<<1, 64>>>();
    // 7) gates GEMM with fused GroupNorm on A -> g_gates
    k_tcn<192, 1><<<dim3(12, 512), 256, SM_TC>>>((const float*)p_amap, w_gates, b_gates,
                                                 (float*)p_gates, 768,
                                                 (const float*)p_mu1, (const float*)p_inv1,
                                                 gn_g, gn_b);
    // 8) LSTM pointwise -> cnext (d_out second half) + hraw
    k_lstm<<<8192, 256>>>(c, out);
    // 9) GroupNorm(hnext) -> d_out first half
    k_gn2_stats<<<1024, 256>>>();
    k_gn2_final<<<1, 64>>>();
    k_finalize<<<24576, 256>>>(gn_g, gn_b, out);
}

// round 7
// speedup vs baseline: 2.5768x; 1.3098x over previous
#include <cuda_runtime.h>
#include <cstdint>

// ---------------- problem constants ----------------
#define TOK    131072              // B*H*W tokens (raster order)
#define HSZ    25165824            // 8*192*128*128 (one output tensor)

// ---------------- static device scratch ----------------
__device__ float g_proj[(size_t)TOK * 192];   // in_proj out (raw, pre-LN)
__device__ float g_qkv [(size_t)TOK * 576];
__device__ float g_attn[(size_t)TOK * 192];
__device__ float g_amap[(size_t)TOK * 192];   // out_proj out (raw, pre-GN)
__device__ float g_hraw[(size_t)TOK * 192];   // BCHW layout
__device__ float g_wperm[768 * 192];          // permuted gates weight
__device__ float g_bperm[768];
__device__ float g_lnmu[TOK], g_lniv[TOK];
__device__ float g_p1s[8 * 192 * 64];
__device__ float g_p1q[8 * 192 * 64];
__device__ float g_mu1[64], g_inv1[64];
__device__ float g_p2s[64 * 16], g_p2q[64 * 16];
__device__ float g_mu2[64], g_inv2[64];

// ---------------- PTX helpers ----------------
#define CP_ASYNC16(sm, gp) \
    asm volatile("cp.async.cg.shared.global [%0], [%1], 16;" :: "r"((uint32_t)(sm)), "l"(gp))
#define CP_COMMIT() asm volatile("cp.async.commit_group;" ::: "memory")
#define CP_WAIT(n)  asm volatile("cp.async.wait_group %0;" :: "n"(n) : "memory")

__device__ __forceinline__ uint32_t smem_to_u32(const void* p) {
    uint32_t a;
    asm("{ .reg .u64 t; cvta.to.shared.u64 t, %1; cvt.u32.u64 %0, t; }" : "=r"(a) : "l"(p));
    return a;
}
__device__ __forceinline__ void mma_tf32(float& c0, float& c1, float& c2, float& c3,
                                         uint32_t a0, uint32_t a1, uint32_t a2, uint32_t a3,
                                         uint32_t b0, uint32_t b1) {
    asm volatile("mma.sync.aligned.m16n8k8.row.col.f32.tf32.tf32.f32 "
                 "{%0,%1,%2,%3}, {%4,%5,%6,%7}, {%8,%9}, {%0,%1,%2,%3};"
                 : "+f"(c0), "+f"(c1), "+f"(c2), "+f"(c3)
                 : "r"(a0), "r"(a1), "r"(a2), "r"(a3), "r"(b0), "r"(b1));
}

// =====================================================================
// Plain tf32 GEMM: C = A[M,K] * W[N,K]^T + bias. CTA 256x64, 8 warps.
// =====================================================================
template<int K>
__global__ __launch_bounds__(256, 2)
void k_tc2(const float* __restrict__ A, const float* __restrict__ W,
           const float* __restrict__ bias, float* __restrict__ C, int Ntot)
{
    constexpr int NCH = K / 32;
    constexpr int AST = 36;
    extern __shared__ float smf[];
    float* Asb[2] = { smf, smf + 256 * AST };
    float* Bsb[2] = { smf + 2 * 256 * AST, smf + 2 * 256 * AST + 64 * AST };

    const int tid  = threadIdx.x;
    const int lane = tid & 31;
    const int warp = tid >> 5;
    const int wm = warp & 3, wn = warp >> 2;
    const int m0 = blockIdx.y * 256;
    const int n0 = blockIdx.x * 64;

    const uint32_t sA[2] = { smem_to_u32(Asb[0]), smem_to_u32(Asb[1]) };
    const uint32_t sB[2] = { smem_to_u32(Bsb[0]), smem_to_u32(Bsb[1]) };

    float acc[4][4][4];
#pragma unroll
    for (int i = 0; i < 4; i++)
#pragma unroll
        for (int j = 0; j < 4; j++)
#pragma unroll
            for (int q = 0; q < 4; q++) acc[i][j][q] = 0.f;

    auto prefetch = [&](int kt) {
        int buf = kt & 1;
        const float* ag = A + (size_t)m0 * K + kt * 32;
        const float* bg = W + (size_t)n0 * K + kt * 32;
#pragma unroll
        for (int j = 0; j < 8; j++) {
            int idx = tid + 256 * j;
            int row = idx >> 3, off = idx & 7;
            CP_ASYNC16(sA[buf] + (uint32_t)(row * AST + off * 4) * 4,
                       ag + (size_t)row * K + off * 4);
        }
#pragma unroll
        for (int j = 0; j < 2; j++) {
            int idx = tid + 256 * j;
            int row = idx >> 3, off = idx & 7;
            CP_ASYNC16(sB[buf] + (uint32_t)(row * AST + off * 4) * 4,
                       bg + (size_t)row * K + off * 4);
        }
        CP_COMMIT();
    };

    prefetch(0);

    for (int kt = 0; kt < NCH; kt++) {
        if (kt + 1 < NCH) { prefetch(kt + 1); CP_WAIT(1); }
        else              { CP_WAIT(0); }
        __syncthreads();
        const float* as = Asb[kt & 1];
        const float* bs = Bsb[kt & 1];
#pragma unroll
        for (int ks = 0; ks < 4; ks++) {
            const int kk = ks * 8;
            const int cc = kk + (lane & 3);
            uint32_t af[4][4];
#pragma unroll
            for (int mf = 0; mf < 4; mf++) {
                int r = wm * 64 + mf * 16 + (lane >> 2);
                af[mf][0] = __float_as_uint(as[r * AST + cc]);
                af[mf][1] = __float_as_uint(as[(r + 8) * AST + cc]);
                af[mf][2] = __float_as_uint(as[r * AST + cc + 4]);
                af[mf][3] = __float_as_uint(as[(r + 8) * AST + cc + 4]);
            }
            uint32_t bf[4][2];
#pragma unroll
            for (int nf = 0; nf < 4; nf++) {
                int rb = wn * 32 + nf * 8 + (lane >> 2);
                bf[nf][0] = __float_as_uint(bs[rb * AST + cc]);
                bf[nf][1] = __float_as_uint(bs[rb * AST + cc + 4]);
            }
#pragma unroll
            for (int mf = 0; mf < 4; mf++)
#pragma unroll
                for (int nf = 0; nf < 4; nf++)
                    mma_tf32(acc[mf][nf][0], acc[mf][nf][1], acc[mf][nf][2], acc[mf][nf][3],
                             af[mf][0], af[mf][1], af[mf][2], af[mf][3],
                             bf[nf][0], bf[nf][1]);
        }
        __syncthreads();
    }

#pragma unroll
    for (int mf = 0; mf < 4; mf++) {
        int row = m0 + wm * 64 + mf * 16 + (lane >> 2);
#pragma unroll
        for (int nf = 0; nf < 4; nf++) {
            int col = n0 + wn * 32 + nf * 8 + 2 * (lane & 3);
            float bx = bias[col], by = bias[col + 1];
            float2 o0 = make_float2(acc[mf][nf][0] + bx, acc[mf][nf][1] + by);
            float2 o1 = make_float2(acc[mf][nf][2] + bx, acc[mf][nf][3] + by);
            *reinterpret_cast<float2*>(&C[(size_t)row * Ntot + col]) = o0;
            *reinterpret_cast<float2*>(&C[(size_t)(row + 8) * Ntot + col]) = o1;
        }
    }
}

// =====================================================================
// qkv GEMM with fused LayerNorm on A (MODE 0 of old k_tcn)
// =====================================================================
template<int K>
__global__ __launch_bounds__(256, 2)
void k_tcln(const float* __restrict__ A, const float* __restrict__ W,
            const float* __restrict__ bias, float* __restrict__ C, int Ntot,
            const float* __restrict__ mu_arr, const float* __restrict__ iv_arr,
            const float* __restrict__ cg, const float* __restrict__ cb)
{
    constexpr int NCH = K / 32;
    constexpr int AST = 36;
    extern __shared__ float smf[];
    float* Asb[2] = { smf, smf + 256 * AST };
    float* Bsb[2] = { smf + 2 * 256 * AST, smf + 2 * 256 * AST + 64 * AST };

    const int tid  = threadIdx.x;
    const int lane = tid & 31;
    const int warp = tid >> 5;
    const int wm = warp & 3, wn = warp >> 2;
    const int m0 = blockIdx.y * 256;
    const int n0 = blockIdx.x * 64;
    const int arow = tid >> 3;
    const int aoff = tid & 7;

    const uint32_t sA[2] = { smem_to_u32(Asb[0]), smem_to_u32(Asb[1]) };
    const uint32_t sB[2] = { smem_to_u32(Bsb[0]), smem_to_u32(Bsb[1]) };

    float rmu[8], riv[8];
#pragma unroll
    for (int j = 0; j < 8; j++) {
        rmu[j] = mu_arr[m0 + arow + 32 * j];
        riv[j] = iv_arr[m0 + arow + 32 * j];
    }

    float acc[4][4][4];
#pragma unroll
    for (int i = 0; i < 4; i++)
#pragma unroll
        for (int j = 0; j < 4; j++)
#pragma unroll
            for (int q = 0; q < 4; q++) acc[i][j][q] = 0.f;

    auto prefetch = [&](int kt) {
        int buf = kt & 1;
        const float* ag = A + (size_t)m0 * K + kt * 32;
        const float* bg = W + (size_t)n0 * K + kt * 32;
#pragma unroll
        for (int j = 0; j < 8; j++) {
            int row = arow + 32 * j;
            CP_ASYNC16(sA[buf] + (uint32_t)(row * AST + aoff * 4) * 4,
                       ag + (size_t)row * K + aoff * 4);
        }
#pragma unroll
        for (int j = 0; j < 2; j++) {
            int idx = tid + 256 * j;
            int row = idx >> 3, off = idx & 7;
            CP_ASYNC16(sB[buf] + (uint32_t)(row * AST + off * 4) * 4,
                       bg + (size_t)row * K + off * 4);
        }
        CP_COMMIT();
    };

    prefetch(0);

    for (int kt = 0; kt < NCH; kt++) {
        if (kt + 1 < NCH) { prefetch(kt + 1); CP_WAIT(1); }
        else              { CP_WAIT(0); }
        __syncthreads();
        {   // in-place LayerNorm on A chunk
            float* as = Asb[kt & 1];
            const int k = kt * 32 + aoff * 4;
            float4 g4 = *reinterpret_cast<const float4*>(&cg[k]);
            float4 b4 = *reinterpret_cast<const float4*>(&cb[k]);
#pragma unroll
            for (int j = 0; j < 8; j++) {
                int row = arow + 32 * j;
                float mu = rmu[j], iv = riv[j];
                float4 v = *reinterpret_cast<float4*>(&as[row * AST + aoff * 4]);
                v.x = (v.x - mu) * iv * g4.x + b4.x;
                v.y = (v.y - mu) * iv * g4.y + b4.y;
                v.z = (v.z - mu) * iv * g4.z + b4.z;
                v.w = (v.w - mu) * iv * g4.w + b4.w;
                *reinterpret_cast<float4*>(&as[row * AST + aoff * 4]) = v;
            }
        }
        __syncthreads();
        const float* as = Asb[kt & 1];
        const float* bs = Bsb[kt & 1];
#pragma unroll
        for (int ks = 0; ks < 4; ks++) {
            const int kk = ks * 8;
            const int cc = kk + (lane & 3);
            uint32_t af[4][4];
#pragma unroll
            for (int mf = 0; mf < 4; mf++) {
                int r = wm * 64 + mf * 16 + (lane >> 2);
                af[mf][0] = __float_as_uint(as[r * AST + cc]);
                af[mf][1] = __float_as_uint(as[(r + 8) * AST + cc]);
                af[mf][2] = __float_as_uint(as[r * AST + cc + 4]);
                af[mf][3] = __float_as_uint(as[(r + 8) * AST + cc + 4]);
            }
            uint32_t bf[4][2];
#pragma unroll
            for (int nf = 0; nf < 4; nf++) {
                int rb = wn * 32 + nf * 8 + (lane >> 2);
                bf[nf][0] = __float_as_uint(bs[rb * AST + cc]);
                bf[nf][1] = __float_as_uint(bs[rb * AST + cc + 4]);
            }
#pragma unroll
            for (int mf = 0; mf < 4; mf++)
#pragma unroll
                for (int nf = 0; nf < 4; nf++)
                    mma_tf32(acc[mf][nf][0], acc[mf][nf][1], acc[mf][nf][2], acc[mf][nf][3],
                             af[mf][0], af[mf][1], af[mf][2], af[mf][3],
                             bf[nf][0], bf[nf][1]);
        }
        __syncthreads();
    }

#pragma unroll
    for (int mf = 0; mf < 4; mf++) {
        int row = m0 + wm * 64 + mf * 16 + (lane >> 2);
#pragma unroll
        for (int nf = 0; nf < 4; nf++) {
            int col = n0 + wn * 32 + nf * 8 + 2 * (lane & 3);
            float bx = bias[col], by = bias[col + 1];
            float2 o0 = make_float2(acc[mf][nf][0] + bx, acc[mf][nf][1] + by);
            float2 o1 = make_float2(acc[mf][nf][2] + bx, acc[mf][nf][3] + by);
            *reinterpret_cast<float2*>(&C[(size_t)row * Ntot + col]) = o0;
            *reinterpret_cast<float2*>(&C[(size_t)(row + 8) * Ntot + col]) = o1;
        }
    }
}

// =====================================================================
// gates GEMM (permuted W) + fused GroupNorm on A + fused LSTM epilogue.
// Permuted col = t*64 + half*32 + b*16 + (gate/2)*8 + q*2 + (gate%2)
//   where ch = t*16 + half*8 + b*4 + q. So the thread owning fragment
//   cols {c0, c0+1} at nf gets: nf=0 -> chA gates i,f; nf=1 -> chA o,g;
//   nf=2 -> chB i,f; nf=3 -> chB o,g.
// Writes cnext -> out[HSZ+...], hraw -> g_hraw (both BCHW). No C output.
// =====================================================================
__global__ __launch_bounds__(256, 2)
void k_tcg(const float* __restrict__ A, const float* __restrict__ W,
           const float* __restrict__ bias,
           const float* __restrict__ mu_arr, const float* __restrict__ iv_arr,
           const float* __restrict__ cg, const float* __restrict__ cb,
           const float* __restrict__ Cin, float* __restrict__ out)
{
    constexpr int K = 192, NCH = 6;
    constexpr int AST = 36;
    extern __shared__ float smf[];
    float* Asb[2] = { smf, smf + 256 * AST };
    float* Bsb[2] = { smf + 2 * 256 * AST, smf + 2 * 256 * AST + 64 * AST };

    const int tid  = threadIdx.x;
    const int lane = tid & 31;
    const int warp = tid >> 5;
    const int wm = warp & 3, wn = warp >> 2;
    const int m0 = blockIdx.y * 256;
    const int n0 = blockIdx.x * 64;
    const int arow = tid >> 3;
    const int aoff = tid & 7;
    const int b8 = (m0 >> 14) << 3;

    const uint32_t sA[2] = { smem_to_u32(Asb[0]), smem_to_u32(Asb[1]) };
    const uint32_t sB[2] = { smem_to_u32(Bsb[0]), smem_to_u32(Bsb[1]) };

    float acc[4][4][4];
#pragma unroll
    for (int i = 0; i < 4; i++)
#pragma unroll
        for (int j = 0; j < 4; j++)
#pragma unroll
            for (int q = 0; q < 4; q++) acc[i][j][q] = 0.f;

    auto prefetch = [&](int kt) {
        int buf = kt & 1;
        const float* ag = A + (size_t)m0 * K + kt * 32;
        const float* bg = W + (size_t)n0 * K + kt * 32;
#pragma unroll
        for (int j = 0; j < 8; j++) {
            int row = arow + 32 * j;
            CP_ASYNC16(sA[buf] + (uint32_t)(row * AST + aoff * 4) * 4,
                       ag + (size_t)row * K + aoff * 4);
        }
#pragma unroll
        for (int j = 0; j < 2; j++) {
            int idx = tid + 256 * j;
            int row = idx >> 3, off = idx & 7;
            CP_ASYNC16(sB[buf] + (uint32_t)(row * AST + off * 4) * 4,
                       bg + (size_t)row * K + off * 4);
        }
        CP_COMMIT();
    };

    prefetch(0);

    for (int kt = 0; kt < NCH; kt++) {
        if (kt + 1 < NCH) { prefetch(kt + 1); CP_WAIT(1); }
        else              { CP_WAIT(0); }
        __syncthreads();
        {   // in-place GroupNorm on A chunk
            float* as = Asb[kt & 1];
            const int k = kt * 32 + aoff * 4;
            float4 g4 = *reinterpret_cast<const float4*>(&cg[k]);
            float4 b4 = *reinterpret_cast<const float4*>(&cb[k]);
            int grp = k / 24;
            float mu = mu_arr[b8 + grp];
            float iv = iv_arr[b8 + grp];
#pragma unroll
            for (int j = 0; j < 8; j++) {
                int row = arow + 32 * j;
                float4 v = *reinterpret_cast<float4*>(&as[row * AST + aoff * 4]);
                v.x = (v.x - mu) * iv * g4.x + b4.x;
                v.y = (v.y - mu) * iv * g4.y + b4.y;
                v.z = (v.z - mu) * iv * g4.z + b4.z;
                v.w = (v.w - mu) * iv * g4.w + b4.w;
                *reinterpret_cast<float4*>(&as[row * AST + aoff * 4]) = v;
            }
        }
        __syncthreads();
        const float* as = Asb[kt & 1];
        const float* bs = Bsb[kt & 1];
#pragma unroll
        for (int ks = 0; ks < 4; ks++) {
            const int kk = ks * 8;
            const int cc = kk + (lane & 3);
            uint32_t af[4][4];
#pragma unroll
            for (int mf = 0; mf < 4; mf++) {
                int r = wm * 64 + mf * 16 + (lane >> 2);
                af[mf][0] = __float_as_uint(as[r * AST + cc]);
                af[mf][1] = __float_as_uint(as[(r + 8) * AST + cc]);
                af[mf][2] = __float_as_uint(as[r * AST + cc + 4]);
                af[mf][3] = __float_as_uint(as[(r + 8) * AST + cc + 4]);
            }
            uint32_t bf[4][2];
#pragma unroll
            for (int nf = 0; nf < 4; nf++) {
                int rb = wn * 32 + nf * 8 + (lane >> 2);
                bf[nf][0] = __float_as_uint(bs[rb * AST + cc]);
                bf[nf][1] = __float_as_uint(bs[rb * AST + cc + 4]);
            }
#pragma unroll
            for (int mf = 0; mf < 4; mf++)
#pragma unroll
                for (int nf = 0; nf < 4; nf++)
                    mma_tf32(acc[mf][nf][0], acc[mf][nf][1], acc[mf][nf][2], acc[mf][nf][3],
                             af[mf][0], af[mf][1], af[mf][2], af[mf][3],
                             bf[nf][0], bf[nf][1]);
        }
        __syncthreads();
    }

    // ---- LSTM epilogue ----
    const int q = lane & 3;
    const int t = blockIdx.x;                       // N-tile == channel tile
    const int chA = t * 16 + wn * 8 + q;            // b=0
    const int chB = chA + 4;                        // b=1
    const int colb = n0 + wn * 32 + 2 * q;
    float bIA = bias[colb + 0],  bFA = bias[colb + 1];
    float bOA = bias[colb + 8],  bGA = bias[colb + 9];
    float bIB = bias[colb + 16], bFB = bias[colb + 17];
    float bOB = bias[colb + 24], bGB = bias[colb + 25];

    const int bt = m0 >> 14;
    const size_t baseA = ((size_t)(bt * 192 + chA)) << 14;
    const size_t baseB = ((size_t)(bt * 192 + chB)) << 14;

#pragma unroll
    for (int mf = 0; mf < 4; mf++) {
        int row = m0 + wm * 64 + mf * 16 + (lane >> 2);
        int p = row & 16383;
#pragma unroll
        for (int half = 0; half < 2; half++) {      // row, row+8
            int pp = p + half * 8;
            int a0 = half * 2;                       // acc idx 0 or 2
            // channel A
            {
                float gi = acc[mf][0][a0]     + bIA;
                float gf = acc[mf][0][a0 + 1] + bFA;
                float go = acc[mf][1][a0]     + bOA;
                float gg = acc[mf][1][a0 + 1] + bGA;
                float i_ = 1.f / (1.f + __expf(-gi));
                float f_ = 1.f / (1.f + __expf(-gf));
                float o_ = 1.f / (1.f + __expf(-go));
                float g_ = tanhf(gg);
                size_t addr = baseA + pp;
                float cn = f_ * Cin[addr] + i_ * g_;
                out[(size_t)HSZ + addr] = cn;
                g_hraw[addr] = o_ * tanhf(cn);
            }
            // channel B
            {
                float gi = acc[mf][2][a0]     + bIB;
                float gf = acc[mf][2][a0 + 1] + bFB;
                float go = acc[mf][3][a0]     + bOB;
                float gg = acc[mf][3][a0 + 1] + bGB;
                float i_ = 1.f / (1.f + __expf(-gi));
                float f_ = 1.f / (1.f + __expf(-gf));
                float o_ = 1.f / (1.f + __expf(-go));
                float g_ = tanhf(gg);
                size_t addr = baseB + pp;
                float cn = f_ * Cin[addr] + i_ * g_;
                out[(size_t)HSZ + addr] = cn;
                g_hraw[addr] = o_ * tanhf(cn);
            }
        }
    }
}

// =====================================================================
// permute gates weight/bias into LSTM-fragment-friendly order
// =====================================================================
__global__ __launch_bounds__(192)
void k_permw(const float* __restrict__ wg, const float* __restrict__ bg)
{
    int col = blockIdx.x;
    int t = col >> 6, l = col & 63;
    int half = l >> 5, l2 = l & 31, b = l2 >> 4, l3 = l2 & 15;
    int ghi = l3 >> 3, l4 = l3 & 7, q = l4 >> 1, glo = l4 & 1;
    int gate = ghi * 2 + glo;
    int ch = t * 16 + half * 8 + b * 4 + q;
    int orow = gate * 192 + ch;
    g_wperm[col * 192 + threadIdx.x] = wg[orow * 192 + threadIdx.x];
    if (threadIdx.x == 0) g_bperm[col] = bg[orow];
}

// =====================================================================
// in_proj GEMM with fused BCHW gather (unchanged)
// =====================================================================
__global__ __launch_bounds__(256, 2)
void k_tc_in(const float* __restrict__ X, const float* __restrict__ Hh,
             const float* __restrict__ W, const float* __restrict__ bias,
             float* __restrict__ C)
{
    constexpr int K = 256, NCH = 8;
    constexpr int MST = 264;
    constexpr int AST = 36;
    extern __shared__ float smf[];
    float* Asb[2] = { smf, smf + 32 * MST };
    float* Bsb[2] = { smf + 2 * 32 * MST, smf + 2 * 32 * MST + 64 * AST };

    const int tid  = threadIdx.x;
    const int lane = tid & 31;
    const int warp = tid >> 5;
    const int wm = warp & 3, wn = warp >> 2;
    const int m0 = blockIdx.y * 256;
    const int n0 = blockIdx.x * 64;
    const int b  = m0 >> 14;
    const int p0 = m0 & 16383;

    const uint32_t sA[2] = { smem_to_u32(Asb[0]), smem_to_u32(Asb[1]) };
    const uint32_t sB[2] = { smem_to_u32(Bsb[0]), smem_to_u32(Bsb[1]) };

    float acc[4][4][4];
#pragma unroll
    for (int i = 0; i < 4; i++)
#pragma unroll
        for (int j = 0; j < 4; j++)
#pragma unroll
            for (int q = 0; q < 4; q++) acc[i][j][q] = 0.f;

    auto prefetch = [&](int kt) {
        int buf = kt & 1;
#pragma unroll
        for (int j = 0; j < 8; j++) {
            int idx = tid + 256 * j;
            int k = idx >> 6, ms = idx & 63;
            int kg = kt * 32 + k;
            const float* src = (kg < 64)
                ? X  + (((size_t)(b * 64  + kg))        << 14) + p0 + ms * 4
                : Hh + (((size_t)(b * 192 + (kg - 64))) << 14) + p0 + ms * 4;
            CP_ASYNC16(sA[buf] + (uint32_t)(k * MST + ms * 4) * 4, src);
        }
        const float* bg = W + (size_t)n0 * K + kt * 32;
#pragma unroll
        for (int j = 0; j < 2; j++) {
            int idx = tid + 256 * j;
            int row = idx >> 3, off = idx & 7;
            CP_ASYNC16(sB[buf] + (uint32_t)(row * AST + off * 4) * 4,
                       bg + (size_t)row * K + off * 4);
        }
        CP_COMMIT();
    };

    prefetch(0);

    for (int kt = 0; kt < NCH; kt++) {
        if (kt + 1 < NCH) { prefetch(kt + 1); CP_WAIT(1); }
        else              { CP_WAIT(0); }
        __syncthreads();
        const float* as = Asb[kt & 1];
        const float* bs = Bsb[kt & 1];
#pragma unroll
        for (int ks = 0; ks < 4; ks++) {
            const int kk = ks * 8;
            const int cc = kk + (lane & 3);
            uint32_t af[4][4];
#pragma unroll
            for (int mf = 0; mf < 4; mf++) {
                int r = wm * 64 + mf * 16 + (lane >> 2);
                af[mf][0] = __float_as_uint(as[cc * MST + r]);
                af[mf][1] = __float_as_uint(as[cc * MST + r + 8]);
                af[mf][2] = __float_as_uint(as[(cc + 4) * MST + r]);
                af[mf][3] = __float_as_uint(as[(cc + 4) * MST + r + 8]);
            }
            uint32_t bf[4][2];
#pragma unroll
            for (int nf = 0; nf < 4; nf++) {
                int rb = wn * 32 + nf * 8 + (lane >> 2);
                bf[nf][0] = __float_as_uint(bs[rb * AST + cc]);
                bf[nf][1] = __float_as_uint(bs[rb * AST + cc + 4]);
            }
#pragma unroll
            for (int mf = 0; mf < 4; mf++)
#pragma unroll
                for (int nf = 0; nf < 4; nf++)
                    mma_tf32(acc[mf][nf][0], acc[mf][nf][1], acc[mf][nf][2], acc[mf][nf][3],
                             af[mf][0], af[mf][1], af[mf][2], af[mf][3],
                             bf[nf][0], bf[nf][1]);
        }
        __syncthreads();
    }

#pragma unroll
    for (int mf = 0; mf < 4; mf++) {
        int row = m0 + wm * 64 + mf * 16 + (lane >> 2);
#pragma unroll
        for (int nf = 0; nf < 4; nf++) {
            int col = n0 + wn * 32 + nf * 8 + 2 * (lane & 3);
            float bx = bias[col], by = bias[col + 1];
            float2 o0 = make_float2(acc[mf][nf][0] + bx, acc[mf][nf][1] + by);
            float2 o1 = make_float2(acc[mf][nf][2] + bx, acc[mf][nf][3] + by);
            *reinterpret_cast<float2*>(&C[(size_t)row * 192 + col]) = o0;
            *reinterpret_cast<float2*>(&C[(size_t)(row + 8) * 192 + col]) = o1;
        }
    }
}

// =====================================================================
// LayerNorm stats only: one warp per token -> mu, inv
// =====================================================================
__global__ __launch_bounds__(256)
void k_lnstats(float* __restrict__ omu, float* __restrict__ oiv)
{
    int warp = (blockIdx.x * blockDim.x + threadIdx.x) >> 5;
    int lane = threadIdx.x & 31;
    const float* row = &g_proj[(size_t)warp * 192];
    float v[6];
    float s = 0.f;
#pragma unroll
    for (int j = 0; j < 6; j++) { v[j] = row[lane + 32 * j]; s += v[j]; }
#pragma unroll
    for (int o = 16; o; o >>= 1) s += __shfl_xor_sync(0xffffffffu, s, o);
    float mean = s * (1.0f / 192.0f);
    float q = 0.f;
#pragma unroll
    for (int j = 0; j < 6; j++) { float d = v[j] - mean; q += d * d; }
#pragma unroll
    for (int o = 16; o; o >>= 1) q += __shfl_xor_sync(0xffffffffu, q, o);
    float inv = rsqrtf(q * (1.0f / 192.0f) + 1e-5f);
    if (lane == 0) { omu[warp] = mean; oiv[warp] = inv; }
}

// =====================================================================
// Window attention — reduced smem traffic
// =====================================================================
#define QS 580
__global__ __launch_bounds__(256, 4)
void k_attn()
{
    __shared__ float sq[16 * QS];
    __shared__ float ss[4 * 16 * 16];
    __shared__ int smm[16];

    int w = blockIdx.x;
    int tid = threadIdx.x;
    if (tid < 16) {
        int b = w >> 10, wi = w & 1023, wy = wi >> 5, wx = wi & 31;
        int ty = tid >> 2, tx = tid & 3;
        smm[tid] = (b << 14) + ((wy * 4 + ty) << 7) + (wx * 4 + tx);
    }
    __syncthreads();

#pragma unroll
    for (int j = 0; j < 9; j++) {
        int i = tid + 256 * j;
        int t = i / 144, c4 = i - t * 144;
        float4 v = *reinterpret_cast<const float4*>(&g_qkv[(size_t)smm[t] * 576 + c4 * 4]);
        *reinterpret_cast<float4*>(&sq[t * QS + c4 * 4]) = v;
    }
    __syncthreads();

    {   // scores: Q held in register chunks, shared across 4 K columns
        int h = tid >> 6, r = (tid >> 2) & 15, c0 = (tid & 3) * 4;
        const float4* qrow = reinterpret_cast<const float4*>(&sq[r * QS + h * 48]);
        float d[4] = {0.f, 0.f, 0.f, 0.f};
#pragma unroll
        for (int ch = 0; ch < 2; ch++) {
            float4 qv[6];
#pragma unroll
            for (int k = 0; k < 6; k++) qv[k] = qrow[ch * 6 + k];
#pragma unroll
            for (int cc = 0; cc < 4; cc++) {
                const float4* krow = reinterpret_cast<const float4*>(
                    &sq[(c0 + cc) * QS + 192 + h * 48]);
#pragma unroll
                for (int k = 0; k < 6; k++) {
                    float4 kv = krow[ch * 6 + k];
                    d[cc] += qv[k].x * kv.x + qv[k].y * kv.y + qv[k].z * kv.z + qv[k].w * kv.w;
                }
            }
        }
#pragma unroll
        for (int cc = 0; cc < 4; cc++)
            ss[(h * 16 + r) * 16 + c0 + cc] = d[cc] * 0.14433756729740643f;
    }
    __syncthreads();

    if (tid < 64) {
        float* row = &ss[tid * 16];
        float mx = row[0];
#pragma unroll
        for (int j = 1; j < 16; j++) mx = fmaxf(mx, row[j]);
        float sm = 0.f;
#pragma unroll
        for (int j = 0; j < 16; j++) { float e = __expf(row[j] - mx); row[j] = e; sm += e; }
        float r = 1.f / sm;
#pragma unroll
        for (int j = 0; j < 16; j++) row[j] *= r;
    }
    __syncthreads();

    // AV: thread owns one c4 column and 4 rows -> V loads reused 4x
    if (tid < 192) {
        int c4 = tid % 48;
        int rp = tid / 48;          // 0..3
        int h = c4 / 12;
        const float* vbase = &sq[384 + c4 * 4];
        float4 o[4];
#pragma unroll
        for (int rr = 0; rr < 4; rr++) o[rr] = make_float4(0.f, 0.f, 0.f, 0.f);
#pragma unroll
        for (int jj = 0; jj < 16; jj++) {
            float4 vv = *reinterpret_cast<const float4*>(&vbase[jj * QS]);
#pragma unroll
            for (int rr = 0; rr < 4; rr++) {
                float sv = ss[(h * 16 + rp + rr * 4) * 16 + jj];
                o[rr].x += sv * vv.x; o[rr].y += sv * vv.y;
                o[rr].z += sv * vv.z; o[rr].w += sv * vv.w;
            }
        }
#pragma unroll
        for (int rr = 0; rr < 4; rr++)
            *reinterpret_cast<float4*>(&g_attn[(size_t)smm[rp + rr * 4] * 192 + c4 * 4]) = o[rr];
    }
}

// =====================================================================
// GroupNorm #1 stats (token-major amap)
// =====================================================================
__global__ __launch_bounds__(192)
void k_gn1_stats()
{
    int b = blockIdx.x >> 6;
    int chunk = blockIdx.x & 63;
    int c = threadIdx.x;
    size_t base = ((size_t)(b * 16384 + chunk * 256)) * 192 + c;
    float s = 0.f, q = 0.f;
    for (int r = 0; r < 256; r++) {
        float v = g_amap[base + (size_t)r * 192];
        s += v; q += v * v;
    }
    g_p1s[(b * 192 + c) * 64 + chunk] = s;
    g_p1q[(b * 192 + c) * 64 + chunk] = q;
}

__global__ void k_gn1_final()
{
    int t = threadIdx.x;
    if (t >= 64) return;
    int b = t >> 3, g = t & 7;
    float S = 0.f, Q = 0.f;
    for (int i = 0; i < 24; i++) {
        int cc = b * 192 + g * 24 + i;
        for (int ch = 0; ch < 64; ch++) { S += g_p1s[cc * 64 + ch]; Q += g_p1q[cc * 64 + ch]; }
    }
    const float inv_n = 1.0f / 393216.0f;
    float mu = S * inv_n;
    float var = Q * inv_n - mu * mu;
    g_mu1[t] = mu;
    g_inv1[t] = rsqrtf(var + 1e-5f);
}

// =====================================================================
// GroupNorm #2 over BCHW hraw
// =====================================================================
__global__ __launch_bounds__(256)
void k_gn2_stats()
{
    __shared__ float rs[256], rq[256];
    int grp = blockIdx.x >> 4;
    int part = blockIdx.x & 15;
    int b = grp >> 3, g = grp & 7;
    size_t base = ((size_t)(b * 192 + g * 24) << 14) + (size_t)part * 24576;
    int tid = threadIdx.x;
    float s = 0.f, q = 0.f;
    for (int j = 0; j < 24; j++) {
        float4 v = *reinterpret_cast<const float4*>(&g_hraw[base + (size_t)(tid + 256 * j) * 4]);
        s += v.x + v.y + v.z + v.w;
        q += v.x * v.x + v.y * v.y + v.z * v.z + v.w * v.w;
    }
    rs[tid] = s; rq[tid] = q;
    __syncthreads();
    for (int o = 128; o; o >>= 1) {
        if (tid < o) { rs[tid] += rs[tid + o]; rq[tid] += rq[tid + o]; }
        __syncthreads();
    }
    if (tid == 0) { g_p2s[grp * 16 + part] = rs[0]; g_p2q[grp * 16 + part] = rq[0]; }
}

__global__ void k_gn2_final()
{
    int t = threadIdx.x;
    if (t >= 64) return;
    float S = 0.f, Q = 0.f;
    for (int i = 0; i < 16; i++) { S += g_p2s[t * 16 + i]; Q += g_p2q[t * 16 + i]; }
    const float inv_n = 1.0f / 393216.0f;
    float mu = S * inv_n;
    float var = Q * inv_n - mu * mu;
    g_mu2[t] = mu;
    g_inv2[t] = rsqrtf(var + 1e-5f);
}

__global__ __launch_bounds__(256)
void k_finalize(const float* __restrict__ gg, const float* __restrict__ gb,
                float* __restrict__ out)
{
    size_t idx4 = (size_t)blockIdx.x * 256 + threadIdx.x;
    size_t base = idx4 * 4;
    int bc = (int)(base >> 14);
    int b = bc / 192;
    int c = bc - b * 192;
    int grp = c / 24;
    float mu = g_mu2[b * 8 + grp], inv = g_inv2[b * 8 + grp];
    float sc = gg[c] * inv;
    float bi = gb[c];
    float4 v = *reinterpret_cast<const float4*>(&g_hraw[base]);
    float4 o;
    o.x = (v.x - mu) * sc + bi;
    o.y = (v.y - mu) * sc + bi;
    o.z = (v.z - mu) * sc + bi;
    o.w = (v.w - mu) * sc + bi;
    *reinterpret_cast<float4*>(&out[base]) = o;
}

// =====================================================================
// host launcher
// =====================================================================
extern "C" void kernel_launch(void* const* d_in, const int* in_sizes, int n_in,
                              void* d_out, int out_size)
{
    const float* x       = (const float*)d_in[0];
    const float* h       = (const float*)d_in[1];
    const float* c       = (const float*)d_in[2];
    const float* w_in    = (const float*)d_in[3];
    const float* b_in    = (const float*)d_in[4];
    const float* ln_g    = (const float*)d_in[5];
    const float* ln_b    = (const float*)d_in[6];
    const float* w_qkv   = (const float*)d_in[7];
    const float* b_qkv   = (const float*)d_in[8];
    const float* w_proj  = (const float*)d_in[9];
    const float* b_proj  = (const float*)d_in[10];
    const float* gn_g    = (const float*)d_in[11];
    const float* gn_b    = (const float*)d_in[12];
    const float* w_gates = (const float*)d_in[13];
    const float* b_gates = (const float*)d_in[14];
    float* out = (float*)d_out;

    void *p_proj, *p_qkv, *p_attn, *p_amap, *p_lnmu, *p_lniv, *p_mu1, *p_inv1,
         *p_wperm, *p_bperm;
    cudaGetSymbolAddress(&p_proj,  g_proj);
    cudaGetSymbolAddress(&p_qkv,   g_qkv);
    cudaGetSymbolAddress(&p_attn,  g_attn);
    cudaGetSymbolAddress(&p_amap,  g_amap);
    cudaGetSymbolAddress(&p_lnmu,  g_lnmu);
    cudaGetSymbolAddress(&p_lniv,  g_lniv);
    cudaGetSymbolAddress(&p_mu1,   g_mu1);
    cudaGetSymbolAddress(&p_inv1,  g_inv1);
    cudaGetSymbolAddress(&p_wperm, g_wperm);
    cudaGetSymbolAddress(&p_bperm, g_bperm);

    const int SM_TC  = (2 * 256 + 2 * 64) * 36 * 4;            // 92160
    const int SM_IN  = (2 * 32 * 264 + 2 * 64 * 36) * 4;       // 86016
    cudaFuncSetAttribute(k_tc2<192>,  cudaFuncAttributeMaxDynamicSharedMemorySize, SM_TC);
    cudaFuncSetAttribute(k_tcln<192>, cudaFuncAttributeMaxDynamicSharedMemorySize, SM_TC);
    cudaFuncSetAttribute(k_tcg,       cudaFuncAttributeMaxDynamicSharedMemorySize, SM_TC);
    cudaFuncSetAttribute(k_tc_in,     cudaFuncAttributeMaxDynamicSharedMemorySize, SM_IN);

    // 0) permute gates weights for the fused-LSTM layout
    k_permw<<<768, 192>>>(w_gates, b_gates);
    // 1) in_proj GEMM with fused BCHW gather -> g_proj (raw)
    k_tc_in<<<dim3(3, 512), 256, SM_IN>>>(x, h, w_in, b_in, (float*)p_proj);
    // 2) LayerNorm stats
    k_lnstats<<<16384, 256>>>((float*)p_lnmu, (float*)p_lniv);
    // 3) qkv GEMM with fused LayerNorm -> g_qkv
    k_tcln<192><<<dim3(9, 512), 256, SM_TC>>>((const float*)p_proj, w_qkv, b_qkv,
                                              (float*)p_qkv, 576,
                                              (const float*)p_lnmu, (const float*)p_lniv,
                                              ln_g, ln_b);
    // 4) window attention -> g_attn
    k_attn<<<8192, 256>>>();
    // 5) out_proj GEMM -> g_amap (raw)
    k_tc2<192><<<dim3(3, 512), 256, SM_TC>>>((const float*)p_attn, w_proj, b_proj,
                                             (float*)p_amap, 192);
    // 6) GroupNorm stats over amap
    k_gn1_stats<<<512, 192>>>();
    k_gn1_final<<<1, 64>>>();
    // 7) gates GEMM + fused GroupNorm + fused LSTM -> cnext (d_out) + g_hraw
    k_tcg<<<dim3(12, 512), 256, SM_TC>>>((const float*)p_amap, (const float*)p_wperm,
                                         (const float*)p_bperm,
                                         (const float*)p_mu1, (const float*)p_inv1,
                                         gn_g, gn_b, c, out);
    // 8) GroupNorm(hnext) -> d_out first half
    k_gn2_stats<<<1024, 256>>>();
    k_gn2_final<<<1, 64>>>();
    k_finalize<<<24576, 256>>>(gn_g, gn_b, out);
}

// round 8
// speedup vs baseline: 2.7606x; 1.0713x over previous
#include <cuda_runtime.h>
#include <cstdint>

// ---------------- problem constants ----------------
#define TOK    131072              // B*H*W tokens (raster order)
#define HSZ    25165824            // 8*192*128*128 (one output tensor)

// ---------------- static device scratch ----------------
__device__ float g_proj[(size_t)TOK * 192];   // in_proj out (raw, pre-LN)
__device__ float g_qkv [(size_t)TOK * 576];
__device__ float g_attn[(size_t)TOK * 192];
__device__ float g_amap[(size_t)TOK * 192];   // out_proj out (raw, pre-GN)
__device__ float g_hraw[(size_t)TOK * 192];   // BCHW layout
__device__ float g_wperm[768 * 192];          // permuted gates weight
__device__ float g_bperm[768];
__device__ float g_lns[TOK], g_lnq[TOK];      // LN partial sums (atomic)
__device__ float g_lnmu[TOK], g_lniv[TOK];
__device__ float g_g1s[64], g_g1q[64];        // GN1 sums (atomic)
__device__ float g_mu1[64], g_inv1[64];
__device__ float g_g2s[64], g_g2q[64];        // GN2 sums (atomic)
__device__ float g_mu2[64], g_inv2[64];

// ---------------- PTX helpers ----------------
#define CP_ASYNC16(sm, gp) \
    asm volatile("cp.async.cg.shared.global [%0], [%1], 16;" :: "r"((uint32_t)(sm)), "l"(gp))
#define CP_COMMIT() asm volatile("cp.async.commit_group;" ::: "memory")
#define CP_WAIT(n)  asm volatile("cp.async.wait_group %0;" :: "n"(n) : "memory")

__device__ __forceinline__ uint32_t smem_to_u32(const void* p) {
    uint32_t a;
    asm("{ .reg .u64 t; cvta.to.shared.u64 t, %1; cvt.u32.u64 %0, t; }" : "=r"(a) : "l"(p));
    return a;
}
__device__ __forceinline__ void mma_tf32(float& c0, float& c1, float& c2, float& c3,
                                         uint32_t a0, uint32_t a1, uint32_t a2, uint32_t a3,
                                         uint32_t b0, uint32_t b1) {
    asm volatile("mma.sync.aligned.m16n8k8.row.col.f32.tf32.tf32.f32 "
                 "{%0,%1,%2,%3}, {%4,%5,%6,%7}, {%8,%9}, {%0,%1,%2,%3};"
                 : "+f"(c0), "+f"(c1), "+f"(c2), "+f"(c3)
                 : "r"(a0), "r"(a1), "r"(a2), "r"(a3), "r"(b0), "r"(b1));
}

// =====================================================================
// zero the atomic stat buffers
// =====================================================================
__global__ __launch_bounds__(256)
void k_zero()
{
    int i = blockIdx.x * 256 + threadIdx.x;       // grid 512 -> TOK
    g_lns[i] = 0.f; g_lnq[i] = 0.f;
    if (i < 64) { g_g1s[i] = 0.f; g_g1q[i] = 0.f; g_g2s[i] = 0.f; g_g2q[i] = 0.f; }
}

// =====================================================================
// permute gates weight/bias into LSTM-fragment-friendly order
// =====================================================================
__global__ __launch_bounds__(192)
void k_permw(const float* __restrict__ wg, const float* __restrict__ bg)
{
    int col = blockIdx.x;
    int t = col >> 6, l = col & 63;
    int half = l >> 5, l2 = l & 31, b = l2 >> 4, l3 = l2 & 15;
    int ghi = l3 >> 3, l4 = l3 & 7, q = l4 >> 1, glo = l4 & 1;
    int gate = ghi * 2 + glo;
    int ch = t * 16 + half * 8 + b * 4 + q;
    int orow = gate * 192 + ch;
    g_wperm[col * 192 + threadIdx.x] = wg[orow * 192 + threadIdx.x];
    if (threadIdx.x == 0) g_bperm[col] = bg[orow];
}

// =====================================================================
// in_proj GEMM with fused BCHW gather + fused LN-stat partials.
// CTA 128x64, warp 32x32, kc=32. A^T smem [32][136].
// =====================================================================
__global__ __launch_bounds__(256, 4)
void k_tc_in(const float* __restrict__ X, const float* __restrict__ Hh,
             const float* __restrict__ W, const float* __restrict__ bias,
             float* __restrict__ C)
{
    constexpr int K = 256, NCH = 8;
    constexpr int MST = 136;
    constexpr int AST = 36;
    extern __shared__ float smf[];
    float* Asb[2] = { smf, smf + 32 * MST };
    float* Bsb[2] = { smf + 2 * 32 * MST, smf + 2 * 32 * MST + 64 * AST };

    const int tid  = threadIdx.x;
    const int lane = tid & 31;
    const int warp = tid >> 5;
    const int wm = warp & 3, wn = warp >> 2;
    const int m0 = blockIdx.y * 128;
    const int n0 = blockIdx.x * 64;
    const int b  = m0 >> 14;
    const int p0 = m0 & 16383;

    const uint32_t sA[2] = { smem_to_u32(Asb[0]), smem_to_u32(Asb[1]) };
    const uint32_t sB[2] = { smem_to_u32(Bsb[0]), smem_to_u32(Bsb[1]) };

    float acc[2][4][4];
#pragma unroll
    for (int i = 0; i < 2; i++)
#pragma unroll
        for (int j = 0; j < 4; j++)
#pragma unroll
            for (int q = 0; q < 4; q++) acc[i][j][q] = 0.f;

    auto prefetch = [&](int kt) {
        int buf = kt & 1;
#pragma unroll
        for (int j = 0; j < 4; j++) {
            int idx = tid + 256 * j;
            int k = idx >> 5, ms4 = idx & 31;
            int kg = kt * 32 + k;
            const float* src = (kg < 64)
                ? X  + (((size_t)(b * 64  + kg))        << 14) + p0 + ms4 * 4
                : Hh + (((size_t)(b * 192 + (kg - 64))) << 14) + p0 + ms4 * 4;
            CP_ASYNC16(sA[buf] + (uint32_t)(k * MST + ms4 * 4) * 4, src);
        }
        const float* bg = W + (size_t)n0 * K + kt * 32;
#pragma unroll
        for (int j = 0; j < 2; j++) {
            int idx = tid + 256 * j;
            int row = idx >> 3, off = idx & 7;
            CP_ASYNC16(sB[buf] + (uint32_t)(row * AST + off * 4) * 4,
                       bg + (size_t)row * K + off * 4);
        }
        CP_COMMIT();
    };

    prefetch(0);

    for (int kt = 0; kt < NCH; kt++) {
        if (kt + 1 < NCH) { prefetch(kt + 1); CP_WAIT(1); }
        else              { CP_WAIT(0); }
        __syncthreads();
        const float* as = Asb[kt & 1];
        const float* bs = Bsb[kt & 1];
#pragma unroll
        for (int ks = 0; ks < 4; ks++) {
            const int cc = ks * 8 + (lane & 3);
            uint32_t af[2][4];
#pragma unroll
            for (int mf = 0; mf < 2; mf++) {
                int r = wm * 32 + mf * 16 + (lane >> 2);
                af[mf][0] = __float_as_uint(as[cc * MST + r]);
                af[mf][1] = __float_as_uint(as[cc * MST + r + 8]);
                af[mf][2] = __float_as_uint(as[(cc + 4) * MST + r]);
                af[mf][3] = __float_as_uint(as[(cc + 4) * MST + r + 8]);
            }
            uint32_t bf[4][2];
#pragma unroll
            for (int nf = 0; nf < 4; nf++) {
                int rb = wn * 32 + nf * 8 + (lane >> 2);
                bf[nf][0] = __float_as_uint(bs[rb * AST + cc]);
                bf[nf][1] = __float_as_uint(bs[rb * AST + cc + 4]);
            }
#pragma unroll
            for (int mf = 0; mf < 2; mf++)
#pragma unroll
                for (int nf = 0; nf < 4; nf++)
                    mma_tf32(acc[mf][nf][0], acc[mf][nf][1], acc[mf][nf][2], acc[mf][nf][3],
                             af[mf][0], af[mf][1], af[mf][2], af[mf][3],
                             bf[nf][0], bf[nf][1]);
        }
        __syncthreads();
    }

    // epilogue: store + LN partial stats (per-row sums over this warp's 32 cols)
    float rs[2][2] = {{0.f,0.f},{0.f,0.f}};
    float rq[2][2] = {{0.f,0.f},{0.f,0.f}};
#pragma unroll
    for (int mf = 0; mf < 2; mf++) {
        int row = m0 + wm * 32 + mf * 16 + (lane >> 2);
#pragma unroll
        for (int nf = 0; nf < 4; nf++) {
            int col = n0 + wn * 32 + nf * 8 + 2 * (lane & 3);
            float bx = bias[col], by = bias[col + 1];
            float2 o0 = make_float2(acc[mf][nf][0] + bx, acc[mf][nf][1] + by);
            float2 o1 = make_float2(acc[mf][nf][2] + bx, acc[mf][nf][3] + by);
            *reinterpret_cast<float2*>(&C[(size_t)row * 192 + col]) = o0;
            *reinterpret_cast<float2*>(&C[(size_t)(row + 8) * 192 + col]) = o1;
            rs[mf][0] += o0.x + o0.y;  rq[mf][0] += o0.x * o0.x + o0.y * o0.y;
            rs[mf][1] += o1.x + o1.y;  rq[mf][1] += o1.x * o1.x + o1.y * o1.y;
        }
    }
#pragma unroll
    for (int mf = 0; mf < 2; mf++)
#pragma unroll
        for (int half = 0; half < 2; half++) {
            float s = rs[mf][half], qq = rq[mf][half];
            s  += __shfl_xor_sync(0xffffffffu, s, 1);
            s  += __shfl_xor_sync(0xffffffffu, s, 2);
            qq += __shfl_xor_sync(0xffffffffu, qq, 1);
            qq += __shfl_xor_sync(0xffffffffu, qq, 2);
            if ((lane & 3) == 0) {
                int row = m0 + wm * 32 + mf * 16 + (lane >> 2) + 8 * half;
                atomicAdd(&g_lns[row], s);
                atomicAdd(&g_lnq[row], qq);
            }
        }
}

// =====================================================================
// LN finalize: per-token mu/iv from atomic sums
// =====================================================================
__global__ __launch_bounds__(256)
void k_lnfin()
{
    int i = blockIdx.x * 256 + threadIdx.x;
    float s = g_lns[i], q = g_lnq[i];
    float mu = s * (1.0f / 192.0f);
    float var = q * (1.0f / 192.0f) - mu * mu;
    g_lnmu[i] = mu;
    g_lniv[i] = rsqrtf(var + 1e-5f);
}

// =====================================================================
// qkv GEMM with fused LayerNorm on A. CTA 128x64, warp 32x32, kc=32.
// mu/iv staged in smem.
// =====================================================================
__global__ __launch_bounds__(256, 4)
void k_tcln(const float* __restrict__ A, const float* __restrict__ W,
            const float* __restrict__ bias, float* __restrict__ C, int Ntot,
            const float* __restrict__ mu_arr, const float* __restrict__ iv_arr,
            const float* __restrict__ cg, const float* __restrict__ cb)
{
    constexpr int K = 192, NCH = 6, AST = 36;
    extern __shared__ float smf[];
    float* Asb[2] = { smf, smf + 128 * AST };
    float* Bsb[2] = { smf + 2 * 128 * AST, smf + 2 * 128 * AST + 64 * AST };
    float* smu = smf + 2 * 128 * AST + 2 * 64 * AST;
    float* siv = smu + 128;

    const int tid  = threadIdx.x;
    const int lane = tid & 31;
    const int warp = tid >> 5;
    const int wm = warp & 3, wn = warp >> 2;
    const int m0 = blockIdx.y * 128;
    const int n0 = blockIdx.x * 64;
    const int arow = tid >> 3, aoff = tid & 7;

    const uint32_t sA[2] = { smem_to_u32(Asb[0]), smem_to_u32(Asb[1]) };
    const uint32_t sB[2] = { smem_to_u32(Bsb[0]), smem_to_u32(Bsb[1]) };

    if (tid < 128) { smu[tid] = mu_arr[m0 + tid]; siv[tid] = iv_arr[m0 + tid]; }

    float acc[2][4][4];
#pragma unroll
    for (int i = 0; i < 2; i++)
#pragma unroll
        for (int j = 0; j < 4; j++)
#pragma unroll
            for (int q = 0; q < 4; q++) acc[i][j][q] = 0.f;

    auto prefetch = [&](int kt) {
        int buf = kt & 1;
        const float* ag = A + (size_t)m0 * K + kt * 32;
        const float* bg = W + (size_t)n0 * K + kt * 32;
#pragma unroll
        for (int j = 0; j < 4; j++) {
            int idx = tid + 256 * j;
            int row = idx >> 3, off = idx & 7;
            CP_ASYNC16(sA[buf] + (uint32_t)(row * AST + off * 4) * 4,
                       ag + (size_t)row * K + off * 4);
        }
#pragma unroll
        for (int j = 0; j < 2; j++) {
            int idx = tid + 256 * j;
            int row = idx >> 3, off = idx & 7;
            CP_ASYNC16(sB[buf] + (uint32_t)(row * AST + off * 4) * 4,
                       bg + (size_t)row * K + off * 4);
        }
        CP_COMMIT();
    };

    prefetch(0);

    for (int kt = 0; kt < NCH; kt++) {
        if (kt + 1 < NCH) { prefetch(kt + 1); CP_WAIT(1); }
        else              { CP_WAIT(0); }
        __syncthreads();
        {   // in-place LayerNorm on A chunk
            float* as = Asb[kt & 1];
            const int k = kt * 32 + aoff * 4;
            float4 g4 = *reinterpret_cast<const float4*>(&cg[k]);
            float4 b4 = *reinterpret_cast<const float4*>(&cb[k]);
#pragma unroll
            for (int j = 0; j < 4; j++) {
                int row = arow + 32 * j;
                float mu = smu[row], iv = siv[row];
                float4 v = *reinterpret_cast<float4*>(&as[row * AST + aoff * 4]);
                v.x = (v.x - mu) * iv * g4.x + b4.x;
                v.y = (v.y - mu) * iv * g4.y + b4.y;
                v.z = (v.z - mu) * iv * g4.z + b4.z;
                v.w = (v.w - mu) * iv * g4.w + b4.w;
                *reinterpret_cast<float4*>(&as[row * AST + aoff * 4]) = v;
            }
        }
        __syncthreads();
        const float* as = Asb[kt & 1];
        const float* bs = Bsb[kt & 1];
#pragma unroll
        for (int ks = 0; ks < 4; ks++) {
            const int cc = ks * 8 + (lane & 3);
            uint32_t af[2][4];
#pragma unroll
            for (int mf = 0; mf < 2; mf++) {
                int r = wm * 32 + mf * 16 + (lane >> 2);
                af[mf][0] = __float_as_uint(as[r * AST + cc]);
                af[mf][1] = __float_as_uint(as[(r + 8) * AST + cc]);
                af[mf][2] = __float_as_uint(as[r * AST + cc + 4]);
                af[mf][3] = __float_as_uint(as[(r + 8) * AST + cc + 4]);
            }
            uint32_t bf[4][2];
#pragma unroll
            for (int nf = 0; nf < 4; nf++) {
                int rb = wn * 32 + nf * 8 + (lane >> 2);
                bf[nf][0] = __float_as_uint(bs[rb * AST + cc]);
                bf[nf][1] = __float_as_uint(bs[rb * AST + cc + 4]);
            }
#pragma unroll
            for (int mf = 0; mf < 2; mf++)
#pragma unroll
                for (int nf = 0; nf < 4; nf++)
                    mma_tf32(acc[mf][nf][0], acc[mf][nf][1], acc[mf][nf][2], acc[mf][nf][3],
                             af[mf][0], af[mf][1], af[mf][2], af[mf][3],
                             bf[nf][0], bf[nf][1]);
        }
        __syncthreads();
    }

#pragma unroll
    for (int mf = 0; mf < 2; mf++) {
        int row = m0 + wm * 32 + mf * 16 + (lane >> 2);
#pragma unroll
        for (int nf = 0; nf < 4; nf++) {
            int col = n0 + wn * 32 + nf * 8 + 2 * (lane & 3);
            float bx = bias[col], by = bias[col + 1];
            float2 o0 = make_float2(acc[mf][nf][0] + bx, acc[mf][nf][1] + by);
            float2 o1 = make_float2(acc[mf][nf][2] + bx, acc[mf][nf][3] + by);
            *reinterpret_cast<float2*>(&C[(size_t)row * Ntot + col]) = o0;
            *reinterpret_cast<float2*>(&C[(size_t)(row + 8) * Ntot + col]) = o1;
        }
    }
}

// =====================================================================
// out_proj GEMM + fused GN1 partial stats. CTA 128x64, warp 32x32.
// =====================================================================
__global__ __launch_bounds__(256, 4)
void k_tc2(const float* __restrict__ A, const float* __restrict__ W,
           const float* __restrict__ bias, float* __restrict__ C)
{
    constexpr int K = 192, NCH = 6, AST = 36;
    extern __shared__ float smf[];
    float* Asb[2] = { smf, smf + 128 * AST };
    float* Bsb[2] = { smf + 2 * 128 * AST, smf + 2 * 128 * AST + 64 * AST };

    const int tid  = threadIdx.x;
    const int lane = tid & 31;
    const int warp = tid >> 5;
    const int wm = warp & 3, wn = warp >> 2;
    const int m0 = blockIdx.y * 128;
    const int n0 = blockIdx.x * 64;

    const uint32_t sA[2] = { smem_to_u32(Asb[0]), smem_to_u32(Asb[1]) };
    const uint32_t sB[2] = { smem_to_u32(Bsb[0]), smem_to_u32(Bsb[1]) };

    float acc[2][4][4];
#pragma unroll
    for (int i = 0; i < 2; i++)
#pragma unroll
        for (int j = 0; j < 4; j++)
#pragma unroll
            for (int q = 0; q < 4; q++) acc[i][j][q] = 0.f;

    auto prefetch = [&](int kt) {
        int buf = kt & 1;
        const float* ag = A + (size_t)m0 * K + kt * 32;
        const float* bg = W + (size_t)n0 * K + kt * 32;
#pragma unroll
        for (int j = 0; j < 4; j++) {
            int idx = tid + 256 * j;
            int row = idx >> 3, off = idx & 7;
            CP_ASYNC16(sA[buf] + (uint32_t)(row * AST + off * 4) * 4,
                       ag + (size_t)row * K + off * 4);
        }
#pragma unroll
        for (int j = 0; j < 2; j++) {
            int idx = tid + 256 * j;
            int row = idx >> 3, off = idx & 7;
            CP_ASYNC16(sB[buf] + (uint32_t)(row * AST + off * 4) * 4,
                       bg + (size_t)row * K + off * 4);
        }
        CP_COMMIT();
    };

    prefetch(0);

    for (int kt = 0; kt < NCH; kt++) {
        if (kt + 1 < NCH) { prefetch(kt + 1); CP_WAIT(1); }
        else              { CP_WAIT(0); }
        __syncthreads();
        const float* as = Asb[kt & 1];
        const float* bs = Bsb[kt & 1];
#pragma unroll
        for (int ks = 0; ks < 4; ks++) {
            const int cc = ks * 8 + (lane & 3);
            uint32_t af[2][4];
#pragma unroll
            for (int mf = 0; mf < 2; mf++) {
                int r = wm * 32 + mf * 16 + (lane >> 2);
                af[mf][0] = __float_as_uint(as[r * AST + cc]);
                af[mf][1] = __float_as_uint(as[(r + 8) * AST + cc]);
                af[mf][2] = __float_as_uint(as[r * AST + cc + 4]);
                af[mf][3] = __float_as_uint(as[(r + 8) * AST + cc + 4]);
            }
            uint32_t bf[4][2];
#pragma unroll
            for (int nf = 0; nf < 4; nf++) {
                int rb = wn * 32 + nf * 8 + (lane >> 2);
                bf[nf][0] = __float_as_uint(bs[rb * AST + cc]);
                bf[nf][1] = __float_as_uint(bs[rb * AST + cc + 4]);
            }
#pragma unroll
            for (int mf = 0; mf < 2; mf++)
#pragma unroll
                for (int nf = 0; nf < 4; nf++)
                    mma_tf32(acc[mf][nf][0], acc[mf][nf][1], acc[mf][nf][2], acc[mf][nf][3],
                             af[mf][0], af[mf][1], af[mf][2], af[mf][3],
                             bf[nf][0], bf[nf][1]);
        }
        __syncthreads();
    }

    // epilogue: store + GN1 partials (per-warp nf-block is group-uniform)
    const int bb = m0 >> 14;
#pragma unroll
    for (int nf = 0; nf < 4; nf++) {
        float s = 0.f, qq = 0.f;
        int col = n0 + wn * 32 + nf * 8 + 2 * (lane & 3);
        float bx = bias[col], by = bias[col + 1];
#pragma unroll
        for (int mf = 0; mf < 2; mf++) {
            int row = m0 + wm * 32 + mf * 16 + (lane >> 2);
            float2 o0 = make_float2(acc[mf][nf][0] + bx, acc[mf][nf][1] + by);
            float2 o1 = make_float2(acc[mf][nf][2] + bx, acc[mf][nf][3] + by);
            *reinterpret_cast<float2*>(&C[(size_t)row * 192 + col]) = o0;
            *reinterpret_cast<float2*>(&C[(size_t)(row + 8) * 192 + col]) = o1;
            s  += o0.x + o0.y + o1.x + o1.y;
            qq += o0.x * o0.x + o0.y * o0.y + o1.x * o1.x + o1.y * o1.y;
        }
#pragma unroll
        for (int o = 16; o; o >>= 1) {
            s  += __shfl_xor_sync(0xffffffffu, s, o);
            qq += __shfl_xor_sync(0xffffffffu, qq, o);
        }
        if (lane == 0) {
            int g = (n0 + wn * 32 + nf * 8) / 24;
            atomicAdd(&g_g1s[bb * 8 + g], s);
            atomicAdd(&g_g1q[bb * 8 + g], qq);
        }
    }
}

__global__ void k_gn1_final()
{
    int t = threadIdx.x;
    if (t >= 64) return;
    const float inv_n = 1.0f / 393216.0f;
    float mu = g_g1s[t] * inv_n;
    float var = g_g1q[t] * inv_n - mu * mu;
    g_mu1[t] = mu;
    g_inv1[t] = rsqrtf(var + 1e-5f);
}

// =====================================================================
// gates GEMM (permuted W) + fused GroupNorm on A + LSTM epilogue +
// fused GN2 partial stats. CTA 128x64, warp 32x32.
// =====================================================================
__global__ __launch_bounds__(256, 4)
void k_tcg(const float* __restrict__ A, const float* __restrict__ W,
           const float* __restrict__ bias,
           const float* __restrict__ mu_arr, const float* __restrict__ iv_arr,
           const float* __restrict__ cg, const float* __restrict__ cb,
           const float* __restrict__ Cin, float* __restrict__ out)
{
    constexpr int K = 192, NCH = 6, AST = 36;
    extern __shared__ float smf[];
    float* Asb[2] = { smf, smf + 128 * AST };
    float* Bsb[2] = { smf + 2 * 128 * AST, smf + 2 * 128 * AST + 64 * AST };

    const int tid  = threadIdx.x;
    const int lane = tid & 31;
    const int warp = tid >> 5;
    const int wm = warp & 3, wn = warp >> 2;
    const int m0 = blockIdx.y * 128;
    const int n0 = blockIdx.x * 64;
    const int arow = tid >> 3, aoff = tid & 7;
    const int b8 = (m0 >> 14) << 3;

    const uint32_t sA[2] = { smem_to_u32(Asb[0]), smem_to_u32(Asb[1]) };
    const uint32_t sB[2] = { smem_to_u32(Bsb[0]), smem_to_u32(Bsb[1]) };

    float acc[2][4][4];
#pragma unroll
    for (int i = 0; i < 2; i++)
#pragma unroll
        for (int j = 0; j < 4; j++)
#pragma unroll
            for (int q = 0; q < 4; q++) acc[i][j][q] = 0.f;

    auto prefetch = [&](int kt) {
        int buf = kt & 1;
        const float* ag = A + (size_t)m0 * K + kt * 32;
        const float* bg = W + (size_t)n0 * K + kt * 32;
#pragma unroll
        for (int j = 0; j < 4; j++) {
            int idx = tid + 256 * j;
            int row = idx >> 3, off = idx & 7;
            CP_ASYNC16(sA[buf] + (uint32_t)(row * AST + off * 4) * 4,
                       ag + (size_t)row * K + off * 4);
        }
#pragma unroll
        for (int j = 0; j < 2; j++) {
            int idx = tid + 256 * j;
            int row = idx >> 3, off = idx & 7;
            CP_ASYNC16(sB[buf] + (uint32_t)(row * AST + off * 4) * 4,
                       bg + (size_t)row * K + off * 4);
        }
        CP_COMMIT();
    };

    prefetch(0);

    for (int kt = 0; kt < NCH; kt++) {
        if (kt + 1 < NCH) { prefetch(kt + 1); CP_WAIT(1); }
        else              { CP_WAIT(0); }
        __syncthreads();
        {   // in-place GroupNorm on A chunk
            float* as = Asb[kt & 1];
            const int k = kt * 32 + aoff * 4;
            float4 g4 = *reinterpret_cast<const float4*>(&cg[k]);
            float4 b4 = *reinterpret_cast<const float4*>(&cb[k]);
            int grp = k / 24;
            float mu = mu_arr[b8 + grp];
            float iv = iv_arr[b8 + grp];
#pragma unroll
            for (int j = 0; j < 4; j++) {
                int row = arow + 32 * j;
                float4 v = *reinterpret_cast<float4*>(&as[row * AST + aoff * 4]);
                v.x = (v.x - mu) * iv * g4.x + b4.x;
                v.y = (v.y - mu) * iv * g4.y + b4.y;
                v.z = (v.z - mu) * iv * g4.z + b4.z;
                v.w = (v.w - mu) * iv * g4.w + b4.w;
                *reinterpret_cast<float4*>(&as[row * AST + aoff * 4]) = v;
            }
        }
        __syncthreads();
        const float* as = Asb[kt & 1];
        const float* bs = Bsb[kt & 1];
#pragma unroll
        for (int ks = 0; ks < 4; ks++) {
            const int cc = ks * 8 + (lane & 3);
            uint32_t af[2][4];
#pragma unroll
            for (int mf = 0; mf < 2; mf++) {
                int r = wm * 32 + mf * 16 + (lane >> 2);
                af[mf][0] = __float_as_uint(as[r * AST + cc]);
                af[mf][1] = __float_as_uint(as[(r + 8) * AST + cc]);
                af[mf][2] = __float_as_uint(as[r * AST + cc + 4]);
                af[mf][3] = __float_as_uint(as[(r + 8) * AST + cc + 4]);
            }
            uint32_t bf[4][2];
#pragma unroll
            for (int nf = 0; nf < 4; nf++) {
                int rb = wn * 32 + nf * 8 + (lane >> 2);
                bf[nf][0] = __float_as_uint(bs[rb * AST + cc]);
                bf[nf][1] = __float_as_uint(bs[rb * AST + cc + 4]);
            }
#pragma unroll
            for (int mf = 0; mf < 2; mf++)
#pragma unroll
                for (int nf = 0; nf < 4; nf++)
                    mma_tf32(acc[mf][nf][0], acc[mf][nf][1], acc[mf][nf][2], acc[mf][nf][3],
                             af[mf][0], af[mf][1], af[mf][2], af[mf][3],
                             bf[nf][0], bf[nf][1]);
        }
        __syncthreads();
    }

    // ---- LSTM epilogue + GN2 partials ----
    const int q = lane & 3;
    const int t = blockIdx.x;
    const int chA = t * 16 + wn * 8 + q;
    const int chB = chA + 4;
    const int colb = n0 + wn * 32 + 2 * q;
    float bIA = bias[colb + 0],  bFA = bias[colb + 1];
    float bOA = bias[colb + 8],  bGA = bias[colb + 9];
    float bIB = bias[colb + 16], bFB = bias[colb + 17];
    float bOB = bias[colb + 24], bGB = bias[colb + 25];

    const int bt = m0 >> 14;
    const size_t baseA = ((size_t)(bt * 192 + chA)) << 14;
    const size_t baseB = ((size_t)(bt * 192 + chB)) << 14;

    float sA_ = 0.f, qA_ = 0.f, sB_ = 0.f, qB_ = 0.f;
#pragma unroll
    for (int mf = 0; mf < 2; mf++) {
        int p = (m0 + wm * 32 + mf * 16 + (lane >> 2)) & 16383;
#pragma unroll
        for (int half = 0; half < 2; half++) {
            int pp = p + half * 8;
            int a0 = half * 2;
            {
                float gi = acc[mf][0][a0]     + bIA;
                float gf = acc[mf][0][a0 + 1] + bFA;
                float go = acc[mf][1][a0]     + bOA;
                float gg = acc[mf][1][a0 + 1] + bGA;
                float i_ = 1.f / (1.f + __expf(-gi));
                float f_ = 1.f / (1.f + __expf(-gf));
                float o_ = 1.f / (1.f + __expf(-go));
                float g_ = tanhf(gg);
                size_t addr = baseA + pp;
                float cn = f_ * Cin[addr] + i_ * g_;
                out[(size_t)HSZ + addr] = cn;
                float hv = o_ * tanhf(cn);
                g_hraw[addr] = hv;
                sA_ += hv; qA_ += hv * hv;
            }
            {
                float gi = acc[mf][2][a0]     + bIB;
                float gf = acc[mf][2][a0 + 1] + bFB;
                float go = acc[mf][3][a0]     + bOB;
                float gg = acc[mf][3][a0 + 1] + bGB;
                float i_ = 1.f / (1.f + __expf(-gi));
                float f_ = 1.f / (1.f + __expf(-gf));
                float o_ = 1.f / (1.f + __expf(-go));
                float g_ = tanhf(gg);
                size_t addr = baseB + pp;
                float cn = f_ * Cin[addr] + i_ * g_;
                out[(size_t)HSZ + addr] = cn;
                float hv = o_ * tanhf(cn);
                g_hraw[addr] = hv;
                sB_ += hv; qB_ += hv * hv;
            }
        }
    }
#pragma unroll
    for (int o = 16; o; o >>= 1) {
        sA_ += __shfl_xor_sync(0xffffffffu, sA_, o);
        qA_ += __shfl_xor_sync(0xffffffffu, qA_, o);
        sB_ += __shfl_xor_sync(0xffffffffu, sB_, o);
        qB_ += __shfl_xor_sync(0xffffffffu, qB_, o);
    }
    if (lane == 0) {
        int gA = (t * 16 + wn * 8) / 24;
        int gB = (t * 16 + wn * 8 + 4) / 24;
        atomicAdd(&g_g2s[bt * 8 + gA], sA_);
        atomicAdd(&g_g2q[bt * 8 + gA], qA_);
        atomicAdd(&g_g2s[bt * 8 + gB], sB_);
        atomicAdd(&g_g2q[bt * 8 + gB], qB_);
    }
}

__global__ void k_gn2_final()
{
    int t = threadIdx.x;
    if (t >= 64) return;
    const float inv_n = 1.0f / 393216.0f;
    float mu = g_g2s[t] * inv_n;
    float var = g_g2q[t] * inv_n - mu * mu;
    g_mu2[t] = mu;
    g_inv2[t] = rsqrtf(var + 1e-5f);
}

// =====================================================================
// Window attention — unchanged from round 7
// =====================================================================
#define QS 580
__global__ __launch_bounds__(256, 4)
void k_attn()
{
    __shared__ float sq[16 * QS];
    __shared__ float ss[4 * 16 * 16];
    __shared__ int smm[16];

    int w = blockIdx.x;
    int tid = threadIdx.x;
    if (tid < 16) {
        int b = w >> 10, wi = w & 1023, wy = wi >> 5, wx = wi & 31;
        int ty = tid >> 2, tx = tid & 3;
        smm[tid] = (b << 14) + ((wy * 4 + ty) << 7) + (wx * 4 + tx);
    }
    __syncthreads();

#pragma unroll
    for (int j = 0; j < 9; j++) {
        int i = tid + 256 * j;
        int t = i / 144, c4 = i - t * 144;
        float4 v = *reinterpret_cast<const float4*>(&g_qkv[(size_t)smm[t] * 576 + c4 * 4]);
        *reinterpret_cast<float4*>(&sq[t * QS + c4 * 4]) = v;
    }
    __syncthreads();

    {
        int h = tid >> 6, r = (tid >> 2) & 15, c0 = (tid & 3) * 4;
        const float4* qrow = reinterpret_cast<const float4*>(&sq[r * QS + h * 48]);
        float d[4] = {0.f, 0.f, 0.f, 0.f};
#pragma unroll
        for (int ch = 0; ch < 2; ch++) {
            float4 qv[6];
#pragma unroll
            for (int k = 0; k < 6; k++) qv[k] = qrow[ch * 6 + k];
#pragma unroll
            for (int cc = 0; cc < 4; cc++) {
                const float4* krow = reinterpret_cast<const float4*>(
                    &sq[(c0 + cc) * QS + 192 + h * 48]);
#pragma unroll
                for (int k = 0; k < 6; k++) {
                    float4 kv = krow[ch * 6 + k];
                    d[cc] += qv[k].x * kv.x + qv[k].y * kv.y + qv[k].z * kv.z + qv[k].w * kv.w;
                }
            }
        }
#pragma unroll
        for (int cc = 0; cc < 4; cc++)
            ss[(h * 16 + r) * 16 + c0 + cc] = d[cc] * 0.14433756729740643f;
    }
    __syncthreads();

    if (tid < 64) {
        float* row = &ss[tid * 16];
        float mx = row[0];
#pragma unroll
        for (int j = 1; j < 16; j++) mx = fmaxf(mx, row[j]);
        float sm = 0.f;
#pragma unroll
        for (int j = 0; j < 16; j++) { float e = __expf(row[j] - mx); row[j] = e; sm += e; }
        float r = 1.f / sm;
#pragma unroll
        for (int j = 0; j < 16; j++) row[j] *= r;
    }
    __syncthreads();

    if (tid < 192) {
        int c4 = tid % 48;
        int rp = tid / 48;
        int h = c4 / 12;
        const float* vbase = &sq[384 + c4 * 4];
        float4 o[4];
#pragma unroll
        for (int rr = 0; rr < 4; rr++) o[rr] = make_float4(0.f, 0.f, 0.f, 0.f);
#pragma unroll
        for (int jj = 0; jj < 16; jj++) {
            float4 vv = *reinterpret_cast<const float4*>(&vbase[jj * QS]);
#pragma unroll
            for (int rr = 0; rr < 4; rr++) {
                float sv = ss[(h * 16 + rp + rr * 4) * 16 + jj];
                o[rr].x += sv * vv.x; o[rr].y += sv * vv.y;
                o[rr].z += sv * vv.z; o[rr].w += sv * vv.w;
            }
        }
#pragma unroll
        for (int rr = 0; rr < 4; rr++)
            *reinterpret_cast<float4*>(&g_attn[(size_t)smm[rp + rr * 4] * 192 + c4 * 4]) = o[rr];
    }
}

// =====================================================================
// final GN apply on hraw -> hnext (d_out first half)
// =====================================================================
__global__ __launch_bounds__(256)
void k_finalize(const float* __restrict__ gg, const float* __restrict__ gb,
                float* __restrict__ out)
{
    size_t idx4 = (size_t)blockIdx.x * 256 + threadIdx.x;
    size_t base = idx4 * 4;
    int bc = (int)(base >> 14);
    int b = bc / 192;
    int c = bc - b * 192;
    int grp = c / 24;
    float mu = g_mu2[b * 8 + grp], inv = g_inv2[b * 8 + grp];
    float sc = gg[c] * inv;
    float bi = gb[c];
    float4 v = *reinterpret_cast<const float4*>(&g_hraw[base]);
    float4 o;
    o.x = (v.x - mu) * sc + bi;
    o.y = (v.y - mu) * sc + bi;
    o.z = (v.z - mu) * sc + bi;
    o.w = (v.w - mu) * sc + bi;
    *reinterpret_cast<float4*>(&out[base]) = o;
}

// =====================================================================
// host launcher
// =====================================================================
extern "C" void kernel_launch(void* const* d_in, const int* in_sizes, int n_in,
                              void* d_out, int out_size)
{
    const float* x       = (const float*)d_in[0];
    const float* h       = (const float*)d_in[1];
    const float* c       = (const float*)d_in[2];
    const float* w_in    = (const float*)d_in[3];
    const float* b_in    = (const float*)d_in[4];
    const float* ln_g    = (const float*)d_in[5];
    const float* ln_b    = (const float*)d_in[6];
    const float* w_qkv   = (const float*)d_in[7];
    const float* b_qkv   = (const float*)d_in[8];
    const float* w_proj  = (const float*)d_in[9];
    const float* b_proj  = (const float*)d_in[10];
    const float* gn_g    = (const float*)d_in[11];
    const float* gn_b    = (const float*)d_in[12];
    const float* w_gates = (const float*)d_in[13];
    const float* b_gates = (const float*)d_in[14];
    float* out = (float*)d_out;

    void *p_proj, *p_qkv, *p_attn, *p_amap, *p_lnmu, *p_lniv, *p_mu1, *p_inv1,
         *p_wperm, *p_bperm;
    cudaGetSymbolAddress(&p_proj,  g_proj);
    cudaGetSymbolAddress(&p_qkv,   g_qkv);
    cudaGetSymbolAddress(&p_attn,  g_attn);
    cudaGetSymbolAddress(&p_amap,  g_amap);
    cudaGetSymbolAddress(&p_lnmu,  g_lnmu);
    cudaGetSymbolAddress(&p_lniv,  g_lniv);
    cudaGetSymbolAddress(&p_mu1,   g_mu1);
    cudaGetSymbolAddress(&p_inv1,  g_inv1);
    cudaGetSymbolAddress(&p_wperm, g_wperm);
    cudaGetSymbolAddress(&p_bperm, g_bperm);

    const int SM_TC = (2 * 128 + 2 * 64) * 36 * 4;                 // 55296
    const int SM_LN = SM_TC + 256 * 4;                             // 56320
    const int SM_IN = (2 * 32 * 136 + 2 * 64 * 36) * 4;            // 53248
    cudaFuncSetAttribute(k_tcln, cudaFuncAttributeMaxDynamicSharedMemorySize, SM_LN);
    cudaFuncSetAttribute(k_tc2,  cudaFuncAttributeMaxDynamicSharedMemorySize, SM_TC);
    cudaFuncSetAttribute(k_tcg,  cudaFuncAttributeMaxDynamicSharedMemorySize, SM_TC);
    cudaFuncSetAttribute(k_tc_in, cudaFuncAttributeMaxDynamicSharedMemorySize, SM_IN);

    // 0) zero stat accumulators + permute gates weights
    k_zero<<<512, 256>>>();
    k_permw<<<768, 192>>>(w_gates, b_gates);
    // 1) in_proj GEMM (gather) + LN partial stats -> g_proj, g_lns/g_lnq
    k_tc_in<<<dim3(3, 1024), 256, SM_IN>>>(x, h, w_in, b_in, (float*)p_proj);
    // 2) LN finalize
    k_lnfin<<<512, 256>>>();
    // 3) qkv GEMM with fused LayerNorm -> g_qkv
    k_tcln<<<dim3(9, 1024), 256, SM_LN>>>((const float*)p_proj, w_qkv, b_qkv,
                                          (float*)p_qkv, 576,
                                          (const float*)p_lnmu, (const float*)p_lniv,
                                          ln_g, ln_b);
    // 4) window attention -> g_attn
    k_attn<<<8192, 256>>>();
    // 5) out_proj GEMM + GN1 partial stats -> g_amap
    k_tc2<<<dim3(3, 1024), 256, SM_TC>>>((const float*)p_attn, w_proj, b_proj,
                                         (float*)p_amap);
    // 6) GN1 finalize
    k_gn1_final<<<1, 64>>>();
    // 7) gates GEMM + GN on A + LSTM + GN2 partials -> cnext (d_out) + g_hraw
    k_tcg<<<dim3(12, 1024), 256, SM_TC>>>((const float*)p_amap, (const float*)p_wperm,
                                          (const float*)p_bperm,
                                          (const float*)p_mu1, (const float*)p_inv1,
                                          gn_g, gn_b, c, out);
    // 8) GN2 finalize + apply -> d_out first half
    k_gn2_final<<<1, 64>>>();
    k_finalize<<<24576, 256>>>(gn_g, gn_b, out);
}

// round 9
// speedup vs baseline: 3.0563x; 1.1071x over previous
#include <cuda_runtime.h>
#include <cstdint>

// ---------------- problem constants ----------------
#define TOK    131072              // B*H*W tokens (raster order)
#define HSZ    25165824            // 8*192*128*128 (one output tensor)

// ---------------- static device scratch ----------------
__device__ float g_proj[(size_t)TOK * 192];   // in_proj out (raw, pre-LN)
__device__ float g_qkv [(size_t)TOK * 576];
__device__ float g_attn[(size_t)TOK * 192];
__device__ float g_amap[(size_t)TOK * 192];   // out_proj out (raw, pre-GN)
__device__ float g_hraw[(size_t)TOK * 192];   // BCHW layout
__device__ float g_wperm[768 * 192];          // permuted gates weight
__device__ float g_bperm[768];
__device__ float g_lns[TOK], g_lnq[TOK];      // LN sums (atomic)
__device__ float g_g1s[64], g_g1q[64];        // GN1 sums (atomic)
__device__ float g_g2s[64], g_g2q[64];        // GN2 sums (atomic)

// ---------------- PTX helpers ----------------
#define CP_ASYNC16(sm, gp) \
    asm volatile("cp.async.cg.shared.global [%0], [%1], 16;" :: "r"((uint32_t)(sm)), "l"(gp))
#define CP_COMMIT() asm volatile("cp.async.commit_group;" ::: "memory")
#define CP_WAIT(n)  asm volatile("cp.async.wait_group %0;" :: "n"(n) : "memory")

__device__ __forceinline__ uint32_t smem_to_u32(const void* p) {
    uint32_t a;
    asm("{ .reg .u64 t; cvta.to.shared.u64 t, %1; cvt.u32.u64 %0, t; }" : "=r"(a) : "l"(p));
    return a;
}
__device__ __forceinline__ void mma_tf32(float& c0, float& c1, float& c2, float& c3,
                                         uint32_t a0, uint32_t a1, uint32_t a2, uint32_t a3,
                                         uint32_t b0, uint32_t b1) {
    asm volatile("mma.sync.aligned.m16n8k8.row.col.f32.tf32.tf32.f32 "
                 "{%0,%1,%2,%3}, {%4,%5,%6,%7}, {%8,%9}, {%0,%1,%2,%3};"
                 : "+f"(c0), "+f"(c1), "+f"(c2), "+f"(c3)
                 : "r"(a0), "r"(a1), "r"(a2), "r"(a3), "r"(b0), "r"(b1));
}

// =====================================================================
// prep: permute gates weight/bias + zero atomic accumulators
// =====================================================================
__global__ __launch_bounds__(192)
void k_prep(const float* __restrict__ wg, const float* __restrict__ bg)
{
    int col = blockIdx.x;
    int t = col >> 6, l = col & 63;
    int half = l >> 5, l2 = l & 31, b = l2 >> 4, l3 = l2 & 15;
    int ghi = l3 >> 3, l4 = l3 & 7, q = l4 >> 1, glo = l4 & 1;
    int gate = ghi * 2 + glo;
    int ch = t * 16 + half * 8 + b * 4 + q;
    int orow = gate * 192 + ch;
    g_wperm[col * 192 + threadIdx.x] = wg[orow * 192 + threadIdx.x];
    if (threadIdx.x == 0) g_bperm[col] = bg[orow];

    int idx = blockIdx.x * 192 + threadIdx.x;
    if (idx < TOK) { g_lns[idx] = 0.f; g_lnq[idx] = 0.f; }
    if (idx < 64) {
        g_g1s[idx] = 0.f; g_g1q[idx] = 0.f;
        g_g2s[idx] = 0.f; g_g2q[idx] = 0.f;
    }
}

// =====================================================================
// in_proj GEMM with fused BCHW gather + fused LN-stat partials.
// CTA 128x64, warp 32x32, kc=32. A^T smem [32][136].
// =====================================================================
__global__ __launch_bounds__(256, 4)
void k_tc_in(const float* __restrict__ X, const float* __restrict__ Hh,
             const float* __restrict__ W, const float* __restrict__ bias,
             float* __restrict__ C)
{
    constexpr int K = 256, NCH = 8;
    constexpr int MST = 136;
    constexpr int AST = 36;
    extern __shared__ float smf[];
    float* Asb[2] = { smf, smf + 32 * MST };
    float* Bsb[2] = { smf + 2 * 32 * MST, smf + 2 * 32 * MST + 64 * AST };

    const int tid  = threadIdx.x;
    const int lane = tid & 31;
    const int warp = tid >> 5;
    const int wm = warp & 3, wn = warp >> 2;
    const int m0 = blockIdx.y * 128;
    const int n0 = blockIdx.x * 64;
    const int b  = m0 >> 14;
    const int p0 = m0 & 16383;

    const uint32_t sA[2] = { smem_to_u32(Asb[0]), smem_to_u32(Asb[1]) };
    const uint32_t sB[2] = { smem_to_u32(Bsb[0]), smem_to_u32(Bsb[1]) };

    float acc[2][4][4];
#pragma unroll
    for (int i = 0; i < 2; i++)
#pragma unroll
        for (int j = 0; j < 4; j++)
#pragma unroll
            for (int q = 0; q < 4; q++) acc[i][j][q] = 0.f;

    auto prefetch = [&](int kt) {
        int buf = kt & 1;
#pragma unroll
        for (int j = 0; j < 4; j++) {
            int idx = tid + 256 * j;
            int k = idx >> 5, ms4 = idx & 31;
            int kg = kt * 32 + k;
            const float* src = (kg < 64)
                ? X  + (((size_t)(b * 64  + kg))        << 14) + p0 + ms4 * 4
                : Hh + (((size_t)(b * 192 + (kg - 64))) << 14) + p0 + ms4 * 4;
            CP_ASYNC16(sA[buf] + (uint32_t)(k * MST + ms4 * 4) * 4, src);
        }
        const float* bg = W + (size_t)n0 * K + kt * 32;
#pragma unroll
        for (int j = 0; j < 2; j++) {
            int idx = tid + 256 * j;
            int row = idx >> 3, off = idx & 7;
            CP_ASYNC16(sB[buf] + (uint32_t)(row * AST + off * 4) * 4,
                       bg + (size_t)row * K + off * 4);
        }
        CP_COMMIT();
    };

    prefetch(0);

    for (int kt = 0; kt < NCH; kt++) {
        if (kt + 1 < NCH) { prefetch(kt + 1); CP_WAIT(1); }
        else              { CP_WAIT(0); }
        __syncthreads();
        const float* as = Asb[kt & 1];
        const float* bs = Bsb[kt & 1];
#pragma unroll
        for (int ks = 0; ks < 4; ks++) {
            const int cc = ks * 8 + (lane & 3);
            uint32_t af[2][4];
#pragma unroll
            for (int mf = 0; mf < 2; mf++) {
                int r = wm * 32 + mf * 16 + (lane >> 2);
                af[mf][0] = __float_as_uint(as[cc * MST + r]);
                af[mf][1] = __float_as_uint(as[cc * MST + r + 8]);
                af[mf][2] = __float_as_uint(as[(cc + 4) * MST + r]);
                af[mf][3] = __float_as_uint(as[(cc + 4) * MST + r + 8]);
            }
            uint32_t bf[4][2];
#pragma unroll
            for (int nf = 0; nf < 4; nf++) {
                int rb = wn * 32 + nf * 8 + (lane >> 2);
                bf[nf][0] = __float_as_uint(bs[rb * AST + cc]);
                bf[nf][1] = __float_as_uint(bs[rb * AST + cc + 4]);
            }
#pragma unroll
            for (int mf = 0; mf < 2; mf++)
#pragma unroll
                for (int nf = 0; nf < 4; nf++)
                    mma_tf32(acc[mf][nf][0], acc[mf][nf][1], acc[mf][nf][2], acc[mf][nf][3],
                             af[mf][0], af[mf][1], af[mf][2], af[mf][3],
                             bf[nf][0], bf[nf][1]);
        }
        __syncthreads();
    }

    // epilogue: store + LN partials
    float rs[2][2] = {{0.f,0.f},{0.f,0.f}};
    float rq[2][2] = {{0.f,0.f},{0.f,0.f}};
#pragma unroll
    for (int mf = 0; mf < 2; mf++) {
        int row = m0 + wm * 32 + mf * 16 + (lane >> 2);
#pragma unroll
        for (int nf = 0; nf < 4; nf++) {
            int col = n0 + wn * 32 + nf * 8 + 2 * (lane & 3);
            float bx = bias[col], by = bias[col + 1];
            float2 o0 = make_float2(acc[mf][nf][0] + bx, acc[mf][nf][1] + by);
            float2 o1 = make_float2(acc[mf][nf][2] + bx, acc[mf][nf][3] + by);
            *reinterpret_cast<float2*>(&C[(size_t)row * 192 + col]) = o0;
            *reinterpret_cast<float2*>(&C[(size_t)(row + 8) * 192 + col]) = o1;
            rs[mf][0] += o0.x + o0.y;  rq[mf][0] += o0.x * o0.x + o0.y * o0.y;
            rs[mf][1] += o1.x + o1.y;  rq[mf][1] += o1.x * o1.x + o1.y * o1.y;
        }
    }
#pragma unroll
    for (int mf = 0; mf < 2; mf++)
#pragma unroll
        for (int half = 0; half < 2; half++) {
            float s = rs[mf][half], qq = rq[mf][half];
            s  += __shfl_xor_sync(0xffffffffu, s, 1);
            s  += __shfl_xor_sync(0xffffffffu, s, 2);
            qq += __shfl_xor_sync(0xffffffffu, qq, 1);
            qq += __shfl_xor_sync(0xffffffffu, qq, 2);
            if ((lane & 3) == 0) {
                int row = m0 + wm * 32 + mf * 16 + (lane >> 2) + 8 * half;
                atomicAdd(&g_lns[row], s);
                atomicAdd(&g_lnq[row], qq);
            }
        }
}

// =====================================================================
// qkv GEMM with fused LayerNorm on A (mu/iv computed in-kernel from
// the atomic sums). CTA 128x64, warp 32x32, kc=32.
// =====================================================================
__global__ __launch_bounds__(256, 4)
void k_tcln(const float* __restrict__ A, const float* __restrict__ W,
            const float* __restrict__ bias, float* __restrict__ C, int Ntot,
            const float* __restrict__ cg, const float* __restrict__ cb)
{
    constexpr int K = 192, NCH = 6, AST = 36;
    extern __shared__ float smf[];
    float* Asb[2] = { smf, smf + 128 * AST };
    float* Bsb[2] = { smf + 2 * 128 * AST, smf + 2 * 128 * AST + 64 * AST };
    float* smu = smf + 2 * 128 * AST + 2 * 64 * AST;
    float* siv = smu + 128;

    const int tid  = threadIdx.x;
    const int lane = tid & 31;
    const int warp = tid >> 5;
    const int wm = warp & 3, wn = warp >> 2;
    const int m0 = blockIdx.y * 128;
    const int n0 = blockIdx.x * 64;
    const int arow = tid >> 3, aoff = tid & 7;

    const uint32_t sA[2] = { smem_to_u32(Asb[0]), smem_to_u32(Asb[1]) };
    const uint32_t sB[2] = { smem_to_u32(Bsb[0]), smem_to_u32(Bsb[1]) };

    if (tid < 128) {
        float s = g_lns[m0 + tid], qn = g_lnq[m0 + tid];
        float m = s * (1.0f / 192.0f);
        smu[tid] = m;
        siv[tid] = rsqrtf(qn * (1.0f / 192.0f) - m * m + 1e-5f);
    }

    float acc[2][4][4];
#pragma unroll
    for (int i = 0; i < 2; i++)
#pragma unroll
        for (int j = 0; j < 4; j++)
#pragma unroll
            for (int q = 0; q < 4; q++) acc[i][j][q] = 0.f;

    auto prefetch = [&](int kt) {
        int buf = kt & 1;
        const float* ag = A + (size_t)m0 * K + kt * 32;
        const float* bg = W + (size_t)n0 * K + kt * 32;
#pragma unroll
        for (int j = 0; j < 4; j++) {
            int idx = tid + 256 * j;
            int row = idx >> 3, off = idx & 7;
            CP_ASYNC16(sA[buf] + (uint32_t)(row * AST + off * 4) * 4,
                       ag + (size_t)row * K + off * 4);
        }
#pragma unroll
        for (int j = 0; j < 2; j++) {
            int idx = tid + 256 * j;
            int row = idx >> 3, off = idx & 7;
            CP_ASYNC16(sB[buf] + (uint32_t)(row * AST + off * 4) * 4,
                       bg + (size_t)row * K + off * 4);
        }
        CP_COMMIT();
    };

    prefetch(0);

    for (int kt = 0; kt < NCH; kt++) {
        if (kt + 1 < NCH) { prefetch(kt + 1); CP_WAIT(1); }
        else              { CP_WAIT(0); }
        __syncthreads();
        {   // in-place LayerNorm on A chunk
            float* as = Asb[kt & 1];
            const int k = kt * 32 + aoff * 4;
            float4 g4 = *reinterpret_cast<const float4*>(&cg[k]);
            float4 b4 = *reinterpret_cast<const float4*>(&cb[k]);
#pragma unroll
            for (int j = 0; j < 4; j++) {
                int row = arow + 32 * j;
                float mu = smu[row], iv = siv[row];
                float4 v = *reinterpret_cast<float4*>(&as[row * AST + aoff * 4]);
                v.x = (v.x - mu) * iv * g4.x + b4.x;
                v.y = (v.y - mu) * iv * g4.y + b4.y;
                v.z = (v.z - mu) * iv * g4.z + b4.z;
                v.w = (v.w - mu) * iv * g4.w + b4.w;
                *reinterpret_cast<float4*>(&as[row * AST + aoff * 4]) = v;
            }
        }
        __syncthreads();
        const float* as = Asb[kt & 1];
        const float* bs = Bsb[kt & 1];
#pragma unroll
        for (int ks = 0; ks < 4; ks++) {
            const int cc = ks * 8 + (lane & 3);
            uint32_t af[2][4];
#pragma unroll
            for (int mf = 0; mf < 2; mf++) {
                int r = wm * 32 + mf * 16 + (lane >> 2);
                af[mf][0] = __float_as_uint(as[r * AST + cc]);
                af[mf][1] = __float_as_uint(as[(r + 8) * AST + cc]);
                af[mf][2] = __float_as_uint(as[r * AST + cc + 4]);
                af[mf][3] = __float_as_uint(as[(r + 8) * AST + cc + 4]);
            }
            uint32_t bf[4][2];
#pragma unroll
            for (int nf = 0; nf < 4; nf++) {
                int rb = wn * 32 + nf * 8 + (lane >> 2);
                bf[nf][0] = __float_as_uint(bs[rb * AST + cc]);
                bf[nf][1] = __float_as_uint(bs[rb * AST + cc + 4]);
            }
#pragma unroll
            for (int mf = 0; mf < 2; mf++)
#pragma unroll
                for (int nf = 0; nf < 4; nf++)
                    mma_tf32(acc[mf][nf][0], acc[mf][nf][1], acc[mf][nf][2], acc[mf][nf][3],
                             af[mf][0], af[mf][1], af[mf][2], af[mf][3],
                             bf[nf][0], bf[nf][1]);
        }
        __syncthreads();
    }

#pragma unroll
    for (int mf = 0; mf < 2; mf++) {
        int row = m0 + wm * 32 + mf * 16 + (lane >> 2);
#pragma unroll
        for (int nf = 0; nf < 4; nf++) {
            int col = n0 + wn * 32 + nf * 8 + 2 * (lane & 3);
            float bx = bias[col], by = bias[col + 1];
            float2 o0 = make_float2(acc[mf][nf][0] + bx, acc[mf][nf][1] + by);
            float2 o1 = make_float2(acc[mf][nf][2] + bx, acc[mf][nf][3] + by);
            *reinterpret_cast<float2*>(&C[(size_t)row * Ntot + col]) = o0;
            *reinterpret_cast<float2*>(&C[(size_t)(row + 8) * Ntot + col]) = o1;
        }
    }
}

// =====================================================================
// out_proj GEMM + fused GN1 partial stats. CTA 128x64, warp 32x32.
// =====================================================================
__global__ __launch_bounds__(256, 4)
void k_tc2(const float* __restrict__ A, const float* __restrict__ W,
           const float* __restrict__ bias, float* __restrict__ C)
{
    constexpr int K = 192, NCH = 6, AST = 36;
    extern __shared__ float smf[];
    float* Asb[2] = { smf, smf + 128 * AST };
    float* Bsb[2] = { smf + 2 * 128 * AST, smf + 2 * 128 * AST + 64 * AST };

    const int tid  = threadIdx.x;
    const int lane = tid & 31;
    const int warp = tid >> 5;
    const int wm = warp & 3, wn = warp >> 2;
    const int m0 = blockIdx.y * 128;
    const int n0 = blockIdx.x * 64;

    const uint32_t sA[2] = { smem_to_u32(Asb[0]), smem_to_u32(Asb[1]) };
    const uint32_t sB[2] = { smem_to_u32(Bsb[0]), smem_to_u32(Bsb[1]) };

    float acc[2][4][4];
#pragma unroll
    for (int i = 0; i < 2; i++)
#pragma unroll
        for (int j = 0; j < 4; j++)
#pragma unroll
            for (int q = 0; q < 4; q++) acc[i][j][q] = 0.f;

    auto prefetch = [&](int kt) {
        int buf = kt & 1;
        const float* ag = A + (size_t)m0 * K + kt * 32;
        const float* bg = W + (size_t)n0 * K + kt * 32;
#pragma unroll
        for (int j = 0; j < 4; j++) {
            int idx = tid + 256 * j;
            int row = idx >> 3, off = idx & 7;
            CP_ASYNC16(sA[buf] + (uint32_t)(row * AST + off * 4) * 4,
                       ag + (size_t)row * K + off * 4);
        }
#pragma unroll
        for (int j = 0; j < 2; j++) {
            int idx = tid + 256 * j;
            int row = idx >> 3, off = idx & 7;
            CP_ASYNC16(sB[buf] + (uint32_t)(row * AST + off * 4) * 4,
                       bg + (size_t)row * K + off * 4);
        }
        CP_COMMIT();
    };

    prefetch(0);

    for (int kt = 0; kt < NCH; kt++) {
        if (kt + 1 < NCH) { prefetch(kt + 1); CP_WAIT(1); }
        else              { CP_WAIT(0); }
        __syncthreads();
        const float* as = Asb[kt & 1];
        const float* bs = Bsb[kt & 1];
#pragma unroll
        for (int ks = 0; ks < 4; ks++) {
            const int cc = ks * 8 + (lane & 3);
            uint32_t af[2][4];
#pragma unroll
            for (int mf = 0; mf < 2; mf++) {
                int r = wm * 32 + mf * 16 + (lane >> 2);
                af[mf][0] = __float_as_uint(as[r * AST + cc]);
                af[mf][1] = __float_as_uint(as[(r + 8) * AST + cc]);
                af[mf][2] = __float_as_uint(as[r * AST + cc + 4]);
                af[mf][3] = __float_as_uint(as[(r + 8) * AST + cc + 4]);
            }
            uint32_t bf[4][2];
#pragma unroll
            for (int nf = 0; nf < 4; nf++) {
                int rb = wn * 32 + nf * 8 + (lane >> 2);
                bf[nf][0] = __float_as_uint(bs[rb * AST + cc]);
                bf[nf][1] = __float_as_uint(bs[rb * AST + cc + 4]);
            }
#pragma unroll
            for (int mf = 0; mf < 2; mf++)
#pragma unroll
                for (int nf = 0; nf < 4; nf++)
                    mma_tf32(acc[mf][nf][0], acc[mf][nf][1], acc[mf][nf][2], acc[mf][nf][3],
                             af[mf][0], af[mf][1], af[mf][2], af[mf][3],
                             bf[nf][0], bf[nf][1]);
        }
        __syncthreads();
    }

    const int bb = m0 >> 14;
#pragma unroll
    for (int nf = 0; nf < 4; nf++) {
        float s = 0.f, qq = 0.f;
        int col = n0 + wn * 32 + nf * 8 + 2 * (lane & 3);
        float bx = bias[col], by = bias[col + 1];
#pragma unroll
        for (int mf = 0; mf < 2; mf++) {
            int row = m0 + wm * 32 + mf * 16 + (lane >> 2);
            float2 o0 = make_float2(acc[mf][nf][0] + bx, acc[mf][nf][1] + by);
            float2 o1 = make_float2(acc[mf][nf][2] + bx, acc[mf][nf][3] + by);
            *reinterpret_cast<float2*>(&C[(size_t)row * 192 + col]) = o0;
            *reinterpret_cast<float2*>(&C[(size_t)(row + 8) * 192 + col]) = o1;
            s  += o0.x + o0.y + o1.x + o1.y;
            qq += o0.x * o0.x + o0.y * o0.y + o1.x * o1.x + o1.y * o1.y;
        }
#pragma unroll
        for (int o = 16; o; o >>= 1) {
            s  += __shfl_xor_sync(0xffffffffu, s, o);
            qq += __shfl_xor_sync(0xffffffffu, qq, o);
        }
        if (lane == 0) {
            int g = (n0 + wn * 32 + nf * 8) / 24;
            atomicAdd(&g_g1s[bb * 8 + g], s);
            atomicAdd(&g_g1q[bb * 8 + g], qq);
        }
    }
}

// =====================================================================
// gates GEMM (permuted W) + register-space GN on A (S/T fold, GN1
// finalize done in-kernel) + LSTM epilogue + GN2 partial stats.
// =====================================================================
__global__ __launch_bounds__(256, 4)
void k_tcg(const float* __restrict__ A, const float* __restrict__ W,
           const float* __restrict__ bias,
           const float* __restrict__ cg, const float* __restrict__ cb,
           const float* __restrict__ Cin, float* __restrict__ out)
{
    constexpr int K = 192, NCH = 6, AST = 36;
    extern __shared__ float smf[];
    float* Asb[2] = { smf, smf + 128 * AST };
    float* Bsb[2] = { smf + 2 * 128 * AST, smf + 2 * 128 * AST + 64 * AST };
    float* sS = smf + 2 * 128 * AST + 2 * 64 * AST;
    float* sT = sS + 192;

    const int tid  = threadIdx.x;
    const int lane = tid & 31;
    const int warp = tid >> 5;
    const int wm = warp & 3, wn = warp >> 2;
    const int m0 = blockIdx.y * 128;
    const int n0 = blockIdx.x * 64;
    const int b8 = (m0 >> 14) << 3;

    const uint32_t sA[2] = { smem_to_u32(Asb[0]), smem_to_u32(Asb[1]) };
    const uint32_t sB[2] = { smem_to_u32(Bsb[0]), smem_to_u32(Bsb[1]) };

    if (tid < 192) {     // fold GN1 finalize: S[k], T[k]
        int grp = tid / 24;
        const float inv_n = 1.0f / 393216.0f;
        float m = g_g1s[b8 + grp] * inv_n;
        float iv = rsqrtf(g_g1q[b8 + grp] * inv_n - m * m + 1e-5f);
        float gv = cg[tid];
        sS[tid] = iv * gv;
        sT[tid] = cb[tid] - m * iv * gv;
    }

    float acc[2][4][4];
#pragma unroll
    for (int i = 0; i < 2; i++)
#pragma unroll
        for (int j = 0; j < 4; j++)
#pragma unroll
            for (int q = 0; q < 4; q++) acc[i][j][q] = 0.f;

    auto prefetch = [&](int kt) {
        int buf = kt & 1;
        const float* ag = A + (size_t)m0 * K + kt * 32;
        const float* bg = W + (size_t)n0 * K + kt * 32;
#pragma unroll
        for (int j = 0; j < 4; j++) {
            int idx = tid + 256 * j;
            int row = idx >> 3, off = idx & 7;
            CP_ASYNC16(sA[buf] + (uint32_t)(row * AST + off * 4) * 4,
                       ag + (size_t)row * K + off * 4);
        }
#pragma unroll
        for (int j = 0; j < 2; j++) {
            int idx = tid + 256 * j;
            int row = idx >> 3, off = idx & 7;
            CP_ASYNC16(sB[buf] + (uint32_t)(row * AST + off * 4) * 4,
                       bg + (size_t)row * K + off * 4);
        }
        CP_COMMIT();
    };

    prefetch(0);

    for (int kt = 0; kt < NCH; kt++) {
        if (kt + 1 < NCH) { prefetch(kt + 1); CP_WAIT(1); }
        else              { CP_WAIT(0); }
        __syncthreads();
        const float* as = Asb[kt & 1];
        const float* bs = Bsb[kt & 1];
#pragma unroll
        for (int ks = 0; ks < 4; ks++) {
            const int cc = ks * 8 + (lane & 3);
            const int kg = kt * 32 + cc;
            float S0 = sS[kg], T0 = sT[kg];
            float S1 = sS[kg + 4], T1 = sT[kg + 4];
            uint32_t af[2][4];
#pragma unroll
            for (int mf = 0; mf < 2; mf++) {
                int r = wm * 32 + mf * 16 + (lane >> 2);
                af[mf][0] = __float_as_uint(fmaf(as[r * AST + cc],       S0, T0));
                af[mf][1] = __float_as_uint(fmaf(as[(r + 8) * AST + cc], S0, T0));
                af[mf][2] = __float_as_uint(fmaf(as[r * AST + cc + 4],   S1, T1));
                af[mf][3] = __float_as_uint(fmaf(as[(r + 8) * AST + cc + 4], S1, T1));
            }
            uint32_t bf[4][2];
#pragma unroll
            for (int nf = 0; nf < 4; nf++) {
                int rb = wn * 32 + nf * 8 + (lane >> 2);
                bf[nf][0] = __float_as_uint(bs[rb * AST + cc]);
                bf[nf][1] = __float_as_uint(bs[rb * AST + cc + 4]);
            }
#pragma unroll
            for (int mf = 0; mf < 2; mf++)
#pragma unroll
                for (int nf = 0; nf < 4; nf++)
                    mma_tf32(acc[mf][nf][0], acc[mf][nf][1], acc[mf][nf][2], acc[mf][nf][3],
                             af[mf][0], af[mf][1], af[mf][2], af[mf][3],
                             bf[nf][0], bf[nf][1]);
        }
        __syncthreads();
    }

    // ---- LSTM epilogue + GN2 partials ----
    const int q = lane & 3;
    const int t = blockIdx.x;
    const int chA = t * 16 + wn * 8 + q;
    const int chB = chA + 4;
    const int colb = n0 + wn * 32 + 2 * q;
    float bIA = bias[colb + 0],  bFA = bias[colb + 1];
    float bOA = bias[colb + 8],  bGA = bias[colb + 9];
    float bIB = bias[colb + 16], bFB = bias[colb + 17];
    float bOB = bias[colb + 24], bGB = bias[colb + 25];

    const int bt = m0 >> 14;
    const size_t baseA = ((size_t)(bt * 192 + chA)) << 14;
    const size_t baseB = ((size_t)(bt * 192 + chB)) << 14;

    float sA_ = 0.f, qA_ = 0.f, sB_ = 0.f, qB_ = 0.f;
#pragma unroll
    for (int mf = 0; mf < 2; mf++) {
        int p = (m0 + wm * 32 + mf * 16 + (lane >> 2)) & 16383;
#pragma unroll
        for (int half = 0; half < 2; half++) {
            int pp = p + half * 8;
            int a0 = half * 2;
            {
                float gi = acc[mf][0][a0]     + bIA;
                float gf = acc[mf][0][a0 + 1] + bFA;
                float go = acc[mf][1][a0]     + bOA;
                float gg = acc[mf][1][a0 + 1] + bGA;
                float i_ = 1.f / (1.f + __expf(-gi));
                float f_ = 1.f / (1.f + __expf(-gf));
                float o_ = 1.f / (1.f + __expf(-go));
                float g_ = tanhf(gg);
                size_t addr = baseA + pp;
                float cn = f_ * Cin[addr] + i_ * g_;
                out[(size_t)HSZ + addr] = cn;
                float hv = o_ * tanhf(cn);
                g_hraw[addr] = hv;
                sA_ += hv; qA_ += hv * hv;
            }
            {
                float gi = acc[mf][2][a0]     + bIB;
                float gf = acc[mf][2][a0 + 1] + bFB;
                float go = acc[mf][3][a0]     + bOB;
                float gg = acc[mf][3][a0 + 1] + bGB;
                float i_ = 1.f / (1.f + __expf(-gi));
                float f_ = 1.f / (1.f + __expf(-gf));
                float o_ = 1.f / (1.f + __expf(-go));
                float g_ = tanhf(gg);
                size_t addr = baseB + pp;
                float cn = f_ * Cin[addr] + i_ * g_;
                out[(size_t)HSZ + addr] = cn;
                float hv = o_ * tanhf(cn);
                g_hraw[addr] = hv;
                sB_ += hv; qB_ += hv * hv;
            }
        }
    }
#pragma unroll
    for (int o = 16; o; o >>= 1) {
        sA_ += __shfl_xor_sync(0xffffffffu, sA_, o);
        qA_ += __shfl_xor_sync(0xffffffffu, qA_, o);
        sB_ += __shfl_xor_sync(0xffffffffu, sB_, o);
        qB_ += __shfl_xor_sync(0xffffffffu, qB_, o);
    }
    if (lane == 0) {
        int gA = (t * 16 + wn * 8) / 24;
        int gB = (t * 16 + wn * 8 + 4) / 24;
        atomicAdd(&g_g2s[bt * 8 + gA], sA_);
        atomicAdd(&g_g2q[bt * 8 + gA], qA_);
        atomicAdd(&g_g2s[bt * 8 + gB], sB_);
        atomicAdd(&g_g2q[bt * 8 + gB], qB_);
    }
}

// =====================================================================
// Window attention — 4 windows/CTA, cp.async double-buffered,
// conflict-free K-column mapping. Dynamic smem.
// =====================================================================
#define QS 580
__global__ __launch_bounds__(256, 2)
void k_attn()
{
    extern __shared__ float smf[];
    float* sq0 = smf;
    float* sq1 = smf + 16 * QS;
    float* ss  = smf + 32 * QS;        // 1024 floats

    const int tid = threadIdx.x;

    auto prefetch = [&](int w, float* buf) {
        int b = w >> 10, wi = w & 1023, wy = wi >> 5, wx = wi & 31;
        int rowbase = (b << 14) + (wy << 9) + (wx << 2);
        uint32_t sbase = smem_to_u32(buf);
#pragma unroll
        for (int j = 0; j < 9; j++) {
            int i = tid + 256 * j;
            int t = i / 144, c4 = i - t * 144;
            int tok = rowbase + ((t >> 2) << 7) + (t & 3);
            CP_ASYNC16(sbase + (uint32_t)(t * QS + c4 * 4) * 4,
                       &g_qkv[(size_t)tok * 576 + c4 * 4]);
        }
        CP_COMMIT();
    };

    const int w0 = blockIdx.x * 4;
    prefetch(w0, sq0);

    for (int it = 0; it < 4; it++) {
        if (it < 3) { prefetch(w0 + it + 1, (it & 1) ? sq0 : sq1); CP_WAIT(1); }
        else        { CP_WAIT(0); }
        __syncthreads();
        const float* sqb = (it & 1) ? sq1 : sq0;
        int w = w0 + it;
        int b = w >> 10, wi = w & 1023, wy = wi >> 5, wx = wi & 31;
        int rowbase = (b << 14) + (wy << 9) + (wx << 2);

        {   // scores: thread cols = cl + 4*cc (conflict-free K reads)
            int h = tid >> 6, r = (tid >> 2) & 15, cl = tid & 3;
            const float4* qrow = reinterpret_cast<const float4*>(&sqb[r * QS + h * 48]);
            float4 qv[12];
#pragma unroll
            for (int k = 0; k < 12; k++) qv[k] = qrow[k];
#pragma unroll
            for (int cc = 0; cc < 4; cc++) {
                int col = cl + 4 * cc;
                const float4* krow = reinterpret_cast<const float4*>(
                    &sqb[col * QS + 192 + h * 48]);
                float d = 0.f;
#pragma unroll
                for (int k = 0; k < 12; k++) {
                    float4 kv = krow[k];
                    d += qv[k].x * kv.x + qv[k].y * kv.y + qv[k].z * kv.z + qv[k].w * kv.w;
                }
                ss[(h * 16 + r) * 16 + col] = d * 0.14433756729740643f;
            }
        }
        __syncthreads();

        if (tid < 64) {
            float* row = &ss[tid * 16];
            float mx = row[0];
#pragma unroll
            for (int j = 1; j < 16; j++) mx = fmaxf(mx, row[j]);
            float sm = 0.f;
#pragma unroll
            for (int j = 0; j < 16; j++) { float e = __expf(row[j] - mx); row[j] = e; sm += e; }
            float r = 1.f / sm;
#pragma unroll
            for (int j = 0; j < 16; j++) row[j] *= r;
        }
        __syncthreads();

        if (tid < 192) {      // AV: V float4 reused across 4 rows
            int c4 = tid % 48;
            int rp = tid / 48;
            int h = c4 / 12;
            const float* vbase = &sqb[384 + c4 * 4];
            float4 o[4];
#pragma unroll
            for (int rr = 0; rr < 4; rr++) o[rr] = make_float4(0.f, 0.f, 0.f, 0.f);
#pragma unroll
            for (int jj = 0; jj < 16; jj++) {
                float4 vv = *reinterpret_cast<const float4*>(&vbase[jj * QS]);
#pragma unroll
                for (int rr = 0; rr < 4; rr++) {
                    float sv = ss[(h * 16 + rp + rr * 4) * 16 + jj];
                    o[rr].x += sv * vv.x; o[rr].y += sv * vv.y;
                    o[rr].z += sv * vv.z; o[rr].w += sv * vv.w;
                }
            }
#pragma unroll
            for (int rr = 0; rr < 4; rr++) {
                int tok = rowbase + (rr << 7) + rp;
                *reinterpret_cast<float4*>(&g_attn[(size_t)tok * 192 + c4 * 4]) = o[rr];
            }
        }
        __syncthreads();      // protect ss + buffer for next iteration
    }
}

// =====================================================================
// final GN apply on hraw (GN2 finalize folded in)
// =====================================================================
__global__ __launch_bounds__(256)
void k_finalize(const float* __restrict__ gg, const float* __restrict__ gb,
                float* __restrict__ out)
{
    __shared__ float sp[2];
    size_t base0 = (size_t)blockIdx.x * 1024;
    if (threadIdx.x == 0) {
        int bc = (int)(base0 >> 14);
        int b = bc / 192, cch = bc - b * 192;
        int grp = cch / 24;
        const float inv_n = 1.0f / 393216.0f;
        float m = g_g2s[b * 8 + grp] * inv_n;
        float iv = rsqrtf(g_g2q[b * 8 + grp] * inv_n - m * m + 1e-5f);
        float sc = gg[cch] * iv;
        sp[0] = sc;
        sp[1] = gb[cch] - m * sc;
    }
    __syncthreads();
    float sc = sp[0], bi = sp[1];
    size_t base = base0 + (size_t)threadIdx.x * 4;
    float4 v = *reinterpret_cast<const float4*>(&g_hraw[base]);
    float4 o;
    o.x = v.x * sc + bi;
    o.y = v.y * sc + bi;
    o.z = v.z * sc + bi;
    o.w = v.w * sc + bi;
    *reinterpret_cast<float4*>(&out[base]) = o;
}

// =====================================================================
// host launcher
// =====================================================================
extern "C" void kernel_launch(void* const* d_in, const int* in_sizes, int n_in,
                              void* d_out, int out_size)
{
    const float* x       = (const float*)d_in[0];
    const float* h       = (const float*)d_in[1];
    const float* c       = (const float*)d_in[2];
    const float* w_in    = (const float*)d_in[3];
    const float* b_in    = (const float*)d_in[4];
    const float* ln_g    = (const float*)d_in[5];
    const float* ln_b    = (const float*)d_in[6];
    const float* w_qkv   = (const float*)d_in[7];
    const float* b_qkv   = (const float*)d_in[8];
    const float* w_proj  = (const float*)d_in[9];
    const float* b_proj  = (const float*)d_in[10];
    const float* gn_g    = (const float*)d_in[11];
    const float* gn_b    = (const float*)d_in[12];
    const float* w_gates = (const float*)d_in[13];
    const float* b_gates = (const float*)d_in[14];
    float* out = (float*)d_out;

    void *p_proj, *p_qkv, *p_attn, *p_amap, *p_wperm, *p_bperm;
    cudaGetSymbolAddress(&p_proj,  g_proj);
    cudaGetSymbolAddress(&p_qkv,   g_qkv);
    cudaGetSymbolAddress(&p_attn,  g_attn);
    cudaGetSymbolAddress(&p_amap,  g_amap);
    cudaGetSymbolAddress(&p_wperm, g_wperm);
    cudaGetSymbolAddress(&p_bperm, g_bperm);

    const int SM_TC = (2 * 128 + 2 * 64) * 36 * 4;                 // 55296
    const int SM_LN = SM_TC + 256 * 4;                             // 56320
    const int SM_GT = SM_TC + 384 * 4;                             // 56832
    const int SM_IN = (2 * 32 * 136 + 2 * 64 * 36) * 4;            // 53248
    const int SM_AT = (2 * 16 * QS + 1024) * 4;                    // 78336
    cudaFuncSetAttribute(k_tcln, cudaFuncAttributeMaxDynamicSharedMemorySize, SM_LN);
    cudaFuncSetAttribute(k_tc2,  cudaFuncAttributeMaxDynamicSharedMemorySize, SM_TC);
    cudaFuncSetAttribute(k_tcg,  cudaFuncAttributeMaxDynamicSharedMemorySize, SM_GT);
    cudaFuncSetAttribute(k_tc_in, cudaFuncAttributeMaxDynamicSharedMemorySize, SM_IN);
    cudaFuncSetAttribute(k_attn, cudaFuncAttributeMaxDynamicSharedMemorySize, SM_AT);

    // 0) prep: permute gates weights + zero stat accumulators
    k_prep<<<768, 192>>>(w_gates, b_gates);
    // 1) in_proj GEMM (gather) + LN partial stats
    k_tc_in<<<dim3(3, 1024), 256, SM_IN>>>(x, h, w_in, b_in, (float*)p_proj);
    // 2) qkv GEMM with fused LayerNorm (lnfin folded)
    k_tcln<<<dim3(9, 1024), 256, SM_LN>>>((const float*)p_proj, w_qkv, b_qkv,
                                          (float*)p_qkv, 576, ln_g, ln_b);
    // 3) window attention (4 windows/CTA, double-buffered)
    k_attn<<<2048, 256, SM_AT>>>();
    // 4) out_proj GEMM + GN1 partial stats
    k_tc2<<<dim3(3, 1024), 256, SM_TC>>>((const float*)p_attn, w_proj, b_proj,
                                         (float*)p_amap);
    // 5) gates GEMM + GN on A (gn1 finalize folded) + LSTM + GN2 partials
    k_tcg<<<dim3(12, 1024), 256, SM_GT>>>((const float*)p_amap, (const float*)p_wperm,
                                          (const float*)p_bperm,
                                          gn_g, gn_b, c, out);
    // 6) GN2 finalize + apply -> d_out first half
    k_finalize<<<24576, 256>>>(gn_g, gn_b, out);
}